// round 9
// baseline (speedup 1.0000x reference)
#include <cuda_runtime.h>
#include <cuda_fp16.h>
#include <math.h>
#include <stdint.h>

#define H   1024
#define ID  512
#define NE  32
#define TK  4
#define MAXT 4096
#define MAXN (MAXT*TK)
#define RSCALE 2.5f

#define TILE_E   8192          // elems per 128x64 fp16 tile
#define TILE_B   16384         // bytes per tile
#define NT_X     160           // row-tiles for padded sorted rows (20480/128)
#define NT_SH    32            // T/128
#define KC_GU    16            // H/64
#define KC_DN    8             // ID/64
#define TN_GU    4             // ID/128
#define TN_DN    8             // H/128

#define NST_GU   3
#define NST_DN   4
#define STAGE_GU 65536         // Ah,Al,Bg,Bu
#define STAGE_DN 49152         // Ah,Al,B
#define SMEM_GU  (NST_GU*STAGE_GU)   // 196608
#define SMEM_DN  (NST_DN*STAGE_DN)   // 196608

#define NTHR     544           // 16 compute warps + 1 producer warp

// ---------------- scratch (device globals; referenced ONLY in device code) --
__device__ float g_outs[(size_t)NT_X * 128 * H];
__device__ float g_shout[(size_t)MAXT * H];
__device__ float g_tw[MAXT * TK];
__device__ int   g_topk[MAXT * TK];
__device__ int   g_counts[NE];
__device__ int   g_offsets[NE + 1];
__device__ int   g_cursor[NE];
__device__ int   g_rowmap[NT_X * 128];
__device__ int   g_pos[MAXN];

// tiled fp16 planes: [tile][kc][8192] swizzled
__device__ __align__(16) __half g_xsh[(size_t)NT_X * KC_GU * TILE_E];
__device__ __align__(16) __half g_xsl[(size_t)NT_X * KC_GU * TILE_E];
__device__ __align__(16) __half g_sxh[(size_t)NT_SH * KC_GU * TILE_E];
__device__ __align__(16) __half g_sxl[(size_t)NT_SH * KC_GU * TILE_E];
__device__ __align__(16) __half g_acth[(size_t)NT_X * KC_DN * TILE_E];
__device__ __align__(16) __half g_actl[(size_t)NT_X * KC_DN * TILE_E];
__device__ __align__(16) __half g_sacth[(size_t)NT_SH * KC_DN * TILE_E];
__device__ __align__(16) __half g_sactl[(size_t)NT_SH * KC_DN * TILE_E];

// tiled weights [e][nt][kc][8192]
__device__ __align__(16) __half g_pwg[(size_t)NE * TN_GU * KC_GU * TILE_E];
__device__ __align__(16) __half g_pwu[(size_t)NE * TN_GU * KC_GU * TILE_E];
__device__ __align__(16) __half g_pwd[(size_t)NE * TN_DN * KC_DN * TILE_E];
__device__ __align__(16) __half g_psg[(size_t)TN_GU * KC_GU * TILE_E];
__device__ __align__(16) __half g_psu[(size_t)TN_GU * KC_GU * TILE_E];
__device__ __align__(16) __half g_psd[(size_t)TN_DN * KC_DN * TILE_E];

// ---------------- helpers ----------------------------------------------
__device__ __forceinline__ uint32_t smem_u32(const void* p) {
    return (uint32_t)__cvta_generic_to_shared(p);
}
__device__ __forceinline__ uint32_t swz(uint32_t b) { return b ^ ((b >> 3) & 0x70); }
__device__ __forceinline__ uint32_t packh(__half a, __half b) {
    return (uint32_t)(*(uint16_t*)&a) | ((uint32_t)(*(uint16_t*)&b) << 16);
}
__device__ __forceinline__ void split2h(float v0, float v1, uint32_t& hi, uint32_t& lo) {
    __half h0 = __float2half_rn(v0), h1 = __float2half_rn(v1);
    float r0 = v0 - __half2float(h0), r1 = v1 - __half2float(h1);
    hi = packh(h0, h1);
    lo = packh(__float2half_rn(r0), __float2half_rn(r1));
}
__device__ __forceinline__ float silu_fast(float g) { return g / (1.f + __expf(-g)); }

__device__ __forceinline__ void mbar_init(uint32_t a, uint32_t cnt) {
    asm volatile("mbarrier.init.shared.b64 [%0], %1;" :: "r"(a), "r"(cnt) : "memory");
}
__device__ __forceinline__ void mbar_arrive(uint32_t a) {
    asm volatile("mbarrier.arrive.shared.b64 _, [%0];" :: "r"(a) : "memory");
}
__device__ __forceinline__ void mbar_expect(uint32_t a, uint32_t bytes) {
    asm volatile("mbarrier.arrive.expect_tx.shared.b64 _, [%0], %1;"
                 :: "r"(a), "r"(bytes) : "memory");
}
__device__ __forceinline__ void mbar_wait(uint32_t a, uint32_t ph) {
    asm volatile(
        "{\n\t.reg .pred P;\n\t"
        "W_%=:\n\t"
        "mbarrier.try_wait.parity.acquire.cta.shared::cta.b64 P, [%0], %1, 0x989680;\n\t"
        "@P bra D_%=;\n\t"
        "bra W_%=;\n\t"
        "D_%=:\n\t}"
        :: "r"(a), "r"(ph) : "memory");
}
#define TMA_BULK(dst, src, bytes, mbar) \
    asm volatile("cp.async.bulk.shared::cta.global.mbarrier::complete_tx::bytes " \
                 "[%0], [%1], %2, [%3];" \
                 :: "r"(dst), "l"(src), "r"(bytes), "r"(mbar) : "memory")

#define LDMX4(r0_,r1_,r2_,r3_,addr) \
    asm volatile("ldmatrix.sync.aligned.m8n8.x4.shared.b16 {%0,%1,%2,%3}, [%4];" \
        : "=r"(r0_), "=r"(r1_), "=r"(r2_), "=r"(r3_) : "r"(addr))

#define MMAH(c_, a_, b0_, b1_) \
    asm volatile("mma.sync.aligned.m16n8k16.row.col.f32.f16.f16.f32 " \
        "{%0,%1,%2,%3}, {%4,%5,%6,%7}, {%8,%9}, {%0,%1,%2,%3};" \
        : "+f"((c_)[0]), "+f"((c_)[1]), "+f"((c_)[2]), "+f"((c_)[3]) \
        : "r"((a_)[0]), "r"((a_)[1]), "r"((a_)[2]), "r"((a_)[3]), \
          "r"(b0_), "r"(b1_))

// ---------------- init / routing -----------------------------------------
__global__ void init_kernel() {
    int i = blockIdx.x * 256 + threadIdx.x;
    if (i < NE) { g_counts[i] = 0; g_cursor[i] = 0; }
    if (i < NT_X * 128) g_rowmap[i] = 0;
}

__global__ void __launch_bounds__(128)
gate_kernel(const float* __restrict__ X, const float* __restrict__ GW,
            const float* __restrict__ EB,
            float* outLogits, float* outTopkF)
{
    __shared__ __align__(16) float xs[H];
    __shared__ float sl[NE];
    __shared__ float ssc[NE];
    __shared__ float ssrt[NE];

    int t = blockIdx.x;
    const float* x = X + (size_t)t * H;
    for (int c = threadIdx.x; c < H; c += 128) xs[c] = x[c];
    __syncthreads();

    int e = threadIdx.x >> 2, q = threadIdx.x & 3;
    const float* w = GW + (size_t)e * H;
    float s = 0.f;
    int c0 = q * 256;
    #pragma unroll 8
    for (int c = c0; c < c0 + 256; c += 4) {
        float4 xv = *(const float4*)&xs[c];
        float4 wv = *(const float4*)(w + c);
        s += xv.x * wv.x + xv.y * wv.y + xv.z * wv.z + xv.w * wv.w;
    }
    s += __shfl_down_sync(0xffffffffu, s, 2);
    s += __shfl_down_sync(0xffffffffu, s, 1);
    if (q == 0) {
        sl[e] = s;
        if (outLogits) outLogits[(size_t)t * NE + e] = s;
    }
    __syncthreads();

    if (threadIdx.x < NE) {
        float v = sl[threadIdx.x];
        float sc = 1.f / (1.f + expf(-v));
        ssc[threadIdx.x] = sc;
        ssrt[threadIdx.x] = sc + EB[threadIdx.x];
    }
    __syncthreads();

    if (threadIdx.x == 0) {
        float gs[4];
        #pragma unroll
        for (int g = 0; g < 4; g++) {
            float m1 = -1e30f, m2 = -1e30f;
            #pragma unroll
            for (int j = 0; j < 8; j++) {
                float v = ssrt[g * 8 + j];
                if (v > m1) { m2 = m1; m1 = v; }
                else if (v > m2) { m2 = v; }
            }
            gs[g] = m1 + m2;
        }
        int g1 = 0;
        for (int g = 1; g < 4; g++) if (gs[g] > gs[g1]) g1 = g;
        int g2 = -1;
        for (int g = 0; g < 4; g++) {
            if (g == g1) continue;
            if (g2 < 0 || gs[g] > gs[g2]) g2 = g;
        }
        bool used[NE];
        #pragma unroll
        for (int i = 0; i < NE; i++) used[i] = false;
        int idx[TK]; float wts[TK]; float sum = 0.f;
        #pragma unroll
        for (int k = 0; k < TK; k++) {
            int best = -1; float bv = -1e30f;
            for (int i = 0; i < NE; i++) {
                int grp = i >> 3;
                if (grp != g1 && grp != g2) continue;
                if (used[i]) continue;
                if (ssrt[i] > bv) { bv = ssrt[i]; best = i; }
            }
            used[best] = true;
            idx[k] = best;
            wts[k] = ssc[best];
            sum += wts[k];
        }
        float inv = RSCALE / (sum + 1e-20f);
        #pragma unroll
        for (int k = 0; k < TK; k++) {
            g_topk[t * TK + k] = idx[k];
            g_tw[t * TK + k]   = wts[k] * inv;
            if (outTopkF) outTopkF[t * TK + k] = (float)idx[k];
            atomicAdd(&g_counts[idx[k]], 1);
        }
    }
}

__global__ void scan_kernel() {
    if (threadIdx.x == 0) {
        int o = 0;
        for (int e = 0; e < NE; e++) {
            g_offsets[e] = o;
            o += (g_counts[e] + 127) & ~127;   // 128-aligned per expert
        }
        g_offsets[NE] = o;
    }
}

__global__ void scatter_kernel(int N) {
    int s = blockIdx.x * 256 + threadIdx.x;
    if (s >= N) return;
    int e = g_topk[s];
    int p = g_offsets[e] + atomicAdd(&g_cursor[e], 1);
    g_rowmap[p] = s;
    g_pos[s] = p;
}

// ---------------- gather X into tiled swizzled fp16 hi/lo -------------------
// mode 0: routed (sorted padded rows, rowmap); mode 1: shared (natural order)
__global__ void __launch_bounds__(256)
gather_x(const float* __restrict__ X, int T, int mode)
{
    int kc = blockIdx.x;
    int gt = blockIdx.y;
    __shared__ int stok[128];
    int total = mode ? T : g_offsets[NE];
    if (gt * 128 >= total) return;

    int tid = threadIdx.x;
    if (tid < 128) {
        int p = gt * 128 + tid;
        stok[tid] = mode ? p : (g_rowmap[p] >> 2);
    }
    __syncthreads();

    __half* dh = (mode ? g_sxh : g_xsh) + ((size_t)gt * KC_GU + kc) * TILE_E;
    __half* dl = (mode ? g_sxl : g_xsl) + ((size_t)gt * KC_GU + kc) * TILE_E;

    for (int i = tid; i < 128 * 16; i += 256) {
        int r = i >> 4, q = (i & 15) * 4;
        float4 v = *(const float4*)(X + (size_t)stok[r] * H + kc * 64 + q);
        uint32_t h0, l0, h1, l1;
        split2h(v.x, v.y, h0, l0);
        split2h(v.z, v.w, h1, l1);
        uint32_t b = swz((uint32_t)(r * 128 + q * 2));
        *(uint2*)((char*)dh + b) = make_uint2(h0, h1);
        *(uint2*)((char*)dl + b) = make_uint2(l0, l1);
    }
}

// ---------------- weight prep core -----------------------------------------
__device__ __forceinline__ void prep_core(const float* src, int N, __half* dst)
{
    __shared__ float sT[128][65];
    int tid = threadIdx.x;
    for (int i = tid; i < 64 * 32; i += 256) {
        int k = i >> 5, nf = (i & 31) * 4;
        float4 v = *(const float4*)(src + (size_t)k * N + nf);
        sT[nf + 0][k] = v.x; sT[nf + 1][k] = v.y;
        sT[nf + 2][k] = v.z; sT[nf + 3][k] = v.w;
    }
    __syncthreads();
    for (int i = tid; i < 128 * 16; i += 256) {
        int n = i >> 4, k4 = (i & 15) * 4;
        uint32_t a = packh(__float2half_rn(sT[n][k4]),     __float2half_rn(sT[n][k4 + 1]));
        uint32_t b = packh(__float2half_rn(sT[n][k4 + 2]), __float2half_rn(sT[n][k4 + 3]));
        uint32_t off = swz((uint32_t)(n * 128 + k4 * 2));
        *(uint2*)((char*)dst + off) = make_uint2(a, b);
    }
}

// z: 0..NE-1 wg, NE..2NE-1 wu, 2NE wsg, 2NE+1 wsu
__global__ void __launch_bounds__(256)
prep_gu(const float* __restrict__ wg, const float* __restrict__ wu,
        const float* __restrict__ wsg, const float* __restrict__ wsu)
{
    int kc = blockIdx.x, nt = blockIdx.y, z = blockIdx.z;
    const float* W; __half* base; int e;
    if (z < NE)          { W = wg;  base = g_pwg; e = z; }
    else if (z < 2 * NE) { W = wu;  base = g_pwu; e = z - NE; }
    else if (z == 2*NE)  { W = wsg; base = g_psg; e = 0; }
    else                 { W = wsu; base = g_psu; e = 0; }
    const float* src = W + ((size_t)e * H + (size_t)kc * 64) * ID + (size_t)nt * 128;
    __half* dst = base + ((size_t)(e * TN_GU + nt) * KC_GU + kc) * TILE_E;
    prep_core(src, ID, dst);
}

// z: 0..NE-1 wd, NE wsd
__global__ void __launch_bounds__(256)
prep_dn(const float* __restrict__ wd, const float* __restrict__ wsd)
{
    int kc = blockIdx.x, nt = blockIdx.y, z = blockIdx.z;
    const float* W; __half* base; int e;
    if (z < NE) { W = wd;  base = g_pwd; e = z; }
    else        { W = wsd; base = g_psd; e = 0; }
    const float* src = W + ((size_t)e * ID + (size_t)kc * 64) * H + (size_t)nt * 128;
    __half* dst = base + ((size_t)(e * TN_DN + nt) * KC_DN + kc) * TILE_E;
    prep_core(src, H, dst);
}

// ---------------- fused gate+up GEMM (fp16x2, producer-warp pipeline) -------
// e = blockIdx.z + base_e; e == NE means shared expert
__global__ void __launch_bounds__(NTHR)
mma_gateup(int T, int base_e)
{
    extern __shared__ char sm[];
    __shared__ __align__(8) unsigned long long s_bar[2 * NST_GU];

    int e = blockIdx.z + base_e;
    bool sh = (e == NE);
    int r0, cnt;
    if (sh) { r0 = 0; cnt = T; }
    else { r0 = g_offsets[e]; cnt = g_counts[e]; }
    int mbase = blockIdx.y * 128;
    if (mbase >= cnt) return;
    int nb = blockIdx.x;
    int gt = (r0 + mbase) >> 7;

    const __half* Ah = sh ? g_sxh : g_xsh;
    const __half* Al = sh ? g_sxl : g_xsl;
    const __half* Bg = (sh ? g_psg : g_pwg)
        + (size_t)(sh ? 0 : e) * TN_GU * KC_GU * TILE_E + (size_t)nb * KC_GU * TILE_E;
    const __half* Bu = (sh ? g_psu : g_pwu)
        + (size_t)(sh ? 0 : e) * TN_GU * KC_GU * TILE_E + (size_t)nb * KC_GU * TILE_E;

    int tid = threadIdx.x;
    int wid = tid >> 5, lane = tid & 31;
    uint32_t smbase = smem_u32(sm);
    uint32_t barb = smem_u32(&s_bar[0]);
    auto fullb  = [&](int s) { return barb + s * 8; };
    auto emptyb = [&](int s) { return barb + (NST_GU + s) * 8; };

    if (tid == 0)
        for (int s = 0; s < NST_GU; s++) { mbar_init(fullb(s), 1); mbar_init(emptyb(s), 16); }
    __syncthreads();

    const int nc = KC_GU;

    if (wid == 16) {
        // producer warp: issue all chunks, throttled by empty barriers
        if (lane == 0) {
            for (int j = 0; j < nc; j++) {
                int s = j % NST_GU;
                if (j >= NST_GU) mbar_wait(emptyb(s), ((j / NST_GU) - 1) & 1);
                uint32_t st = smbase + s * STAGE_GU;
                mbar_expect(fullb(s), STAGE_GU);
                TMA_BULK(st,         (const char*)(Ah + ((size_t)gt * KC_GU + j) * TILE_E), TILE_B, fullb(s));
                TMA_BULK(st + 16384, (const char*)(Al + ((size_t)gt * KC_GU + j) * TILE_E), TILE_B, fullb(s));
                TMA_BULK(st + 32768, (const char*)(Bg + (size_t)j * TILE_E), TILE_B, fullb(s));
                TMA_BULK(st + 49152, (const char*)(Bu + (size_t)j * TILE_E), TILE_B, fullb(s));
            }
        }
        return;
    }

    int warpM = wid & 3, warpN = wid >> 2;
    float accG[2][4][4], accU[2][4][4];
    #pragma unroll
    for (int a = 0; a < 2; a++)
        #pragma unroll
        for (int b = 0; b < 4; b++)
            #pragma unroll
            for (int cc = 0; cc < 4; cc++) { accG[a][b][cc] = 0.f; accU[a][b][cc] = 0.f; }

    int arow = (lane & 7) + ((lane >> 3) & 1) * 8;
    int aselB = (lane >> 4) * 16;
    int brow = (lane & 7) + (lane >> 4) * 8;
    int bselB = ((lane >> 3) & 1) * 16;

    for (int c = 0; c < nc; c++) {
        int s = c % NST_GU;
        mbar_wait(fullb(s), (c / NST_GU) & 1);

        uint32_t base = smbase + s * STAGE_GU;
        #pragma unroll
        for (int k16 = 0; k16 < 4; k16++) {
            uint32_t ah[2][4], al4[2][4], b[4][2];
            #pragma unroll
            for (int mi = 0; mi < 2; mi++) {
                uint32_t off = (uint32_t)((warpM * 32 + mi * 16 + arow) * 128 + k16 * 32 + aselB);
                uint32_t sa = base + swz(off);
                LDMX4(ah[mi][0], ah[mi][1], ah[mi][2], ah[mi][3], sa);
                LDMX4(al4[mi][0], al4[mi][1], al4[mi][2], al4[mi][3], sa + 16384);
            }
            // --- G ---
            #pragma unroll
            for (int gi = 0; gi < 2; gi++) {
                uint32_t off = (uint32_t)((warpN * 32 + gi * 16 + brow) * 128 + k16 * 32 + bselB);
                uint32_t x0, x1, x2, x3;
                LDMX4(x0, x1, x2, x3, base + 32768 + swz(off));
                b[gi*2][0]=x0; b[gi*2][1]=x1; b[gi*2+1][0]=x2; b[gi*2+1][1]=x3;
            }
            #pragma unroll
            for (int mi = 0; mi < 2; mi++)
                #pragma unroll
                for (int ni = 0; ni < 4; ni++) {
                    MMAH(accG[mi][ni], ah[mi], b[ni][0], b[ni][1]);
                    MMAH(accG[mi][ni], al4[mi], b[ni][0], b[ni][1]);
                }
            // --- U ---
            #pragma unroll
            for (int gi = 0; gi < 2; gi++) {
                uint32_t off = (uint32_t)((warpN * 32 + gi * 16 + brow) * 128 + k16 * 32 + bselB);
                uint32_t x0, x1, x2, x3;
                LDMX4(x0, x1, x2, x3, base + 49152 + swz(off));
                b[gi*2][0]=x0; b[gi*2][1]=x1; b[gi*2+1][0]=x2; b[gi*2+1][1]=x3;
            }
            #pragma unroll
            for (int mi = 0; mi < 2; mi++)
                #pragma unroll
                for (int ni = 0; ni < 4; ni++) {
                    MMAH(accU[mi][ni], ah[mi], b[ni][0], b[ni][1]);
                    MMAH(accU[mi][ni], al4[mi], b[ni][0], b[ni][1]);
                }
        }
        __syncwarp();
        if (lane == 0) mbar_arrive(emptyb(s));
    }

    // epilogue: act = silu(G)*U -> tiled swizzled fp16 hi/lo for down GEMM
    __half* Dh = sh ? g_sacth : g_acth;
    __half* Dl = sh ? g_sactl : g_actl;
    int g = lane >> 2, tg = lane & 3;
    #pragma unroll
    for (int mi = 0; mi < 2; mi++) {
        #pragma unroll
        for (int ni = 0; ni < 4; ni++) {
            int cl = warpN * 32 + ni * 8 + tg * 2;
            int gcol = nb * 128 + cl;
            int kcd = gcol >> 6, cc = gcol & 63;
            char* th = (char*)(Dh + ((size_t)gt * KC_DN + kcd) * TILE_E);
            char* tl = (char*)(Dl + ((size_t)gt * KC_DN + kcd) * TILE_E);
            #pragma unroll
            for (int half8 = 0; half8 < 2; half8++) {
                int rl = warpM * 32 + mi * 16 + g + half8 * 8;
                if (mbase + rl >= cnt) continue;
                float a0 = silu_fast(accG[mi][ni][half8*2])   * accU[mi][ni][half8*2];
                float a1 = silu_fast(accG[mi][ni][half8*2+1]) * accU[mi][ni][half8*2+1];
                uint32_t hi, lo;
                split2h(a0, a1, hi, lo);
                uint32_t b = swz((uint32_t)(rl * 128 + cc * 2));
                *(uint32_t*)(th + b) = hi;
                *(uint32_t*)(tl + b) = lo;
            }
        }
    }
}

// ---------------- down GEMM (fp16x2, producer-warp pipeline) -----------------
__global__ void __launch_bounds__(NTHR)
mma_down(int T, int base_e)
{
    extern __shared__ char sm[];
    __shared__ __align__(8) unsigned long long s_bar[2 * NST_DN];

    int e = blockIdx.z + base_e;
    bool sh = (e == NE);
    int r0, cnt;
    if (sh) { r0 = 0; cnt = T; }
    else { r0 = g_offsets[e]; cnt = g_counts[e]; }
    int mbase = blockIdx.y * 128;
    if (mbase >= cnt) return;
    int nb = blockIdx.x;
    int gt = (r0 + mbase) >> 7;

    const __half* Ahp = sh ? g_sacth : g_acth;
    const __half* Alp = sh ? g_sactl : g_actl;
    const __half* Bd = (sh ? g_psd : g_pwd)
        + (size_t)(sh ? 0 : e) * TN_DN * KC_DN * TILE_E + (size_t)nb * KC_DN * TILE_E;
    float* C = sh ? g_shout : g_outs;

    int tid = threadIdx.x;
    int wid = tid >> 5, lane = tid & 31;
    uint32_t smbase = smem_u32(sm);
    uint32_t barb = smem_u32(&s_bar[0]);
    auto fullb  = [&](int s) { return barb + s * 8; };
    auto emptyb = [&](int s) { return barb + (NST_DN + s) * 8; };

    if (tid == 0)
        for (int s = 0; s < NST_DN; s++) { mbar_init(fullb(s), 1); mbar_init(emptyb(s), 16); }
    __syncthreads();

    const int nc = KC_DN;

    if (wid == 16) {
        if (lane == 0) {
            for (int j = 0; j < nc; j++) {
                int s = j % NST_DN;
                if (j >= NST_DN) mbar_wait(emptyb(s), ((j / NST_DN) - 1) & 1);
                uint32_t st = smbase + s * STAGE_DN;
                mbar_expect(fullb(s), STAGE_DN);
                TMA_BULK(st,         (const char*)(Ahp + ((size_t)gt * KC_DN + j) * TILE_E), TILE_B, fullb(s));
                TMA_BULK(st + 16384, (const char*)(Alp + ((size_t)gt * KC_DN + j) * TILE_E), TILE_B, fullb(s));
                TMA_BULK(st + 32768, (const char*)(Bd + (size_t)j * TILE_E), TILE_B, fullb(s));
            }
        }
        return;
    }

    int warpM = wid & 3, warpN = wid >> 2;
    float acc[2][4][4];
    #pragma unroll
    for (int a = 0; a < 2; a++)
        #pragma unroll
        for (int b = 0; b < 4; b++)
            #pragma unroll
            for (int cc = 0; cc < 4; cc++) acc[a][b][cc] = 0.f;

    int arow = (lane & 7) + ((lane >> 3) & 1) * 8;
    int aselB = (lane >> 4) * 16;
    int brow = (lane & 7) + (lane >> 4) * 8;
    int bselB = ((lane >> 3) & 1) * 16;

    for (int c = 0; c < nc; c++) {
        int s = c % NST_DN;
        mbar_wait(fullb(s), (c / NST_DN) & 1);

        uint32_t base = smbase + s * STAGE_DN;
        #pragma unroll
        for (int k16 = 0; k16 < 4; k16++) {
            uint32_t ah[2][4], al4[2][4], b[4][2];
            #pragma unroll
            for (int mi = 0; mi < 2; mi++) {
                uint32_t off = (uint32_t)((warpM * 32 + mi * 16 + arow) * 128 + k16 * 32 + aselB);
                uint32_t sa = base + swz(off);
                LDMX4(ah[mi][0], ah[mi][1], ah[mi][2], ah[mi][3], sa);
                LDMX4(al4[mi][0], al4[mi][1], al4[mi][2], al4[mi][3], sa + 16384);
            }
            #pragma unroll
            for (int gi = 0; gi < 2; gi++) {
                uint32_t off = (uint32_t)((warpN * 32 + gi * 16 + brow) * 128 + k16 * 32 + bselB);
                uint32_t x0, x1, x2, x3;
                LDMX4(x0, x1, x2, x3, base + 32768 + swz(off));
                b[gi*2][0]=x0; b[gi*2][1]=x1; b[gi*2+1][0]=x2; b[gi*2+1][1]=x3;
            }
            #pragma unroll
            for (int mi = 0; mi < 2; mi++)
                #pragma unroll
                for (int ni = 0; ni < 4; ni++) {
                    MMAH(acc[mi][ni], ah[mi], b[ni][0], b[ni][1]);
                    MMAH(acc[mi][ni], al4[mi], b[ni][0], b[ni][1]);
                }
        }
        __syncwarp();
        if (lane == 0) mbar_arrive(emptyb(s));
    }

    int g = lane >> 2, tg = lane & 3;
    #pragma unroll
    for (int mi = 0; mi < 2; mi++) {
        int row = mbase + warpM * 32 + mi * 16 + g;
        #pragma unroll
        for (int ni = 0; ni < 4; ni++) {
            int col = nb * 128 + warpN * 32 + ni * 8 + tg * 2;
            if (row < cnt)
                *(float2*)(C + (size_t)(r0 + row) * H + col)
                    = make_float2(acc[mi][ni][0], acc[mi][ni][1]);
            if (row + 8 < cnt)
                *(float2*)(C + (size_t)(r0 + row + 8) * H + col)
                    = make_float2(acc[mi][ni][2], acc[mi][ni][3]);
        }
    }
}

// ---------------- combine ---------------------------------------------------
__global__ void __launch_bounds__(256)
combine_kernel(float* __restrict__ Y)
{
    int t = blockIdx.x;
    __shared__ float w[TK];
    __shared__ int   p[TK];
    if (threadIdx.x < TK) {
        w[threadIdx.x] = g_tw[t * TK + threadIdx.x];
        p[threadIdx.x] = g_pos[t * TK + threadIdx.x];
    }
    __syncthreads();
    int c = threadIdx.x * 4;
    float4 acc = *(const float4*)(g_shout + (size_t)t * H + c);
    #pragma unroll
    for (int k = 0; k < TK; k++) {
        float4 v = *(const float4*)(g_outs + (size_t)p[k] * H + c);
        acc.x += w[k] * v.x; acc.y += w[k] * v.y;
        acc.z += w[k] * v.z; acc.w += w[k] * v.w;
    }
    *(float4*)(Y + (size_t)t * H + c) = acc;
}

__global__ void fill_zero(float* p, long long n) {
    long long i = (long long)blockIdx.x * 256 + threadIdx.x;
    if (i < n) p[i] = 0.f;
}

// ---------------- launch -----------------------------------------------------
extern "C" void kernel_launch(void* const* d_in, const int* in_sizes, int n_in,
                              void* d_out, int out_size)
{
    const float* x   = (const float*)d_in[0];
    const float* gw  = (const float*)d_in[1];
    const float* eb  = (const float*)d_in[2];
    const float* wg  = (const float*)d_in[3];
    const float* wu  = (const float*)d_in[4];
    const float* wd  = (const float*)d_in[5];
    const float* wsg = (const float*)d_in[6];
    const float* wsu = (const float*)d_in[7];
    const float* wsd = (const float*)d_in[8];
    float* out = (float*)d_out;

    int T = in_sizes[0] / H;
    int N = T * TK;
    int MT = (T + 127) / 128;

    long long oL = (long long)T * H;
    long long oK = oL + (long long)T * NE;
    long long oEnd = oK + (long long)T * TK;

    float* outLogits = ((long long)out_size >= oK)   ? (out + oL) : nullptr;
    float* outTopkF  = ((long long)out_size >= oEnd) ? (out + oK) : nullptr;
    long long written = ((long long)out_size >= oEnd) ? oEnd
                       : ((long long)out_size >= oK) ? oK
                       : oL;

    cudaFuncSetAttribute(mma_gateup, cudaFuncAttributeMaxDynamicSharedMemorySize, SMEM_GU);
    cudaFuncSetAttribute(mma_down,   cudaFuncAttributeMaxDynamicSharedMemorySize, SMEM_DN);

    // shared-expert chain first; launch #4 (profiled slot) = shared gateup GEMM
    gather_x<<<dim3(KC_GU, NT_SH, 1), 256>>>(x, T, 1);
    prep_gu<<<dim3(KC_GU, TN_GU, 2 * NE + 2), 256>>>(wg, wu, wsg, wsu);
    prep_dn<<<dim3(KC_DN, TN_DN, NE + 1), 256>>>(wd, wsd);
    mma_gateup<<<dim3(TN_GU, MT, 1), NTHR, SMEM_GU>>>(T, NE);
    mma_down  <<<dim3(TN_DN, MT, 1), NTHR, SMEM_DN>>>(T, NE);

    // routing
    init_kernel<<<80, 256>>>();
    gate_kernel<<<T, 128>>>(x, gw, eb, outLogits, outTopkF);
    scan_kernel<<<1, 1>>>();
    scatter_kernel<<<(N + 255) / 256, 256>>>(N);
    gather_x<<<dim3(KC_GU, NT_X, 1), 256>>>(x, T, 0);

    // routed GEMMs
    mma_gateup<<<dim3(TN_GU, MT, NE), NTHR, SMEM_GU>>>(T, 0);
    mma_down  <<<dim3(TN_DN, MT, NE), NTHR, SMEM_DN>>>(T, 0);

    combine_kernel<<<T, 256>>>(out);

    if ((long long)out_size > written) {
        long long rest = (long long)out_size - written;
        fill_zero<<<(unsigned)((rest + 255) / 256), 256>>>(out + written, rest);
    }
}

// round 10
// speedup vs baseline: 1.3029x; 1.3029x over previous
#include <cuda_runtime.h>
#include <cuda_fp16.h>
#include <math.h>
#include <stdint.h>

#define H   1024
#define ID  512
#define NE  32
#define TK  4
#define MAXT 4096
#define MAXN (MAXT*TK)
#define RSCALE 2.5f

#define TILE_E   8192          // elems per 128x64 fp16 tile
#define TILE_B   16384         // bytes per tile
#define NT_X     160           // row-tiles for padded sorted rows (20480/128)
#define NT_SH    32            // T/128
#define KC_GU    16            // H/64
#define KC_DN    8             // ID/64
#define TN_GU    4             // ID/128
#define TN_DN    8             // H/128

#define NST_GU   4
#define NST_DN   6
#define STAGE_GU 49152         // A, Bg, Bu
#define STAGE_DN 32768         // A, B
#define SMEM_GU  (NST_GU*STAGE_GU)   // 196608
#define SMEM_DN  (NST_DN*STAGE_DN)   // 196608

// ---------------- scratch (device globals; referenced ONLY in device code) --
__device__ float g_outs[(size_t)NT_X * 128 * H];
__device__ float g_shout[(size_t)MAXT * H];
__device__ float g_tw[MAXT * TK];
__device__ int   g_topk[MAXT * TK];
__device__ int   g_counts[NE];
__device__ int   g_offsets[NE + 1];
__device__ int   g_cursor[NE];
__device__ int   g_rowmap[NT_X * 128];
__device__ int   g_pos[MAXN];

// tiled fp16 planes: [tile][kc][8192] swizzled
__device__ __align__(16) __half g_xsh[(size_t)NT_X * KC_GU * TILE_E];
__device__ __align__(16) __half g_sxh[(size_t)NT_SH * KC_GU * TILE_E];
__device__ __align__(16) __half g_acth[(size_t)NT_X * KC_DN * TILE_E];
__device__ __align__(16) __half g_sacth[(size_t)NT_SH * KC_DN * TILE_E];

// tiled weights [e][nt][kc][8192]
__device__ __align__(16) __half g_pwg[(size_t)NE * TN_GU * KC_GU * TILE_E];
__device__ __align__(16) __half g_pwu[(size_t)NE * TN_GU * KC_GU * TILE_E];
__device__ __align__(16) __half g_pwd[(size_t)NE * TN_DN * KC_DN * TILE_E];
__device__ __align__(16) __half g_psg[(size_t)TN_GU * KC_GU * TILE_E];
__device__ __align__(16) __half g_psu[(size_t)TN_GU * KC_GU * TILE_E];
__device__ __align__(16) __half g_psd[(size_t)TN_DN * KC_DN * TILE_E];

// ---------------- helpers ----------------------------------------------
__device__ __forceinline__ uint32_t smem_u32(const void* p) {
    return (uint32_t)__cvta_generic_to_shared(p);
}
__device__ __forceinline__ uint32_t swz(uint32_t b) { return b ^ ((b >> 3) & 0x70); }
__device__ __forceinline__ uint32_t packh(__half a, __half b) {
    return (uint32_t)(*(uint16_t*)&a) | ((uint32_t)(*(uint16_t*)&b) << 16);
}
__device__ __forceinline__ float silu_fast(float g) { return g / (1.f + __expf(-g)); }

__device__ __forceinline__ void mbar_init(uint32_t a, uint32_t cnt) {
    asm volatile("mbarrier.init.shared.b64 [%0], %1;" :: "r"(a), "r"(cnt) : "memory");
}
__device__ __forceinline__ void mbar_arrive(uint32_t a) {
    asm volatile("mbarrier.arrive.shared.b64 _, [%0];" :: "r"(a) : "memory");
}
__device__ __forceinline__ void mbar_expect(uint32_t a, uint32_t bytes) {
    asm volatile("mbarrier.arrive.expect_tx.shared.b64 _, [%0], %1;"
                 :: "r"(a), "r"(bytes) : "memory");
}
__device__ __forceinline__ void mbar_wait(uint32_t a, uint32_t ph) {
    asm volatile(
        "{\n\t.reg .pred P;\n\t"
        "W_%=:\n\t"
        "mbarrier.try_wait.parity.acquire.cta.shared::cta.b64 P, [%0], %1, 0x989680;\n\t"
        "@P bra D_%=;\n\t"
        "bra W_%=;\n\t"
        "D_%=:\n\t}"
        :: "r"(a), "r"(ph) : "memory");
}
#define TMA_BULK(dst, src, bytes, mbar) \
    asm volatile("cp.async.bulk.shared::cta.global.mbarrier::complete_tx::bytes " \
                 "[%0], [%1], %2, [%3];" \
                 :: "r"(dst), "l"(src), "r"(bytes), "r"(mbar) : "memory")

#define LDMX4(r0_,r1_,r2_,r3_,addr) \
    asm volatile("ldmatrix.sync.aligned.m8n8.x4.shared.b16 {%0,%1,%2,%3}, [%4];" \
        : "=r"(r0_), "=r"(r1_), "=r"(r2_), "=r"(r3_) : "r"(addr))

#define MMAH(c_, a_, b0_, b1_) \
    asm volatile("mma.sync.aligned.m16n8k16.row.col.f32.f16.f16.f32 " \
        "{%0,%1,%2,%3}, {%4,%5,%6,%7}, {%8,%9}, {%0,%1,%2,%3};" \
        : "+f"((c_)[0]), "+f"((c_)[1]), "+f"((c_)[2]), "+f"((c_)[3]) \
        : "r"((a_)[0]), "r"((a_)[1]), "r"((a_)[2]), "r"((a_)[3]), \
          "r"(b0_), "r"(b1_))

// ---------------- init / routing -----------------------------------------
__global__ void init_kernel() {
    int i = blockIdx.x * 256 + threadIdx.x;
    if (i < NE) { g_counts[i] = 0; g_cursor[i] = 0; }
    if (i < NT_X * 128) g_rowmap[i] = 0;
}

__global__ void __launch_bounds__(128)
gate_kernel(const float* __restrict__ X, const float* __restrict__ GW,
            const float* __restrict__ EB,
            float* outLogits, float* outTopkF)
{
    __shared__ __align__(16) float xs[H];
    __shared__ float sl[NE];
    __shared__ float ssc[NE];
    __shared__ float ssrt[NE];

    int t = blockIdx.x;
    const float* x = X + (size_t)t * H;
    for (int c = threadIdx.x; c < H; c += 128) xs[c] = x[c];
    __syncthreads();

    int e = threadIdx.x >> 2, q = threadIdx.x & 3;
    const float* w = GW + (size_t)e * H;
    float s = 0.f;
    int c0 = q * 256;
    #pragma unroll 8
    for (int c = c0; c < c0 + 256; c += 4) {
        float4 xv = *(const float4*)&xs[c];
        float4 wv = *(const float4*)(w + c);
        s += xv.x * wv.x + xv.y * wv.y + xv.z * wv.z + xv.w * wv.w;
    }
    s += __shfl_down_sync(0xffffffffu, s, 2);
    s += __shfl_down_sync(0xffffffffu, s, 1);
    if (q == 0) {
        sl[e] = s;
        if (outLogits) outLogits[(size_t)t * NE + e] = s;
    }
    __syncthreads();

    if (threadIdx.x < NE) {
        float v = sl[threadIdx.x];
        float sc = 1.f / (1.f + expf(-v));
        ssc[threadIdx.x] = sc;
        ssrt[threadIdx.x] = sc + EB[threadIdx.x];
    }
    __syncthreads();

    if (threadIdx.x == 0) {
        float gs[4];
        #pragma unroll
        for (int g = 0; g < 4; g++) {
            float m1 = -1e30f, m2 = -1e30f;
            #pragma unroll
            for (int j = 0; j < 8; j++) {
                float v = ssrt[g * 8 + j];
                if (v > m1) { m2 = m1; m1 = v; }
                else if (v > m2) { m2 = v; }
            }
            gs[g] = m1 + m2;
        }
        int g1 = 0;
        for (int g = 1; g < 4; g++) if (gs[g] > gs[g1]) g1 = g;
        int g2 = -1;
        for (int g = 0; g < 4; g++) {
            if (g == g1) continue;
            if (g2 < 0 || gs[g] > gs[g2]) g2 = g;
        }
        bool used[NE];
        #pragma unroll
        for (int i = 0; i < NE; i++) used[i] = false;
        int idx[TK]; float wts[TK]; float sum = 0.f;
        #pragma unroll
        for (int k = 0; k < TK; k++) {
            int best = -1; float bv = -1e30f;
            for (int i = 0; i < NE; i++) {
                int grp = i >> 3;
                if (grp != g1 && grp != g2) continue;
                if (used[i]) continue;
                if (ssrt[i] > bv) { bv = ssrt[i]; best = i; }
            }
            used[best] = true;
            idx[k] = best;
            wts[k] = ssc[best];
            sum += wts[k];
        }
        float inv = RSCALE / (sum + 1e-20f);
        #pragma unroll
        for (int k = 0; k < TK; k++) {
            g_topk[t * TK + k] = idx[k];
            g_tw[t * TK + k]   = wts[k] * inv;
            if (outTopkF) outTopkF[t * TK + k] = (float)idx[k];
            atomicAdd(&g_counts[idx[k]], 1);
        }
    }
}

__global__ void scan_kernel() {
    if (threadIdx.x == 0) {
        int o = 0;
        for (int e = 0; e < NE; e++) {
            g_offsets[e] = o;
            o += (g_counts[e] + 127) & ~127;   // 128-aligned per expert
        }
        g_offsets[NE] = o;
    }
}

__global__ void scatter_kernel(int N) {
    int s = blockIdx.x * 256 + threadIdx.x;
    if (s >= N) return;
    int e = g_topk[s];
    int p = g_offsets[e] + atomicAdd(&g_cursor[e], 1);
    g_rowmap[p] = s;
    g_pos[s] = p;
}

// ---------------- gather X into tiled swizzled fp16 -------------------------
// mode 0: routed (sorted padded rows, rowmap); mode 1: shared (natural order)
__global__ void __launch_bounds__(256)
gather_x(const float* __restrict__ X, int T, int mode)
{
    int kc = blockIdx.x;
    int gt = blockIdx.y;
    __shared__ int stok[128];
    int total = mode ? T : g_offsets[NE];
    if (gt * 128 >= total) return;

    int tid = threadIdx.x;
    if (tid < 128) {
        int p = gt * 128 + tid;
        stok[tid] = mode ? p : (g_rowmap[p] >> 2);
    }
    __syncthreads();

    __half* dh = (mode ? g_sxh : g_xsh) + ((size_t)gt * KC_GU + kc) * TILE_E;

    for (int i = tid; i < 128 * 16; i += 256) {
        int r = i >> 4, q = (i & 15) * 4;
        float4 v = *(const float4*)(X + (size_t)stok[r] * H + kc * 64 + q);
        uint32_t h0 = packh(__float2half_rn(v.x), __float2half_rn(v.y));
        uint32_t h1 = packh(__float2half_rn(v.z), __float2half_rn(v.w));
        uint32_t b = swz((uint32_t)(r * 128 + q * 2));
        *(uint2*)((char*)dh + b) = make_uint2(h0, h1);
    }
}

// ---------------- weight prep core -----------------------------------------
__device__ __forceinline__ void prep_core(const float* src, int N, __half* dst)
{
    __shared__ float sT[128][65];
    int tid = threadIdx.x;
    for (int i = tid; i < 64 * 32; i += 256) {
        int k = i >> 5, nf = (i & 31) * 4;
        float4 v = *(const float4*)(src + (size_t)k * N + nf);
        sT[nf + 0][k] = v.x; sT[nf + 1][k] = v.y;
        sT[nf + 2][k] = v.z; sT[nf + 3][k] = v.w;
    }
    __syncthreads();
    for (int i = tid; i < 128 * 16; i += 256) {
        int n = i >> 4, k4 = (i & 15) * 4;
        uint32_t a = packh(__float2half_rn(sT[n][k4]),     __float2half_rn(sT[n][k4 + 1]));
        uint32_t b = packh(__float2half_rn(sT[n][k4 + 2]), __float2half_rn(sT[n][k4 + 3]));
        uint32_t off = swz((uint32_t)(n * 128 + k4 * 2));
        *(uint2*)((char*)dst + off) = make_uint2(a, b);
    }
}

// z: 0..NE-1 wg, NE..2NE-1 wu, 2NE wsg, 2NE+1 wsu
__global__ void __launch_bounds__(256)
prep_gu(const float* __restrict__ wg, const float* __restrict__ wu,
        const float* __restrict__ wsg, const float* __restrict__ wsu)
{
    int kc = blockIdx.x, nt = blockIdx.y, z = blockIdx.z;
    const float* W; __half* base; int e;
    if (z < NE)          { W = wg;  base = g_pwg; e = z; }
    else if (z < 2 * NE) { W = wu;  base = g_pwu; e = z - NE; }
    else if (z == 2*NE)  { W = wsg; base = g_psg; e = 0; }
    else                 { W = wsu; base = g_psu; e = 0; }
    const float* src = W + ((size_t)e * H + (size_t)kc * 64) * ID + (size_t)nt * 128;
    __half* dst = base + ((size_t)(e * TN_GU + nt) * KC_GU + kc) * TILE_E;
    prep_core(src, ID, dst);
}

// z: 0..NE-1 wd, NE wsd
__global__ void __launch_bounds__(256)
prep_dn(const float* __restrict__ wd, const float* __restrict__ wsd)
{
    int kc = blockIdx.x, nt = blockIdx.y, z = blockIdx.z;
    const float* W; __half* base; int e;
    if (z < NE) { W = wd;  base = g_pwd; e = z; }
    else        { W = wsd; base = g_psd; e = 0; }
    const float* src = W + ((size_t)e * ID + (size_t)kc * 64) * H + (size_t)nt * 128;
    __half* dst = base + ((size_t)(e * TN_DN + nt) * KC_DN + kc) * TILE_E;
    prep_core(src, H, dst);
}

// ---------------- fused gate+up GEMM (pure fp16, bulk pipeline) -------------
// e = blockIdx.z + base_e; e == NE means shared expert
__global__ void __launch_bounds__(512)
mma_gateup(int T, int base_e)
{
    extern __shared__ char sm[];
    __shared__ __align__(8) unsigned long long s_bar[2 * NST_GU];

    int e = blockIdx.z + base_e;
    bool sh = (e == NE);
    int r0, cnt;
    if (sh) { r0 = 0; cnt = T; }
    else { r0 = g_offsets[e]; cnt = g_counts[e]; }
    int mbase = blockIdx.y * 128;
    if (mbase >= cnt) return;
    int nb = blockIdx.x;
    int gt = (r0 + mbase) >> 7;

    const __half* Ah = sh ? g_sxh : g_xsh;
    const __half* Bg = (sh ? g_psg : g_pwg)
        + (size_t)(sh ? 0 : e) * TN_GU * KC_GU * TILE_E + (size_t)nb * KC_GU * TILE_E;
    const __half* Bu = (sh ? g_psu : g_pwu)
        + (size_t)(sh ? 0 : e) * TN_GU * KC_GU * TILE_E + (size_t)nb * KC_GU * TILE_E;

    int tid = threadIdx.x;
    int wid = tid >> 5, lane = tid & 31;
    int warpM = wid & 3, warpN = wid >> 2;
    uint32_t smbase = smem_u32(sm);
    uint32_t barb = smem_u32(&s_bar[0]);
    auto fullb  = [&](int s) { return barb + s * 8; };
    auto emptyb = [&](int s) { return barb + (NST_GU + s) * 8; };

    if (tid == 0)
        for (int s = 0; s < NST_GU; s++) { mbar_init(fullb(s), 1); mbar_init(emptyb(s), 16); }
    __syncthreads();

    auto issue = [&](int j) {
        int s = j % NST_GU;
        uint32_t st = smbase + s * STAGE_GU;
        mbar_expect(fullb(s), STAGE_GU);
        TMA_BULK(st,         (const char*)(Ah + ((size_t)gt * KC_GU + j) * TILE_E), TILE_B, fullb(s));
        TMA_BULK(st + 16384, (const char*)(Bg + (size_t)j * TILE_E), TILE_B, fullb(s));
        TMA_BULK(st + 32768, (const char*)(Bu + (size_t)j * TILE_E), TILE_B, fullb(s));
    };

    const int nc = KC_GU;
    if (tid == 0)
        for (int j = 0; j < NST_GU - 1; j++) issue(j);

    float accG[2][4][4], accU[2][4][4];
    #pragma unroll
    for (int a = 0; a < 2; a++)
        #pragma unroll
        for (int b = 0; b < 4; b++)
            #pragma unroll
            for (int cc = 0; cc < 4; cc++) { accG[a][b][cc] = 0.f; accU[a][b][cc] = 0.f; }

    int arow = (lane & 7) + ((lane >> 3) & 1) * 8;
    int aselB = (lane >> 4) * 16;
    int brow = (lane & 7) + (lane >> 4) * 8;
    int bselB = ((lane >> 3) & 1) * 16;

    for (int c = 0; c < nc; c++) {
        int s = c % NST_GU;
        if (tid == 0) {
            int j = c + NST_GU - 1;
            if (j < nc) {
                if (j >= NST_GU) mbar_wait(emptyb(j % NST_GU), (j / NST_GU - 1) & 1);
                issue(j);
            }
        }
        mbar_wait(fullb(s), (c / NST_GU) & 1);

        uint32_t base = smbase + s * STAGE_GU;
        #pragma unroll
        for (int k16 = 0; k16 < 4; k16++) {
            uint32_t a[2][4], b[4][2];
            #pragma unroll
            for (int mi = 0; mi < 2; mi++) {
                uint32_t off = (uint32_t)((warpM * 32 + mi * 16 + arow) * 128 + k16 * 32 + aselB);
                LDMX4(a[mi][0], a[mi][1], a[mi][2], a[mi][3], base + swz(off));
            }
            // --- G ---
            #pragma unroll
            for (int gi = 0; gi < 2; gi++) {
                uint32_t off = (uint32_t)((warpN * 32 + gi * 16 + brow) * 128 + k16 * 32 + bselB);
                uint32_t x0, x1, x2, x3;
                LDMX4(x0, x1, x2, x3, base + 16384 + swz(off));
                b[gi*2][0]=x0; b[gi*2][1]=x1; b[gi*2+1][0]=x2; b[gi*2+1][1]=x3;
            }
            #pragma unroll
            for (int mi = 0; mi < 2; mi++)
                #pragma unroll
                for (int ni = 0; ni < 4; ni++)
                    MMAH(accG[mi][ni], a[mi], b[ni][0], b[ni][1]);
            // --- U ---
            #pragma unroll
            for (int gi = 0; gi < 2; gi++) {
                uint32_t off = (uint32_t)((warpN * 32 + gi * 16 + brow) * 128 + k16 * 32 + bselB);
                uint32_t x0, x1, x2, x3;
                LDMX4(x0, x1, x2, x3, base + 32768 + swz(off));
                b[gi*2][0]=x0; b[gi*2][1]=x1; b[gi*2+1][0]=x2; b[gi*2+1][1]=x3;
            }
            #pragma unroll
            for (int mi = 0; mi < 2; mi++)
                #pragma unroll
                for (int ni = 0; ni < 4; ni++)
                    MMAH(accU[mi][ni], a[mi], b[ni][0], b[ni][1]);
        }
        __syncwarp();
        if (lane == 0) mbar_arrive(emptyb(s));
    }

    // epilogue: act = silu(G)*U -> tiled swizzled fp16 for down GEMM
    __half* Dh = sh ? g_sacth : g_acth;
    int g = lane >> 2, tg = lane & 3;
    #pragma unroll
    for (int mi = 0; mi < 2; mi++) {
        #pragma unroll
        for (int ni = 0; ni < 4; ni++) {
            int cl = warpN * 32 + ni * 8 + tg * 2;
            int gcol = nb * 128 + cl;
            int kcd = gcol >> 6, cc = gcol & 63;
            char* th = (char*)(Dh + ((size_t)gt * KC_DN + kcd) * TILE_E);
            #pragma unroll
            for (int half8 = 0; half8 < 2; half8++) {
                int rl = warpM * 32 + mi * 16 + g + half8 * 8;
                if (mbase + rl >= cnt) continue;
                float a0 = silu_fast(accG[mi][ni][half8*2])   * accU[mi][ni][half8*2];
                float a1 = silu_fast(accG[mi][ni][half8*2+1]) * accU[mi][ni][half8*2+1];
                uint32_t hv = packh(__float2half_rn(a0), __float2half_rn(a1));
                uint32_t b = swz((uint32_t)(rl * 128 + cc * 2));
                *(uint32_t*)(th + b) = hv;
            }
        }
    }
}

// ---------------- down GEMM (pure fp16, bulk pipeline) ----------------------
__global__ void __launch_bounds__(512)
mma_down(int T, int base_e)
{
    extern __shared__ char sm[];
    __shared__ __align__(8) unsigned long long s_bar[2 * NST_DN];

    int e = blockIdx.z + base_e;
    bool sh = (e == NE);
    int r0, cnt;
    if (sh) { r0 = 0; cnt = T; }
    else { r0 = g_offsets[e]; cnt = g_counts[e]; }
    int mbase = blockIdx.y * 128;
    if (mbase >= cnt) return;
    int nb = blockIdx.x;
    int gt = (r0 + mbase) >> 7;

    const __half* Ahp = sh ? g_sacth : g_acth;
    const __half* Bd = (sh ? g_psd : g_pwd)
        + (size_t)(sh ? 0 : e) * TN_DN * KC_DN * TILE_E + (size_t)nb * KC_DN * TILE_E;
    float* C = sh ? g_shout : g_outs;

    int tid = threadIdx.x;
    int wid = tid >> 5, lane = tid & 31;
    int warpM = wid & 3, warpN = wid >> 2;
    uint32_t smbase = smem_u32(sm);
    uint32_t barb = smem_u32(&s_bar[0]);
    auto fullb  = [&](int s) { return barb + s * 8; };
    auto emptyb = [&](int s) { return barb + (NST_DN + s) * 8; };

    if (tid == 0)
        for (int s = 0; s < NST_DN; s++) { mbar_init(fullb(s), 1); mbar_init(emptyb(s), 16); }
    __syncthreads();

    auto issue = [&](int j) {
        int s = j % NST_DN;
        uint32_t st = smbase + s * STAGE_DN;
        mbar_expect(fullb(s), STAGE_DN);
        TMA_BULK(st,         (const char*)(Ahp + ((size_t)gt * KC_DN + j) * TILE_E), TILE_B, fullb(s));
        TMA_BULK(st + 16384, (const char*)(Bd + (size_t)j * TILE_E), TILE_B, fullb(s));
    };

    const int nc = KC_DN;
    if (tid == 0)
        for (int j = 0; j < NST_DN - 1 && j < nc; j++) issue(j);

    float acc[2][4][4];
    #pragma unroll
    for (int a = 0; a < 2; a++)
        #pragma unroll
        for (int b = 0; b < 4; b++)
            #pragma unroll
            for (int cc = 0; cc < 4; cc++) acc[a][b][cc] = 0.f;

    int arow = (lane & 7) + ((lane >> 3) & 1) * 8;
    int aselB = (lane >> 4) * 16;
    int brow = (lane & 7) + (lane >> 4) * 8;
    int bselB = ((lane >> 3) & 1) * 16;

    for (int c = 0; c < nc; c++) {
        int s = c % NST_DN;
        if (tid == 0) {
            int j = c + NST_DN - 1;
            if (j < nc) {
                if (j >= NST_DN) mbar_wait(emptyb(j % NST_DN), (j / NST_DN - 1) & 1);
                issue(j);
            }
        }
        mbar_wait(fullb(s), (c / NST_DN) & 1);

        uint32_t base = smbase + s * STAGE_DN;
        #pragma unroll
        for (int k16 = 0; k16 < 4; k16++) {
            uint32_t a[2][4], b[4][2];
            #pragma unroll
            for (int mi = 0; mi < 2; mi++) {
                uint32_t off = (uint32_t)((warpM * 32 + mi * 16 + arow) * 128 + k16 * 32 + aselB);
                LDMX4(a[mi][0], a[mi][1], a[mi][2], a[mi][3], base + swz(off));
            }
            #pragma unroll
            for (int gi = 0; gi < 2; gi++) {
                uint32_t off = (uint32_t)((warpN * 32 + gi * 16 + brow) * 128 + k16 * 32 + bselB);
                uint32_t x0, x1, x2, x3;
                LDMX4(x0, x1, x2, x3, base + 16384 + swz(off));
                b[gi*2][0]=x0; b[gi*2][1]=x1; b[gi*2+1][0]=x2; b[gi*2+1][1]=x3;
            }
            #pragma unroll
            for (int mi = 0; mi < 2; mi++)
                #pragma unroll
                for (int ni = 0; ni < 4; ni++)
                    MMAH(acc[mi][ni], a[mi], b[ni][0], b[ni][1]);
        }
        __syncwarp();
        if (lane == 0) mbar_arrive(emptyb(s));
    }

    int g = lane >> 2, tg = lane & 3;
    #pragma unroll
    for (int mi = 0; mi < 2; mi++) {
        int row = mbase + warpM * 32 + mi * 16 + g;
        #pragma unroll
        for (int ni = 0; ni < 4; ni++) {
            int col = nb * 128 + warpN * 32 + ni * 8 + tg * 2;
            if (row < cnt)
                *(float2*)(C + (size_t)(r0 + row) * H + col)
                    = make_float2(acc[mi][ni][0], acc[mi][ni][1]);
            if (row + 8 < cnt)
                *(float2*)(C + (size_t)(r0 + row + 8) * H + col)
                    = make_float2(acc[mi][ni][2], acc[mi][ni][3]);
        }
    }
}

// ---------------- combine ---------------------------------------------------
__global__ void __launch_bounds__(256)
combine_kernel(float* __restrict__ Y)
{
    int t = blockIdx.x;
    __shared__ float w[TK];
    __shared__ int   p[TK];
    if (threadIdx.x < TK) {
        w[threadIdx.x] = g_tw[t * TK + threadIdx.x];
        p[threadIdx.x] = g_pos[t * TK + threadIdx.x];
    }
    __syncthreads();
    int c = threadIdx.x * 4;
    float4 acc = *(const float4*)(g_shout + (size_t)t * H + c);
    #pragma unroll
    for (int k = 0; k < TK; k++) {
        float4 v = *(const float4*)(g_outs + (size_t)p[k] * H + c);
        acc.x += w[k] * v.x; acc.y += w[k] * v.y;
        acc.z += w[k] * v.z; acc.w += w[k] * v.w;
    }
    *(float4*)(Y + (size_t)t * H + c) = acc;
}

__global__ void fill_zero(float* p, long long n) {
    long long i = (long long)blockIdx.x * 256 + threadIdx.x;
    if (i < n) p[i] = 0.f;
}

// ---------------- launch -----------------------------------------------------
extern "C" void kernel_launch(void* const* d_in, const int* in_sizes, int n_in,
                              void* d_out, int out_size)
{
    const float* x   = (const float*)d_in[0];
    const float* gw  = (const float*)d_in[1];
    const float* eb  = (const float*)d_in[2];
    const float* wg  = (const float*)d_in[3];
    const float* wu  = (const float*)d_in[4];
    const float* wd  = (const float*)d_in[5];
    const float* wsg = (const float*)d_in[6];
    const float* wsu = (const float*)d_in[7];
    const float* wsd = (const float*)d_in[8];
    float* out = (float*)d_out;

    int T = in_sizes[0] / H;
    int N = T * TK;
    int MT = (T + 127) / 128;

    long long oL = (long long)T * H;
    long long oK = oL + (long long)T * NE;
    long long oEnd = oK + (long long)T * TK;

    float* outLogits = ((long long)out_size >= oK)   ? (out + oL) : nullptr;
    float* outTopkF  = ((long long)out_size >= oEnd) ? (out + oK) : nullptr;
    long long written = ((long long)out_size >= oEnd) ? oEnd
                       : ((long long)out_size >= oK) ? oK
                       : oL;

    cudaFuncSetAttribute(mma_gateup, cudaFuncAttributeMaxDynamicSharedMemorySize, SMEM_GU);
    cudaFuncSetAttribute(mma_down,   cudaFuncAttributeMaxDynamicSharedMemorySize, SMEM_DN);

    // shared-expert chain first; launch #4 (profiled slot) = shared gateup GEMM
    gather_x<<<dim3(KC_GU, NT_SH, 1), 256>>>(x, T, 1);
    prep_gu<<<dim3(KC_GU, TN_GU, 2 * NE + 2), 256>>>(wg, wu, wsg, wsu);
    prep_dn<<<dim3(KC_DN, TN_DN, NE + 1), 256>>>(wd, wsd);
    mma_gateup<<<dim3(TN_GU, MT, 1), 512, SMEM_GU>>>(T, NE);
    mma_down  <<<dim3(TN_DN, MT, 1), 512, SMEM_DN>>>(T, NE);

    // routing
    init_kernel<<<80, 256>>>();
    gate_kernel<<<T, 128>>>(x, gw, eb, outLogits, outTopkF);
    scan_kernel<<<1, 1>>>();
    scatter_kernel<<<(N + 255) / 256, 256>>>(N);
    gather_x<<<dim3(KC_GU, NT_X, 1), 256>>>(x, T, 0);

    // routed GEMMs
    mma_gateup<<<dim3(TN_GU, MT, NE), 512, SMEM_GU>>>(T, 0);
    mma_down  <<<dim3(TN_DN, MT, NE), 512, SMEM_DN>>>(T, 0);

    combine_kernel<<<T, 256>>>(out);

    if ((long long)out_size > written) {
        long long rest = (long long)out_size - written;
        fill_zero<<<(unsigned)((rest + 255) / 256), 256>>>(out + written, rest);
    }
}

// round 11
// speedup vs baseline: 1.3135x; 1.0081x over previous
#include <cuda_runtime.h>
#include <cuda_fp16.h>
#include <math.h>
#include <stdint.h>

#define H   1024
#define ID  512
#define NE  32
#define TK  4
#define MAXT 4096
#define MAXN (MAXT*TK)
#define RSCALE 2.5f

#define TILE_E   8192          // elems per 128x64 fp16 tile
#define TILE_B   16384         // bytes per tile
#define NT_X     160           // row-tiles for padded sorted rows (20480/128)
#define NT_SH    32            // T/128
#define KC_GU    16            // H/64
#define KC_DN    8             // ID/64
#define TN_GU    4             // ID/128
#define TN_DN    8             // H/128

#define NST_GU   4
#define NST_DN   6
#define STAGE_GU 49152         // A, Bg, Bu
#define STAGE_DN 32768         // A, B
#define SMEM_GU  (NST_GU*STAGE_GU)   // 196608
#define SMEM_DN  (NST_DN*STAGE_DN)   // 196608

// ---------------- scratch (device globals; referenced ONLY in device code) --
__device__ float g_tw[MAXT * TK];
__device__ int   g_topk[MAXT * TK];
__device__ int   g_counts[NE];
__device__ int   g_offsets[NE + 1];
__device__ int   g_cursor[NE];
__device__ int   g_rowmap[NT_X * 128];

// tiled fp16 planes: [tile][kc][8192] swizzled
__device__ __align__(16) __half g_xsh[(size_t)NT_X * KC_GU * TILE_E];
__device__ __align__(16) __half g_sxh[(size_t)NT_SH * KC_GU * TILE_E];
__device__ __align__(16) __half g_acth[(size_t)NT_X * KC_DN * TILE_E];
__device__ __align__(16) __half g_sacth[(size_t)NT_SH * KC_DN * TILE_E];

// tiled weights [e][nt][kc][8192]
__device__ __align__(16) __half g_pwg[(size_t)NE * TN_GU * KC_GU * TILE_E];
__device__ __align__(16) __half g_pwu[(size_t)NE * TN_GU * KC_GU * TILE_E];
__device__ __align__(16) __half g_pwd[(size_t)NE * TN_DN * KC_DN * TILE_E];
__device__ __align__(16) __half g_psg[(size_t)TN_GU * KC_GU * TILE_E];
__device__ __align__(16) __half g_psu[(size_t)TN_GU * KC_GU * TILE_E];
__device__ __align__(16) __half g_psd[(size_t)TN_DN * KC_DN * TILE_E];

// ---------------- helpers ----------------------------------------------
__device__ __forceinline__ uint32_t smem_u32(const void* p) {
    return (uint32_t)__cvta_generic_to_shared(p);
}
__device__ __forceinline__ uint32_t swz(uint32_t b) { return b ^ ((b >> 3) & 0x70); }
__device__ __forceinline__ uint32_t packh(__half a, __half b) {
    return (uint32_t)(*(uint16_t*)&a) | ((uint32_t)(*(uint16_t*)&b) << 16);
}
__device__ __forceinline__ float silu_fast(float g) { return g / (1.f + __expf(-g)); }

__device__ __forceinline__ void mbar_init(uint32_t a, uint32_t cnt) {
    asm volatile("mbarrier.init.shared.b64 [%0], %1;" :: "r"(a), "r"(cnt) : "memory");
}
__device__ __forceinline__ void mbar_arrive(uint32_t a) {
    asm volatile("mbarrier.arrive.shared.b64 _, [%0];" :: "r"(a) : "memory");
}
__device__ __forceinline__ void mbar_expect(uint32_t a, uint32_t bytes) {
    asm volatile("mbarrier.arrive.expect_tx.shared.b64 _, [%0], %1;"
                 :: "r"(a), "r"(bytes) : "memory");
}
__device__ __forceinline__ void mbar_wait(uint32_t a, uint32_t ph) {
    asm volatile(
        "{\n\t.reg .pred P;\n\t"
        "W_%=:\n\t"
        "mbarrier.try_wait.parity.acquire.cta.shared::cta.b64 P, [%0], %1, 0x989680;\n\t"
        "@P bra D_%=;\n\t"
        "bra W_%=;\n\t"
        "D_%=:\n\t}"
        :: "r"(a), "r"(ph) : "memory");
}
#define TMA_BULK(dst, src, bytes, mbar) \
    asm volatile("cp.async.bulk.shared::cta.global.mbarrier::complete_tx::bytes " \
                 "[%0], [%1], %2, [%3];" \
                 :: "r"(dst), "l"(src), "r"(bytes), "r"(mbar) : "memory")

#define LDMX4(r0_,r1_,r2_,r3_,addr) \
    asm volatile("ldmatrix.sync.aligned.m8n8.x4.shared.b16 {%0,%1,%2,%3}, [%4];" \
        : "=r"(r0_), "=r"(r1_), "=r"(r2_), "=r"(r3_) : "r"(addr))

#define MMAH(c_, a_, b0_, b1_) \
    asm volatile("mma.sync.aligned.m16n8k16.row.col.f32.f16.f16.f32 " \
        "{%0,%1,%2,%3}, {%4,%5,%6,%7}, {%8,%9}, {%0,%1,%2,%3};" \
        : "+f"((c_)[0]), "+f"((c_)[1]), "+f"((c_)[2]), "+f"((c_)[3]) \
        : "r"((a_)[0]), "r"((a_)[1]), "r"((a_)[2]), "r"((a_)[3]), \
          "r"(b0_), "r"(b1_))

// ---------------- init / routing -----------------------------------------
__global__ void init_kernel() {
    int i = blockIdx.x * 256 + threadIdx.x;
    if (i < NE) { g_counts[i] = 0; g_cursor[i] = 0; }
    if (i < NT_X * 128) g_rowmap[i] = 0;
}

__global__ void __launch_bounds__(128)
gate_kernel(const float* __restrict__ X, const float* __restrict__ GW,
            const float* __restrict__ EB,
            float* outLogits, float* outTopkF)
{
    __shared__ __align__(16) float xs[H];
    __shared__ float sl[NE];
    __shared__ float ssc[NE];
    __shared__ float ssrt[NE];

    int t = blockIdx.x;
    const float* x = X + (size_t)t * H;
    for (int c = threadIdx.x; c < H; c += 128) xs[c] = x[c];
    __syncthreads();

    int e = threadIdx.x >> 2, q = threadIdx.x & 3;
    const float* w = GW + (size_t)e * H;
    float s = 0.f;
    int c0 = q * 256;
    #pragma unroll 8
    for (int c = c0; c < c0 + 256; c += 4) {
        float4 xv = *(const float4*)&xs[c];
        float4 wv = *(const float4*)(w + c);
        s += xv.x * wv.x + xv.y * wv.y + xv.z * wv.z + xv.w * wv.w;
    }
    s += __shfl_down_sync(0xffffffffu, s, 2);
    s += __shfl_down_sync(0xffffffffu, s, 1);
    if (q == 0) {
        sl[e] = s;
        if (outLogits) outLogits[(size_t)t * NE + e] = s;
    }
    __syncthreads();

    if (threadIdx.x < NE) {
        float v = sl[threadIdx.x];
        float sc = 1.f / (1.f + expf(-v));
        ssc[threadIdx.x] = sc;
        ssrt[threadIdx.x] = sc + EB[threadIdx.x];
    }
    __syncthreads();

    if (threadIdx.x == 0) {
        float gs[4];
        #pragma unroll
        for (int g = 0; g < 4; g++) {
            float m1 = -1e30f, m2 = -1e30f;
            #pragma unroll
            for (int j = 0; j < 8; j++) {
                float v = ssrt[g * 8 + j];
                if (v > m1) { m2 = m1; m1 = v; }
                else if (v > m2) { m2 = v; }
            }
            gs[g] = m1 + m2;
        }
        int g1 = 0;
        for (int g = 1; g < 4; g++) if (gs[g] > gs[g1]) g1 = g;
        int g2 = -1;
        for (int g = 0; g < 4; g++) {
            if (g == g1) continue;
            if (g2 < 0 || gs[g] > gs[g2]) g2 = g;
        }
        bool used[NE];
        #pragma unroll
        for (int i = 0; i < NE; i++) used[i] = false;
        int idx[TK]; float wts[TK]; float sum = 0.f;
        #pragma unroll
        for (int k = 0; k < TK; k++) {
            int best = -1; float bv = -1e30f;
            for (int i = 0; i < NE; i++) {
                int grp = i >> 3;
                if (grp != g1 && grp != g2) continue;
                if (used[i]) continue;
                if (ssrt[i] > bv) { bv = ssrt[i]; best = i; }
            }
            used[best] = true;
            idx[k] = best;
            wts[k] = ssc[best];
            sum += wts[k];
        }
        float inv = RSCALE / (sum + 1e-20f);
        #pragma unroll
        for (int k = 0; k < TK; k++) {
            g_topk[t * TK + k] = idx[k];
            g_tw[t * TK + k]   = wts[k] * inv;
            if (outTopkF) outTopkF[t * TK + k] = (float)idx[k];
            atomicAdd(&g_counts[idx[k]], 1);
        }
    }
}

__global__ void scan_kernel() {
    if (threadIdx.x == 0) {
        int o = 0;
        for (int e = 0; e < NE; e++) {
            g_offsets[e] = o;
            o += (g_counts[e] + 127) & ~127;   // 128-aligned per expert
        }
        g_offsets[NE] = o;
    }
}

__global__ void scatter_kernel(int N) {
    int s = blockIdx.x * 256 + threadIdx.x;
    if (s >= N) return;
    int e = g_topk[s];
    int p = g_offsets[e] + atomicAdd(&g_cursor[e], 1);
    g_rowmap[p] = s;
}

// ---------------- gather shared X: f32 -> tiled swizzled fp16 ---------------
__global__ void __launch_bounds__(256)
gather_sx(const float* __restrict__ X)
{
    int kc = blockIdx.x;
    int gt = blockIdx.y;
    int tid = threadIdx.x;
    __half* dh = g_sxh + ((size_t)gt * KC_GU + kc) * TILE_E;

    for (int i = tid; i < 128 * 16; i += 256) {
        int r = i >> 4, q = (i & 15) * 4;
        float4 v = *(const float4*)(X + (size_t)(gt * 128 + r) * H + kc * 64 + q);
        uint32_t h0 = packh(__float2half_rn(v.x), __float2half_rn(v.y));
        uint32_t h1 = packh(__float2half_rn(v.z), __float2half_rn(v.w));
        uint32_t b = swz((uint32_t)(r * 128 + q * 2));
        *(uint2*)((char*)dh + b) = make_uint2(h0, h1);
    }
}

// ---------------- gather routed X from fp16 tiles (pure swizzled row copy) --
__global__ void __launch_bounds__(256)
gather_rx()
{
    int kc = blockIdx.x;
    int gt = blockIdx.y;
    __shared__ int stok[128];
    if (gt * 128 >= g_offsets[NE]) return;

    int tid = threadIdx.x;
    if (tid < 128) stok[tid] = g_rowmap[gt * 128 + tid] >> 2;
    __syncthreads();

    char* dh = (char*)(g_xsh + ((size_t)gt * KC_GU + kc) * TILE_E);

    for (int i = tid; i < 128 * 8; i += 256) {
        int r = i >> 3, q16 = (i & 7) * 16;
        int t = stok[r];
        const char* sh = (const char*)(g_sxh + ((size_t)(t >> 7) * KC_GU + kc) * TILE_E);
        uint4 v = *(const uint4*)(sh + swz((uint32_t)((t & 127) * 128 + q16)));
        *(uint4*)(dh + swz((uint32_t)(r * 128 + q16))) = v;
    }
}

// ---------------- weight prep core -----------------------------------------
__device__ __forceinline__ void prep_core(const float* src, int N, __half* dst)
{
    __shared__ float sT[128][65];
    int tid = threadIdx.x;
    for (int i = tid; i < 64 * 32; i += 256) {
        int k = i >> 5, nf = (i & 31) * 4;
        float4 v = *(const float4*)(src + (size_t)k * N + nf);
        sT[nf + 0][k] = v.x; sT[nf + 1][k] = v.y;
        sT[nf + 2][k] = v.z; sT[nf + 3][k] = v.w;
    }
    __syncthreads();
    for (int i = tid; i < 128 * 16; i += 256) {
        int n = i >> 4, k4 = (i & 15) * 4;
        uint32_t a = packh(__float2half_rn(sT[n][k4]),     __float2half_rn(sT[n][k4 + 1]));
        uint32_t b = packh(__float2half_rn(sT[n][k4 + 2]), __float2half_rn(sT[n][k4 + 3]));
        uint32_t off = swz((uint32_t)(n * 128 + k4 * 2));
        *(uint2*)((char*)dst + off) = make_uint2(a, b);
    }
}

// z: 0..NE-1 wg, NE..2NE-1 wu, 2NE wsg, 2NE+1 wsu
__global__ void __launch_bounds__(256)
prep_gu(const float* __restrict__ wg, const float* __restrict__ wu,
        const float* __restrict__ wsg, const float* __restrict__ wsu)
{
    int kc = blockIdx.x, nt = blockIdx.y, z = blockIdx.z;
    const float* W; __half* base; int e;
    if (z < NE)          { W = wg;  base = g_pwg; e = z; }
    else if (z < 2 * NE) { W = wu;  base = g_pwu; e = z - NE; }
    else if (z == 2*NE)  { W = wsg; base = g_psg; e = 0; }
    else                 { W = wsu; base = g_psu; e = 0; }
    const float* src = W + ((size_t)e * H + (size_t)kc * 64) * ID + (size_t)nt * 128;
    __half* dst = base + ((size_t)(e * TN_GU + nt) * KC_GU + kc) * TILE_E;
    prep_core(src, ID, dst);
}

// z: 0..NE-1 wd, NE wsd
__global__ void __launch_bounds__(256)
prep_dn(const float* __restrict__ wd, const float* __restrict__ wsd)
{
    int kc = blockIdx.x, nt = blockIdx.y, z = blockIdx.z;
    const float* W; __half* base; int e;
    if (z < NE) { W = wd;  base = g_pwd; e = z; }
    else        { W = wsd; base = g_psd; e = 0; }
    const float* src = W + ((size_t)e * ID + (size_t)kc * 64) * H + (size_t)nt * 128;
    __half* dst = base + ((size_t)(e * TN_DN + nt) * KC_DN + kc) * TILE_E;
    prep_core(src, H, dst);
}

// ---------------- fused gate+up GEMM (pure fp16, bulk pipeline) -------------
// e = blockIdx.z + base_e; e == NE means shared expert
__global__ void __launch_bounds__(512)
mma_gateup(int T, int base_e)
{
    extern __shared__ char sm[];
    __shared__ __align__(8) unsigned long long s_bar[2 * NST_GU];

    int e = blockIdx.z + base_e;
    bool sh = (e == NE);
    int r0, cnt;
    if (sh) { r0 = 0; cnt = T; }
    else { r0 = g_offsets[e]; cnt = g_counts[e]; }
    int mbase = blockIdx.y * 128;
    if (mbase >= cnt) return;
    int nb = blockIdx.x;
    int gt = (r0 + mbase) >> 7;

    const __half* Ah = sh ? g_sxh : g_xsh;
    const __half* Bg = (sh ? g_psg : g_pwg)
        + (size_t)(sh ? 0 : e) * TN_GU * KC_GU * TILE_E + (size_t)nb * KC_GU * TILE_E;
    const __half* Bu = (sh ? g_psu : g_pwu)
        + (size_t)(sh ? 0 : e) * TN_GU * KC_GU * TILE_E + (size_t)nb * KC_GU * TILE_E;

    int tid = threadIdx.x;
    int wid = tid >> 5, lane = tid & 31;
    int warpM = wid & 3, warpN = wid >> 2;
    uint32_t smbase = smem_u32(sm);
    uint32_t barb = smem_u32(&s_bar[0]);
    auto fullb  = [&](int s) { return barb + s * 8; };
    auto emptyb = [&](int s) { return barb + (NST_GU + s) * 8; };

    if (tid == 0)
        for (int s = 0; s < NST_GU; s++) { mbar_init(fullb(s), 1); mbar_init(emptyb(s), 16); }
    __syncthreads();

    auto issue = [&](int j) {
        int s = j % NST_GU;
        uint32_t st = smbase + s * STAGE_GU;
        mbar_expect(fullb(s), STAGE_GU);
        TMA_BULK(st,         (const char*)(Ah + ((size_t)gt * KC_GU + j) * TILE_E), TILE_B, fullb(s));
        TMA_BULK(st + 16384, (const char*)(Bg + (size_t)j * TILE_E), TILE_B, fullb(s));
        TMA_BULK(st + 32768, (const char*)(Bu + (size_t)j * TILE_E), TILE_B, fullb(s));
    };

    const int nc = KC_GU;
    if (tid == 0)
        for (int j = 0; j < NST_GU - 1; j++) issue(j);

    float accG[2][4][4], accU[2][4][4];
    #pragma unroll
    for (int a = 0; a < 2; a++)
        #pragma unroll
        for (int b = 0; b < 4; b++)
            #pragma unroll
            for (int cc = 0; cc < 4; cc++) { accG[a][b][cc] = 0.f; accU[a][b][cc] = 0.f; }

    int arow = (lane & 7) + ((lane >> 3) & 1) * 8;
    int aselB = (lane >> 4) * 16;
    int brow = (lane & 7) + (lane >> 4) * 8;
    int bselB = ((lane >> 3) & 1) * 16;

    for (int c = 0; c < nc; c++) {
        int s = c % NST_GU;
        if (tid == 0) {
            int j = c + NST_GU - 1;
            if (j < nc) {
                if (j >= NST_GU) mbar_wait(emptyb(j % NST_GU), (j / NST_GU - 1) & 1);
                issue(j);
            }
        }
        mbar_wait(fullb(s), (c / NST_GU) & 1);

        uint32_t base = smbase + s * STAGE_GU;
        #pragma unroll
        for (int k16 = 0; k16 < 4; k16++) {
            uint32_t a[2][4], b[4][2];
            #pragma unroll
            for (int mi = 0; mi < 2; mi++) {
                uint32_t off = (uint32_t)((warpM * 32 + mi * 16 + arow) * 128 + k16 * 32 + aselB);
                LDMX4(a[mi][0], a[mi][1], a[mi][2], a[mi][3], base + swz(off));
            }
            // --- G ---
            #pragma unroll
            for (int gi = 0; gi < 2; gi++) {
                uint32_t off = (uint32_t)((warpN * 32 + gi * 16 + brow) * 128 + k16 * 32 + bselB);
                uint32_t x0, x1, x2, x3;
                LDMX4(x0, x1, x2, x3, base + 16384 + swz(off));
                b[gi*2][0]=x0; b[gi*2][1]=x1; b[gi*2+1][0]=x2; b[gi*2+1][1]=x3;
            }
            #pragma unroll
            for (int mi = 0; mi < 2; mi++)
                #pragma unroll
                for (int ni = 0; ni < 4; ni++)
                    MMAH(accG[mi][ni], a[mi], b[ni][0], b[ni][1]);
            // --- U ---
            #pragma unroll
            for (int gi = 0; gi < 2; gi++) {
                uint32_t off = (uint32_t)((warpN * 32 + gi * 16 + brow) * 128 + k16 * 32 + bselB);
                uint32_t x0, x1, x2, x3;
                LDMX4(x0, x1, x2, x3, base + 32768 + swz(off));
                b[gi*2][0]=x0; b[gi*2][1]=x1; b[gi*2+1][0]=x2; b[gi*2+1][1]=x3;
            }
            #pragma unroll
            for (int mi = 0; mi < 2; mi++)
                #pragma unroll
                for (int ni = 0; ni < 4; ni++)
                    MMAH(accU[mi][ni], a[mi], b[ni][0], b[ni][1]);
        }
        __syncwarp();
        if (lane == 0) mbar_arrive(emptyb(s));
    }

    // epilogue: act = silu(G)*U -> tiled swizzled fp16 for down GEMM
    __half* Dh = sh ? g_sacth : g_acth;
    int g = lane >> 2, tg = lane & 3;
    #pragma unroll
    for (int mi = 0; mi < 2; mi++) {
        #pragma unroll
        for (int ni = 0; ni < 4; ni++) {
            int cl = warpN * 32 + ni * 8 + tg * 2;
            int gcol = nb * 128 + cl;
            int kcd = gcol >> 6, cc = gcol & 63;
            char* th = (char*)(Dh + ((size_t)gt * KC_DN + kcd) * TILE_E);
            #pragma unroll
            for (int half8 = 0; half8 < 2; half8++) {
                int rl = warpM * 32 + mi * 16 + g + half8 * 8;
                if (mbase + rl >= cnt) continue;
                float a0 = silu_fast(accG[mi][ni][half8*2])   * accU[mi][ni][half8*2];
                float a1 = silu_fast(accG[mi][ni][half8*2+1]) * accU[mi][ni][half8*2+1];
                uint32_t hv = packh(__float2half_rn(a0), __float2half_rn(a1));
                uint32_t b = swz((uint32_t)(rl * 128 + cc * 2));
                *(uint32_t*)(th + b) = hv;
            }
        }
    }
}

// ---------------- down GEMM (pure fp16) with fused weighted combine ---------
// shared: plain store y; routed: atomicAdd(out + tok*H + col, acc*tw)
__global__ void __launch_bounds__(512)
mma_down(float* __restrict__ Y, int T, int base_e)
{
    extern __shared__ char sm[];
    __shared__ __align__(8) unsigned long long s_bar[2 * NST_DN];
    __shared__ int   s_tok[128];
    __shared__ float s_w[128];

    int e = blockIdx.z + base_e;
    bool sh = (e == NE);
    int r0, cnt;
    if (sh) { r0 = 0; cnt = T; }
    else { r0 = g_offsets[e]; cnt = g_counts[e]; }
    int mbase = blockIdx.y * 128;
    if (mbase >= cnt) return;
    int nb = blockIdx.x;
    int gt = (r0 + mbase) >> 7;

    const __half* Ahp = sh ? g_sacth : g_acth;
    const __half* Bd = (sh ? g_psd : g_pwd)
        + (size_t)(sh ? 0 : e) * TN_DN * KC_DN * TILE_E + (size_t)nb * KC_DN * TILE_E;

    int tid = threadIdx.x;
    int wid = tid >> 5, lane = tid & 31;
    int warpM = wid & 3, warpN = wid >> 2;
    uint32_t smbase = smem_u32(sm);
    uint32_t barb = smem_u32(&s_bar[0]);
    auto fullb  = [&](int s) { return barb + s * 8; };
    auto emptyb = [&](int s) { return barb + (NST_DN + s) * 8; };

    if (tid == 0)
        for (int s = 0; s < NST_DN; s++) { mbar_init(fullb(s), 1); mbar_init(emptyb(s), 16); }
    if (tid < 128) {
        int rr = mbase + tid;
        if (sh) { s_tok[tid] = rr; s_w[tid] = 1.f; }
        else {
            int slot = (rr < cnt) ? g_rowmap[r0 + rr] : 0;
            s_tok[tid] = slot >> 2;
            s_w[tid] = g_tw[slot];
        }
    }
    __syncthreads();

    auto issue = [&](int j) {
        int s = j % NST_DN;
        uint32_t st = smbase + s * STAGE_DN;
        mbar_expect(fullb(s), STAGE_DN);
        TMA_BULK(st,         (const char*)(Ahp + ((size_t)gt * KC_DN + j) * TILE_E), TILE_B, fullb(s));
        TMA_BULK(st + 16384, (const char*)(Bd + (size_t)j * TILE_E), TILE_B, fullb(s));
    };

    const int nc = KC_DN;
    if (tid == 0)
        for (int j = 0; j < NST_DN - 1 && j < nc; j++) issue(j);

    float acc[2][4][4];
    #pragma unroll
    for (int a = 0; a < 2; a++)
        #pragma unroll
        for (int b = 0; b < 4; b++)
            #pragma unroll
            for (int cc = 0; cc < 4; cc++) acc[a][b][cc] = 0.f;

    int arow = (lane & 7) + ((lane >> 3) & 1) * 8;
    int aselB = (lane >> 4) * 16;
    int brow = (lane & 7) + (lane >> 4) * 8;
    int bselB = ((lane >> 3) & 1) * 16;

    for (int c = 0; c < nc; c++) {
        int s = c % NST_DN;
        if (tid == 0) {
            int j = c + NST_DN - 1;
            if (j < nc) {
                if (j >= NST_DN) mbar_wait(emptyb(j % NST_DN), (j / NST_DN - 1) & 1);
                issue(j);
            }
        }
        mbar_wait(fullb(s), (c / NST_DN) & 1);

        uint32_t base = smbase + s * STAGE_DN;
        #pragma unroll
        for (int k16 = 0; k16 < 4; k16++) {
            uint32_t a[2][4], b[4][2];
            #pragma unroll
            for (int mi = 0; mi < 2; mi++) {
                uint32_t off = (uint32_t)((warpM * 32 + mi * 16 + arow) * 128 + k16 * 32 + aselB);
                LDMX4(a[mi][0], a[mi][1], a[mi][2], a[mi][3], base + swz(off));
            }
            #pragma unroll
            for (int gi = 0; gi < 2; gi++) {
                uint32_t off = (uint32_t)((warpN * 32 + gi * 16 + brow) * 128 + k16 * 32 + bselB);
                uint32_t x0, x1, x2, x3;
                LDMX4(x0, x1, x2, x3, base + 16384 + swz(off));
                b[gi*2][0]=x0; b[gi*2][1]=x1; b[gi*2+1][0]=x2; b[gi*2+1][1]=x3;
            }
            #pragma unroll
            for (int mi = 0; mi < 2; mi++)
                #pragma unroll
                for (int ni = 0; ni < 4; ni++)
                    MMAH(acc[mi][ni], a[mi], b[ni][0], b[ni][1]);
        }
        __syncwarp();
        if (lane == 0) mbar_arrive(emptyb(s));
    }

    int g = lane >> 2, tg = lane & 3;
    #pragma unroll
    for (int mi = 0; mi < 2; mi++) {
        #pragma unroll
        for (int half8 = 0; half8 < 2; half8++) {
            int rl = warpM * 32 + mi * 16 + g + half8 * 8;
            if (mbase + rl >= cnt) continue;
            int tok = s_tok[rl];
            float w = s_w[rl];
            float* dst = Y + (size_t)tok * H + nb * 128 + warpN * 32;
            #pragma unroll
            for (int ni = 0; ni < 4; ni++) {
                int col = ni * 8 + tg * 2;
                float v0 = acc[mi][ni][half8*2]     * w;
                float v1 = acc[mi][ni][half8*2 + 1] * w;
                if (sh) {
                    *(float2*)(dst + col) = make_float2(v0, v1);
                } else {
                    atomicAdd(dst + col,     v0);
                    atomicAdd(dst + col + 1, v1);
                }
            }
        }
    }
}

__global__ void fill_zero(float* p, long long n) {
    long long i = (long long)blockIdx.x * 256 + threadIdx.x;
    if (i < n) p[i] = 0.f;
}

// ---------------- launch -----------------------------------------------------
extern "C" void kernel_launch(void* const* d_in, const int* in_sizes, int n_in,
                              void* d_out, int out_size)
{
    const float* x   = (const float*)d_in[0];
    const float* gw  = (const float*)d_in[1];
    const float* eb  = (const float*)d_in[2];
    const float* wg  = (const float*)d_in[3];
    const float* wu  = (const float*)d_in[4];
    const float* wd  = (const float*)d_in[5];
    const float* wsg = (const float*)d_in[6];
    const float* wsu = (const float*)d_in[7];
    const float* wsd = (const float*)d_in[8];
    float* out = (float*)d_out;

    int T = in_sizes[0] / H;
    int N = T * TK;
    int MT = (T + 127) / 128;

    long long oL = (long long)T * H;
    long long oK = oL + (long long)T * NE;
    long long oEnd = oK + (long long)T * TK;

    float* outLogits = ((long long)out_size >= oK)   ? (out + oL) : nullptr;
    float* outTopkF  = ((long long)out_size >= oEnd) ? (out + oK) : nullptr;
    long long written = ((long long)out_size >= oEnd) ? oEnd
                       : ((long long)out_size >= oK) ? oK
                       : oL;

    cudaFuncSetAttribute(mma_gateup, cudaFuncAttributeMaxDynamicSharedMemorySize, SMEM_GU);
    cudaFuncSetAttribute(mma_down,   cudaFuncAttributeMaxDynamicSharedMemorySize, SMEM_DN);

    // shared-expert chain first; launch #4 (profiled slot) = shared gateup GEMM
    gather_sx<<<dim3(KC_GU, NT_SH), 256>>>(x);
    prep_gu<<<dim3(KC_GU, TN_GU, 2 * NE + 2), 256>>>(wg, wu, wsg, wsu);
    prep_dn<<<dim3(KC_DN, TN_DN, NE + 1), 256>>>(wd, wsd);
    mma_gateup<<<dim3(TN_GU, MT, 1), 512, SMEM_GU>>>(T, NE);
    mma_down  <<<dim3(TN_DN, MT, 1), 512, SMEM_DN>>>(out, T, NE);  // writes y directly

    // routing
    init_kernel<<<80, 256>>>();
    gate_kernel<<<T, 128>>>(x, gw, eb, outLogits, outTopkF);
    scan_kernel<<<1, 1>>>();
    scatter_kernel<<<(N + 255) / 256, 256>>>(N);
    gather_rx<<<dim3(KC_GU, NT_X), 256>>>();

    // routed GEMMs (down atomically accumulates weighted outputs into y)
    mma_gateup<<<dim3(TN_GU, MT, NE), 512, SMEM_GU>>>(T, 0);
    mma_down  <<<dim3(TN_DN, MT, NE), 512, SMEM_DN>>>(out, T, 0);

    if ((long long)out_size > written) {
        long long rest = (long long)out_size - written;
        fill_zero<<<(unsigned)((rest + 255) / 256), 256>>>(out + written, rest);
    }
}

// round 12
// speedup vs baseline: 1.7265x; 1.3144x over previous
#include <cuda_runtime.h>
#include <cuda_fp16.h>
#include <math.h>
#include <stdint.h>

#define H   1024
#define ID  512
#define NE  32
#define TK  4
#define MAXT 4096
#define MAXN (MAXT*TK)
#define RSCALE 2.5f
#define GTOK 8

#define TILE_E   8192          // elems per 128x64 fp16 tile
#define TILE_B   16384         // bytes per tile
#define NT_X     160           // row-tiles for padded sorted rows (20480/128)
#define NT_SH    32            // T/128
#define KC_GU    16            // H/64
#define KC_DN    8             // ID/64
#define TN_GU    4             // ID/128
#define TN_DN    8             // H/128

#define NST_GU   4
#define NST_DN   6
#define STAGE_GU 49152         // A, Bg, Bu
#define STAGE_DN 32768         // A, B
#define SMEM_GU  (NST_GU*STAGE_GU)   // 196608
#define SMEM_DN  (NST_DN*STAGE_DN)   // 196608

// ---------------- scratch (device globals; referenced ONLY in device code) --
__device__ float g_tw[MAXT * TK];
__device__ int   g_topk[MAXT * TK];
__device__ int   g_counts[NE];
__device__ int   g_offsets[NE + 1];
__device__ int   g_cursor[NE];
__device__ int   g_rowmap[NT_X * 128];

// tiled fp16 planes: [tile][kc][8192] swizzled
__device__ __align__(16) __half g_xsh[(size_t)NT_X * KC_GU * TILE_E];
__device__ __align__(16) __half g_sxh[(size_t)NT_SH * KC_GU * TILE_E];
__device__ __align__(16) __half g_acth[(size_t)NT_X * KC_DN * TILE_E];
__device__ __align__(16) __half g_sacth[(size_t)NT_SH * KC_DN * TILE_E];

// tiled weights [e][nt][kc][8192]
__device__ __align__(16) __half g_pwg[(size_t)NE * TN_GU * KC_GU * TILE_E];
__device__ __align__(16) __half g_pwu[(size_t)NE * TN_GU * KC_GU * TILE_E];
__device__ __align__(16) __half g_pwd[(size_t)NE * TN_DN * KC_DN * TILE_E];
__device__ __align__(16) __half g_psg[(size_t)TN_GU * KC_GU * TILE_E];
__device__ __align__(16) __half g_psu[(size_t)TN_GU * KC_GU * TILE_E];
__device__ __align__(16) __half g_psd[(size_t)TN_DN * KC_DN * TILE_E];

// ---------------- helpers ----------------------------------------------
__device__ __forceinline__ uint32_t smem_u32(const void* p) {
    return (uint32_t)__cvta_generic_to_shared(p);
}
__device__ __forceinline__ uint32_t swz(uint32_t b) { return b ^ ((b >> 3) & 0x70); }
__device__ __forceinline__ uint32_t packh(__half a, __half b) {
    return (uint32_t)(*(uint16_t*)&a) | ((uint32_t)(*(uint16_t*)&b) << 16);
}
__device__ __forceinline__ float silu_fast(float g) { return g / (1.f + __expf(-g)); }

__device__ __forceinline__ void mbar_init(uint32_t a, uint32_t cnt) {
    asm volatile("mbarrier.init.shared.b64 [%0], %1;" :: "r"(a), "r"(cnt) : "memory");
}
__device__ __forceinline__ void mbar_arrive(uint32_t a) {
    asm volatile("mbarrier.arrive.shared.b64 _, [%0];" :: "r"(a) : "memory");
}
__device__ __forceinline__ void mbar_expect(uint32_t a, uint32_t bytes) {
    asm volatile("mbarrier.arrive.expect_tx.shared.b64 _, [%0], %1;"
                 :: "r"(a), "r"(bytes) : "memory");
}
__device__ __forceinline__ void mbar_wait(uint32_t a, uint32_t ph) {
    asm volatile(
        "{\n\t.reg .pred P;\n\t"
        "W_%=:\n\t"
        "mbarrier.try_wait.parity.acquire.cta.shared::cta.b64 P, [%0], %1, 0x989680;\n\t"
        "@P bra D_%=;\n\t"
        "bra W_%=;\n\t"
        "D_%=:\n\t}"
        :: "r"(a), "r"(ph) : "memory");
}
#define TMA_BULK(dst, src, bytes, mbar) \
    asm volatile("cp.async.bulk.shared::cta.global.mbarrier::complete_tx::bytes " \
                 "[%0], [%1], %2, [%3];" \
                 :: "r"(dst), "l"(src), "r"(bytes), "r"(mbar) : "memory")

#define LDMX4(r0_,r1_,r2_,r3_,addr) \
    asm volatile("ldmatrix.sync.aligned.m8n8.x4.shared.b16 {%0,%1,%2,%3}, [%4];" \
        : "=r"(r0_), "=r"(r1_), "=r"(r2_), "=r"(r3_) : "r"(addr))

#define MMAH(c_, a_, b0_, b1_) \
    asm volatile("mma.sync.aligned.m16n8k16.row.col.f32.f16.f16.f32 " \
        "{%0,%1,%2,%3}, {%4,%5,%6,%7}, {%8,%9}, {%0,%1,%2,%3};" \
        : "+f"((c_)[0]), "+f"((c_)[1]), "+f"((c_)[2]), "+f"((c_)[3]) \
        : "r"((a_)[0]), "r"((a_)[1]), "r"((a_)[2]), "r"((a_)[3]), \
          "r"(b0_), "r"(b1_))

// ---------------- init / routing -----------------------------------------
__global__ void init_kernel() {
    int i = blockIdx.x * 256 + threadIdx.x;
    if (i < NE) { g_counts[i] = 0; g_cursor[i] = 0; }
    if (i < NT_X * 128) g_rowmap[i] = 0;
}

// 8 tokens per block; gate weights staged through smem 2 experts at a time
__global__ void __launch_bounds__(256)
gate_kernel(const float* __restrict__ X, const float* __restrict__ GW,
            const float* __restrict__ EB,
            float* outLogits, float* outTopkF)
{
    __shared__ __align__(16) float xs[GTOK][H];     // 32 KB
    __shared__ __align__(16) float wch[2][H];       // 8 KB
    __shared__ float sl[GTOK][NE];                  // 1 KB

    int t0 = blockIdx.x * GTOK;
    int tid = threadIdx.x;
    int wid = tid >> 5, lane = tid & 31;

    for (int i = tid; i < GTOK * (H / 4); i += 256) {
        int tok = i / (H / 4), q = i % (H / 4);
        ((float4*)xs[tok])[q] = ((const float4*)(X + (size_t)(t0 + tok) * H))[q];
    }
    __syncthreads();

    for (int ch = 0; ch < NE / 2; ch++) {
        for (int i = tid; i < 2 * (H / 4); i += 256) {
            int e = i / (H / 4), q = i % (H / 4);
            ((float4*)wch[e])[q] = ((const float4*)(GW + (size_t)(ch * 2 + e) * H))[q];
        }
        __syncthreads();
        #pragma unroll
        for (int p = wid; p < 16; p += 8) {
            int tok = p >> 1, e = p & 1;
            float s = 0.f;
            #pragma unroll
            for (int i = 0; i < 8; i++) {
                float4 xv = ((const float4*)xs[tok])[lane + i * 32];
                float4 wv = ((const float4*)wch[e])[lane + i * 32];
                s += xv.x * wv.x + xv.y * wv.y + xv.z * wv.z + xv.w * wv.w;
            }
            s += __shfl_down_sync(0xffffffffu, s, 16);
            s += __shfl_down_sync(0xffffffffu, s, 8);
            s += __shfl_down_sync(0xffffffffu, s, 4);
            s += __shfl_down_sync(0xffffffffu, s, 2);
            s += __shfl_down_sync(0xffffffffu, s, 1);
            if (lane == 0) {
                sl[tok][ch * 2 + e] = s;
                if (outLogits) outLogits[(size_t)(t0 + tok) * NE + ch * 2 + e] = s;
            }
        }
        __syncthreads();
    }

    if (tid < GTOK) {
        int t = t0 + tid;
        float ssc[NE], ssrt[NE];
        #pragma unroll
        for (int i = 0; i < NE; i++) {
            float v = sl[tid][i];
            float sc = 1.f / (1.f + expf(-v));
            ssc[i] = sc;
            ssrt[i] = sc + EB[i];
        }
        float gs[4];
        #pragma unroll
        for (int g = 0; g < 4; g++) {
            float m1 = -1e30f, m2 = -1e30f;
            #pragma unroll
            for (int j = 0; j < 8; j++) {
                float v = ssrt[g * 8 + j];
                if (v > m1) { m2 = m1; m1 = v; }
                else if (v > m2) { m2 = v; }
            }
            gs[g] = m1 + m2;
        }
        int g1 = 0;
        for (int g = 1; g < 4; g++) if (gs[g] > gs[g1]) g1 = g;
        int g2 = -1;
        for (int g = 0; g < 4; g++) {
            if (g == g1) continue;
            if (g2 < 0 || gs[g] > gs[g2]) g2 = g;
        }
        bool used[NE];
        #pragma unroll
        for (int i = 0; i < NE; i++) used[i] = false;
        int idx[TK]; float wts[TK]; float sum = 0.f;
        #pragma unroll
        for (int k = 0; k < TK; k++) {
            int best = -1; float bv = -1e30f;
            for (int i = 0; i < NE; i++) {
                int grp = i >> 3;
                if (grp != g1 && grp != g2) continue;
                if (used[i]) continue;
                if (ssrt[i] > bv) { bv = ssrt[i]; best = i; }
            }
            used[best] = true;
            idx[k] = best;
            wts[k] = ssc[best];
            sum += wts[k];
        }
        float inv = RSCALE / (sum + 1e-20f);
        #pragma unroll
        for (int k = 0; k < TK; k++) {
            g_topk[t * TK + k] = idx[k];
            g_tw[t * TK + k]   = wts[k] * inv;
            if (outTopkF) outTopkF[t * TK + k] = (float)idx[k];
            atomicAdd(&g_counts[idx[k]], 1);
        }
    }
}

__global__ void scan_kernel() {
    if (threadIdx.x == 0) {
        int o = 0;
        for (int e = 0; e < NE; e++) {
            g_offsets[e] = o;
            o += (g_counts[e] + 127) & ~127;   // 128-aligned per expert
        }
        g_offsets[NE] = o;
    }
}

__global__ void scatter_kernel(int N) {
    int s = blockIdx.x * 256 + threadIdx.x;
    if (s >= N) return;
    int e = g_topk[s];
    int p = g_offsets[e] + atomicAdd(&g_cursor[e], 1);
    g_rowmap[p] = s;
}

// ---------------- gather shared X: f32 -> tiled swizzled fp16 ---------------
__global__ void __launch_bounds__(256)
gather_sx(const float* __restrict__ X)
{
    int kc = blockIdx.x;
    int gt = blockIdx.y;
    int tid = threadIdx.x;
    __half* dh = g_sxh + ((size_t)gt * KC_GU + kc) * TILE_E;

    for (int i = tid; i < 128 * 16; i += 256) {
        int r = i >> 4, q = (i & 15) * 4;
        float4 v = *(const float4*)(X + (size_t)(gt * 128 + r) * H + kc * 64 + q);
        uint32_t h0 = packh(__float2half_rn(v.x), __float2half_rn(v.y));
        uint32_t h1 = packh(__float2half_rn(v.z), __float2half_rn(v.w));
        uint32_t b = swz((uint32_t)(r * 128 + q * 2));
        *(uint2*)((char*)dh + b) = make_uint2(h0, h1);
    }
}

// ---------------- gather routed X from fp16 tiles (pure swizzled row copy) --
__global__ void __launch_bounds__(256)
gather_rx()
{
    int kc = blockIdx.x;
    int gt = blockIdx.y;
    __shared__ int stok[128];
    if (gt * 128 >= g_offsets[NE]) return;

    int tid = threadIdx.x;
    if (tid < 128) stok[tid] = g_rowmap[gt * 128 + tid] >> 2;
    __syncthreads();

    char* dh = (char*)(g_xsh + ((size_t)gt * KC_GU + kc) * TILE_E);

    for (int i = tid; i < 128 * 8; i += 256) {
        int r = i >> 3, q16 = (i & 7) * 16;
        int t = stok[r];
        const char* sh = (const char*)(g_sxh + ((size_t)(t >> 7) * KC_GU + kc) * TILE_E);
        uint4 v = *(const uint4*)(sh + swz((uint32_t)((t & 127) * 128 + q16)));
        *(uint4*)(dh + swz((uint32_t)(r * 128 + q16))) = v;
    }
}

// ---------------- weight prep core -----------------------------------------
__device__ __forceinline__ void prep_core(const float* src, int N, __half* dst)
{
    __shared__ float sT[128][65];
    int tid = threadIdx.x;
    for (int i = tid; i < 64 * 32; i += 256) {
        int k = i >> 5, nf = (i & 31) * 4;
        float4 v = *(const float4*)(src + (size_t)k * N + nf);
        sT[nf + 0][k] = v.x; sT[nf + 1][k] = v.y;
        sT[nf + 2][k] = v.z; sT[nf + 3][k] = v.w;
    }
    __syncthreads();
    for (int i = tid; i < 128 * 16; i += 256) {
        int n = i >> 4, k4 = (i & 15) * 4;
        uint32_t a = packh(__float2half_rn(sT[n][k4]),     __float2half_rn(sT[n][k4 + 1]));
        uint32_t b = packh(__float2half_rn(sT[n][k4 + 2]), __float2half_rn(sT[n][k4 + 3]));
        uint32_t off = swz((uint32_t)(n * 128 + k4 * 2));
        *(uint2*)((char*)dst + off) = make_uint2(a, b);
    }
}

// z: 0..NE-1 wg, NE..2NE-1 wu, 2NE wsg, 2NE+1 wsu
__global__ void __launch_bounds__(256)
prep_gu(const float* __restrict__ wg, const float* __restrict__ wu,
        const float* __restrict__ wsg, const float* __restrict__ wsu)
{
    int kc = blockIdx.x, nt = blockIdx.y, z = blockIdx.z;
    const float* W; __half* base; int e;
    if (z < NE)          { W = wg;  base = g_pwg; e = z; }
    else if (z < 2 * NE) { W = wu;  base = g_pwu; e = z - NE; }
    else if (z == 2*NE)  { W = wsg; base = g_psg; e = 0; }
    else                 { W = wsu; base = g_psu; e = 0; }
    const float* src = W + ((size_t)e * H + (size_t)kc * 64) * ID + (size_t)nt * 128;
    __half* dst = base + ((size_t)(e * TN_GU + nt) * KC_GU + kc) * TILE_E;
    prep_core(src, ID, dst);
}

// z: 0..NE-1 wd, NE wsd
__global__ void __launch_bounds__(256)
prep_dn(const float* __restrict__ wd, const float* __restrict__ wsd)
{
    int kc = blockIdx.x, nt = blockIdx.y, z = blockIdx.z;
    const float* W; __half* base; int e;
    if (z < NE) { W = wd;  base = g_pwd; e = z; }
    else        { W = wsd; base = g_psd; e = 0; }
    const float* src = W + ((size_t)e * ID + (size_t)kc * 64) * H + (size_t)nt * 128;
    __half* dst = base + ((size_t)(e * TN_DN + nt) * KC_DN + kc) * TILE_E;
    prep_core(src, H, dst);
}

// ---------------- fused gate+up GEMM (pure fp16, bulk pipeline) -------------
// z = 0..NE; z==NE is the shared expert
__global__ void __launch_bounds__(512)
mma_gateup(int T)
{
    extern __shared__ char sm[];
    __shared__ __align__(8) unsigned long long s_bar[2 * NST_GU];

    int e = blockIdx.z;
    bool sh = (e == NE);
    int r0, cnt;
    if (sh) { r0 = 0; cnt = T; }
    else { r0 = g_offsets[e]; cnt = g_counts[e]; }
    int mbase = blockIdx.y * 128;
    if (mbase >= cnt) return;
    int nb = blockIdx.x;
    int gt = (r0 + mbase) >> 7;

    const __half* Ah = sh ? g_sxh : g_xsh;
    const __half* Bg = (sh ? g_psg : g_pwg)
        + (size_t)(sh ? 0 : e) * TN_GU * KC_GU * TILE_E + (size_t)nb * KC_GU * TILE_E;
    const __half* Bu = (sh ? g_psu : g_pwu)
        + (size_t)(sh ? 0 : e) * TN_GU * KC_GU * TILE_E + (size_t)nb * KC_GU * TILE_E;

    int tid = threadIdx.x;
    int wid = tid >> 5, lane = tid & 31;
    int warpM = wid & 3, warpN = wid >> 2;
    uint32_t smbase = smem_u32(sm);
    uint32_t barb = smem_u32(&s_bar[0]);
    auto fullb  = [&](int s) { return barb + s * 8; };
    auto emptyb = [&](int s) { return barb + (NST_GU + s) * 8; };

    if (tid == 0)
        for (int s = 0; s < NST_GU; s++) { mbar_init(fullb(s), 1); mbar_init(emptyb(s), 16); }
    __syncthreads();

    auto issue = [&](int j) {
        int s = j % NST_GU;
        uint32_t st = smbase + s * STAGE_GU;
        mbar_expect(fullb(s), STAGE_GU);
        TMA_BULK(st,         (const char*)(Ah + ((size_t)gt * KC_GU + j) * TILE_E), TILE_B, fullb(s));
        TMA_BULK(st + 16384, (const char*)(Bg + (size_t)j * TILE_E), TILE_B, fullb(s));
        TMA_BULK(st + 32768, (const char*)(Bu + (size_t)j * TILE_E), TILE_B, fullb(s));
    };

    const int nc = KC_GU;
    if (tid == 0)
        for (int j = 0; j < NST_GU - 1; j++) issue(j);

    float accG[2][4][4], accU[2][4][4];
    #pragma unroll
    for (int a = 0; a < 2; a++)
        #pragma unroll
        for (int b = 0; b < 4; b++)
            #pragma unroll
            for (int cc = 0; cc < 4; cc++) { accG[a][b][cc] = 0.f; accU[a][b][cc] = 0.f; }

    int arow = (lane & 7) + ((lane >> 3) & 1) * 8;
    int aselB = (lane >> 4) * 16;
    int brow = (lane & 7) + (lane >> 4) * 8;
    int bselB = ((lane >> 3) & 1) * 16;

    for (int c = 0; c < nc; c++) {
        int s = c % NST_GU;
        if (tid == 0) {
            int j = c + NST_GU - 1;
            if (j < nc) {
                if (j >= NST_GU) mbar_wait(emptyb(j % NST_GU), (j / NST_GU - 1) & 1);
                issue(j);
            }
        }
        mbar_wait(fullb(s), (c / NST_GU) & 1);

        uint32_t base = smbase + s * STAGE_GU;
        #pragma unroll
        for (int k16 = 0; k16 < 4; k16++) {
            uint32_t a[2][4], b[4][2];
            #pragma unroll
            for (int mi = 0; mi < 2; mi++) {
                uint32_t off = (uint32_t)((warpM * 32 + mi * 16 + arow) * 128 + k16 * 32 + aselB);
                LDMX4(a[mi][0], a[mi][1], a[mi][2], a[mi][3], base + swz(off));
            }
            // --- G ---
            #pragma unroll
            for (int gi = 0; gi < 2; gi++) {
                uint32_t off = (uint32_t)((warpN * 32 + gi * 16 + brow) * 128 + k16 * 32 + bselB);
                uint32_t x0, x1, x2, x3;
                LDMX4(x0, x1, x2, x3, base + 16384 + swz(off));
                b[gi*2][0]=x0; b[gi*2][1]=x1; b[gi*2+1][0]=x2; b[gi*2+1][1]=x3;
            }
            #pragma unroll
            for (int mi = 0; mi < 2; mi++)
                #pragma unroll
                for (int ni = 0; ni < 4; ni++)
                    MMAH(accG[mi][ni], a[mi], b[ni][0], b[ni][1]);
            // --- U ---
            #pragma unroll
            for (int gi = 0; gi < 2; gi++) {
                uint32_t off = (uint32_t)((warpN * 32 + gi * 16 + brow) * 128 + k16 * 32 + bselB);
                uint32_t x0, x1, x2, x3;
                LDMX4(x0, x1, x2, x3, base + 32768 + swz(off));
                b[gi*2][0]=x0; b[gi*2][1]=x1; b[gi*2+1][0]=x2; b[gi*2+1][1]=x3;
            }
            #pragma unroll
            for (int mi = 0; mi < 2; mi++)
                #pragma unroll
                for (int ni = 0; ni < 4; ni++)
                    MMAH(accU[mi][ni], a[mi], b[ni][0], b[ni][1]);
        }
        __syncwarp();
        if (lane == 0) mbar_arrive(emptyb(s));
    }

    // epilogue: act = silu(G)*U -> tiled swizzled fp16 for down GEMM
    __half* Dh = sh ? g_sacth : g_acth;
    int g = lane >> 2, tg = lane & 3;
    #pragma unroll
    for (int mi = 0; mi < 2; mi++) {
        #pragma unroll
        for (int ni = 0; ni < 4; ni++) {
            int cl = warpN * 32 + ni * 8 + tg * 2;
            int gcol = nb * 128 + cl;
            int kcd = gcol >> 6, cc = gcol & 63;
            char* th = (char*)(Dh + ((size_t)gt * KC_DN + kcd) * TILE_E);
            #pragma unroll
            for (int half8 = 0; half8 < 2; half8++) {
                int rl = warpM * 32 + mi * 16 + g + half8 * 8;
                if (mbase + rl >= cnt) continue;
                float a0 = silu_fast(accG[mi][ni][half8*2])   * accU[mi][ni][half8*2];
                float a1 = silu_fast(accG[mi][ni][half8*2+1]) * accU[mi][ni][half8*2+1];
                uint32_t hv = packh(__float2half_rn(a0), __float2half_rn(a1));
                uint32_t b = swz((uint32_t)(rl * 128 + cc * 2));
                *(uint32_t*)(th + b) = hv;
            }
        }
    }
}

// ---------------- down GEMM (pure fp16) with fused weighted combine ---------
// z = 0..NE (z==NE shared, weight 1); all epilogues atomicAdd into zeroed y
__global__ void __launch_bounds__(512)
mma_down(float* __restrict__ Y, int T)
{
    extern __shared__ char sm[];
    __shared__ __align__(8) unsigned long long s_bar[2 * NST_DN];
    __shared__ int   s_tok[128];
    __shared__ float s_w[128];

    int e = blockIdx.z;
    bool sh = (e == NE);
    int r0, cnt;
    if (sh) { r0 = 0; cnt = T; }
    else { r0 = g_offsets[e]; cnt = g_counts[e]; }
    int mbase = blockIdx.y * 128;
    if (mbase >= cnt) return;
    int nb = blockIdx.x;
    int gt = (r0 + mbase) >> 7;

    const __half* Ahp = sh ? g_sacth : g_acth;
    const __half* Bd = (sh ? g_psd : g_pwd)
        + (size_t)(sh ? 0 : e) * TN_DN * KC_DN * TILE_E + (size_t)nb * KC_DN * TILE_E;

    int tid = threadIdx.x;
    int wid = tid >> 5, lane = tid & 31;
    int warpM = wid & 3, warpN = wid >> 2;
    uint32_t smbase = smem_u32(sm);
    uint32_t barb = smem_u32(&s_bar[0]);
    auto fullb  = [&](int s) { return barb + s * 8; };
    auto emptyb = [&](int s) { return barb + (NST_DN + s) * 8; };

    if (tid == 0)
        for (int s = 0; s < NST_DN; s++) { mbar_init(fullb(s), 1); mbar_init(emptyb(s), 16); }
    if (tid < 128) {
        int rr = mbase + tid;
        if (sh) { s_tok[tid] = rr; s_w[tid] = 1.f; }
        else {
            int slot = (rr < cnt) ? g_rowmap[r0 + rr] : 0;
            s_tok[tid] = slot >> 2;
            s_w[tid] = g_tw[slot];
        }
    }
    __syncthreads();

    auto issue = [&](int j) {
        int s = j % NST_DN;
        uint32_t st = smbase + s * STAGE_DN;
        mbar_expect(fullb(s), STAGE_DN);
        TMA_BULK(st,         (const char*)(Ahp + ((size_t)gt * KC_DN + j) * TILE_E), TILE_B, fullb(s));
        TMA_BULK(st + 16384, (const char*)(Bd + (size_t)j * TILE_E), TILE_B, fullb(s));
    };

    const int nc = KC_DN;
    if (tid == 0)
        for (int j = 0; j < NST_DN - 1 && j < nc; j++) issue(j);

    float acc[2][4][4];
    #pragma unroll
    for (int a = 0; a < 2; a++)
        #pragma unroll
        for (int b = 0; b < 4; b++)
            #pragma unroll
            for (int cc = 0; cc < 4; cc++) acc[a][b][cc] = 0.f;

    int arow = (lane & 7) + ((lane >> 3) & 1) * 8;
    int aselB = (lane >> 4) * 16;
    int brow = (lane & 7) + (lane >> 4) * 8;
    int bselB = ((lane >> 3) & 1) * 16;

    for (int c = 0; c < nc; c++) {
        int s = c % NST_DN;
        if (tid == 0) {
            int j = c + NST_DN - 1;
            if (j < nc) {
                if (j >= NST_DN) mbar_wait(emptyb(j % NST_DN), (j / NST_DN - 1) & 1);
                issue(j);
            }
        }
        mbar_wait(fullb(s), (c / NST_DN) & 1);

        uint32_t base = smbase + s * STAGE_DN;
        #pragma unroll
        for (int k16 = 0; k16 < 4; k16++) {
            uint32_t a[2][4], b[4][2];
            #pragma unroll
            for (int mi = 0; mi < 2; mi++) {
                uint32_t off = (uint32_t)((warpM * 32 + mi * 16 + arow) * 128 + k16 * 32 + aselB);
                LDMX4(a[mi][0], a[mi][1], a[mi][2], a[mi][3], base + swz(off));
            }
            #pragma unroll
            for (int gi = 0; gi < 2; gi++) {
                uint32_t off = (uint32_t)((warpN * 32 + gi * 16 + brow) * 128 + k16 * 32 + bselB);
                uint32_t x0, x1, x2, x3;
                LDMX4(x0, x1, x2, x3, base + 16384 + swz(off));
                b[gi*2][0]=x0; b[gi*2][1]=x1; b[gi*2+1][0]=x2; b[gi*2+1][1]=x3;
            }
            #pragma unroll
            for (int mi = 0; mi < 2; mi++)
                #pragma unroll
                for (int ni = 0; ni < 4; ni++)
                    MMAH(acc[mi][ni], a[mi], b[ni][0], b[ni][1]);
        }
        __syncwarp();
        if (lane == 0) mbar_arrive(emptyb(s));
    }

    int g = lane >> 2, tg = lane & 3;
    #pragma unroll
    for (int mi = 0; mi < 2; mi++) {
        #pragma unroll
        for (int half8 = 0; half8 < 2; half8++) {
            int rl = warpM * 32 + mi * 16 + g + half8 * 8;
            if (mbase + rl >= cnt) continue;
            int tok = s_tok[rl];
            float w = s_w[rl];
            float* dst = Y + (size_t)tok * H + nb * 128 + warpN * 32;
            #pragma unroll
            for (int ni = 0; ni < 4; ni++) {
                int col = ni * 8 + tg * 2;
                atomicAdd(dst + col,     acc[mi][ni][half8*2]     * w);
                atomicAdd(dst + col + 1, acc[mi][ni][half8*2 + 1] * w);
            }
        }
    }
}

__global__ void fill_zero(float* p, long long n) {
    long long i = (long long)blockIdx.x * 256 + threadIdx.x;
    if (i < n) p[i] = 0.f;
}

// ---------------- launch -----------------------------------------------------
extern "C" void kernel_launch(void* const* d_in, const int* in_sizes, int n_in,
                              void* d_out, int out_size)
{
    const float* x   = (const float*)d_in[0];
    const float* gw  = (const float*)d_in[1];
    const float* eb  = (const float*)d_in[2];
    const float* wg  = (const float*)d_in[3];
    const float* wu  = (const float*)d_in[4];
    const float* wd  = (const float*)d_in[5];
    const float* wsg = (const float*)d_in[6];
    const float* wsu = (const float*)d_in[7];
    const float* wsd = (const float*)d_in[8];
    float* out = (float*)d_out;

    int T = in_sizes[0] / H;
    int N = T * TK;
    int MT = (T + 127) / 128;

    long long oL = (long long)T * H;
    long long oK = oL + (long long)T * NE;
    long long oEnd = oK + (long long)T * TK;

    float* outLogits = ((long long)out_size >= oK)   ? (out + oL) : nullptr;
    float* outTopkF  = ((long long)out_size >= oEnd) ? (out + oK) : nullptr;
    long long written = ((long long)out_size >= oEnd) ? oEnd
                       : ((long long)out_size >= oK) ? oK
                       : oL;

    cudaFuncSetAttribute(mma_gateup, cudaFuncAttributeMaxDynamicSharedMemorySize, SMEM_GU);
    cudaFuncSetAttribute(mma_down,   cudaFuncAttributeMaxDynamicSharedMemorySize, SMEM_DN);

    // zero y (both down variants atomically accumulate into it)
    fill_zero<<<(unsigned)((oL + 255) / 256), 256>>>(out, oL);
    init_kernel<<<80, 256>>>();
    gate_kernel<<<T / GTOK, 256>>>(x, gw, eb, outLogits, outTopkF);
    scan_kernel<<<1, 1>>>();
    scatter_kernel<<<(N + 255) / 256, 256>>>(N);
    gather_sx<<<dim3(KC_GU, NT_SH), 256>>>(x);
    gather_rx<<<dim3(KC_GU, NT_X), 256>>>();

    prep_gu<<<dim3(KC_GU, TN_GU, 2 * NE + 2), 256>>>(wg, wu, wsg, wsu);
    prep_dn<<<dim3(KC_DN, TN_DN, NE + 1), 256>>>(wd, wsd);

    // merged GEMMs (shared expert = z==NE) for full-wave packing
    mma_gateup<<<dim3(TN_GU, MT, NE + 1), 512, SMEM_GU>>>(T);
    mma_down  <<<dim3(TN_DN, MT, NE + 1), 512, SMEM_DN>>>(out, T);

    if ((long long)out_size > written) {
        long long rest = (long long)out_size - written;
        fill_zero<<<(unsigned)((rest + 255) / 256), 256>>>(out + written, rest);
    }
}

// round 13
// speedup vs baseline: 1.7856x; 1.0342x over previous
#include <cuda_runtime.h>
#include <cuda_fp16.h>
#include <math.h>
#include <stdint.h>

#define H   1024
#define ID  512
#define NE  32
#define TK  4
#define MAXT 4096
#define MAXN (MAXT*TK)
#define RSCALE 2.5f
#define GTOK 8

#define TILE_E   8192          // elems per 128x64 fp16 tile
#define TILE_B   16384         // bytes per tile
#define NT_X     160           // row-tiles for padded sorted rows (20480/128)
#define NT_SH    32            // T/128
#define KC_GU    16            // H/64
#define KC_DN    8             // ID/64
#define TN_GU    4             // ID/128
#define TN_DN    8             // H/128

#define NST_GU   4
#define NST_DN   6
#define STAGE_GU 49152         // A, Bg, Bu
#define STAGE_DN 32768         // A, B
#define SMEM_GU  (NST_GU*STAGE_GU)   // 196608
#define SMEM_DN  (NST_DN*STAGE_DN)   // 196608

// ---------------- scratch (device globals; referenced ONLY in device code) --
__device__ float g_tw[MAXT * TK];
__device__ int   g_topk[MAXT * TK];
__device__ int   g_counts[NE];
__device__ int   g_offsets[NE + 1];
__device__ int   g_cursor[NE];
__device__ int   g_rowmap[NT_X * 128];

// tiled fp16 planes: [tile][kc][8192] swizzled
__device__ __align__(16) __half g_xsh[(size_t)NT_X * KC_GU * TILE_E];
__device__ __align__(16) __half g_sxh[(size_t)NT_SH * KC_GU * TILE_E];
__device__ __align__(16) __half g_acth[(size_t)NT_X * KC_DN * TILE_E];
__device__ __align__(16) __half g_sacth[(size_t)NT_SH * KC_DN * TILE_E];

// tiled weights [e][nt][kc][8192]
__device__ __align__(16) __half g_pwg[(size_t)NE * TN_GU * KC_GU * TILE_E];
__device__ __align__(16) __half g_pwu[(size_t)NE * TN_GU * KC_GU * TILE_E];
__device__ __align__(16) __half g_pwd[(size_t)NE * TN_DN * KC_DN * TILE_E];
__device__ __align__(16) __half g_psg[(size_t)TN_GU * KC_GU * TILE_E];
__device__ __align__(16) __half g_psu[(size_t)TN_GU * KC_GU * TILE_E];
__device__ __align__(16) __half g_psd[(size_t)TN_DN * KC_DN * TILE_E];

// ---------------- helpers ----------------------------------------------
__device__ __forceinline__ uint32_t smem_u32(const void* p) {
    return (uint32_t)__cvta_generic_to_shared(p);
}
__device__ __forceinline__ uint32_t swz(uint32_t b) { return b ^ ((b >> 3) & 0x70); }
__device__ __forceinline__ uint32_t packh(__half a, __half b) {
    return (uint32_t)(*(uint16_t*)&a) | ((uint32_t)(*(uint16_t*)&b) << 16);
}
__device__ __forceinline__ float silu_fast(float g) { return g / (1.f + __expf(-g)); }

__device__ __forceinline__ void mbar_init(uint32_t a, uint32_t cnt) {
    asm volatile("mbarrier.init.shared.b64 [%0], %1;" :: "r"(a), "r"(cnt) : "memory");
}
__device__ __forceinline__ void mbar_arrive(uint32_t a) {
    asm volatile("mbarrier.arrive.shared.b64 _, [%0];" :: "r"(a) : "memory");
}
__device__ __forceinline__ void mbar_expect(uint32_t a, uint32_t bytes) {
    asm volatile("mbarrier.arrive.expect_tx.shared.b64 _, [%0], %1;"
                 :: "r"(a), "r"(bytes) : "memory");
}
__device__ __forceinline__ void mbar_wait(uint32_t a, uint32_t ph) {
    asm volatile(
        "{\n\t.reg .pred P;\n\t"
        "W_%=:\n\t"
        "mbarrier.try_wait.parity.acquire.cta.shared::cta.b64 P, [%0], %1, 0x989680;\n\t"
        "@P bra D_%=;\n\t"
        "bra W_%=;\n\t"
        "D_%=:\n\t}"
        :: "r"(a), "r"(ph) : "memory");
}
#define TMA_BULK(dst, src, bytes, mbar) \
    asm volatile("cp.async.bulk.shared::cta.global.mbarrier::complete_tx::bytes " \
                 "[%0], [%1], %2, [%3];" \
                 :: "r"(dst), "l"(src), "r"(bytes), "r"(mbar) : "memory")

#define LDMX4(r0_,r1_,r2_,r3_,addr) \
    asm volatile("ldmatrix.sync.aligned.m8n8.x4.shared.b16 {%0,%1,%2,%3}, [%4];" \
        : "=r"(r0_), "=r"(r1_), "=r"(r2_), "=r"(r3_) : "r"(addr))

#define MMAH(c_, a_, b0_, b1_) \
    asm volatile("mma.sync.aligned.m16n8k16.row.col.f32.f16.f16.f32 " \
        "{%0,%1,%2,%3}, {%4,%5,%6,%7}, {%8,%9}, {%0,%1,%2,%3};" \
        : "+f"((c_)[0]), "+f"((c_)[1]), "+f"((c_)[2]), "+f"((c_)[3]) \
        : "r"((a_)[0]), "r"((a_)[1]), "r"((a_)[2]), "r"((a_)[3]), \
          "r"(b0_), "r"(b1_))

// ---------------- zero y + init counters -----------------------------------
__global__ void zero_init(float* __restrict__ y, long long n4) {
    long long i = (long long)blockIdx.x * 256 + threadIdx.x;
    if (i < n4) ((float4*)y)[i] = make_float4(0.f, 0.f, 0.f, 0.f);
    if (i < NE) { g_counts[i] = 0; g_cursor[i] = 0; }
    if (i < NT_X * 128) g_rowmap[i] = 0;
}

// ---------------- gate: 8 tokens/block, weights staged 2 experts at a time --
__global__ void __launch_bounds__(256)
gate_kernel(const float* __restrict__ X, const float* __restrict__ GW,
            const float* __restrict__ EB,
            float* outLogits, float* outTopkF)
{
    __shared__ __align__(16) float xs[GTOK][H];
    __shared__ __align__(16) float wch[2][H];
    __shared__ float sl[GTOK][NE];

    int t0 = blockIdx.x * GTOK;
    int tid = threadIdx.x;
    int wid = tid >> 5, lane = tid & 31;

    for (int i = tid; i < GTOK * (H / 4); i += 256) {
        int tok = i / (H / 4), q = i % (H / 4);
        ((float4*)xs[tok])[q] = ((const float4*)(X + (size_t)(t0 + tok) * H))[q];
    }
    __syncthreads();

    for (int ch = 0; ch < NE / 2; ch++) {
        for (int i = tid; i < 2 * (H / 4); i += 256) {
            int e = i / (H / 4), q = i % (H / 4);
            ((float4*)wch[e])[q] = ((const float4*)(GW + (size_t)(ch * 2 + e) * H))[q];
        }
        __syncthreads();
        #pragma unroll
        for (int p = wid; p < 16; p += 8) {
            int tok = p >> 1, e = p & 1;
            float s = 0.f;
            #pragma unroll
            for (int i = 0; i < 8; i++) {
                float4 xv = ((const float4*)xs[tok])[lane + i * 32];
                float4 wv = ((const float4*)wch[e])[lane + i * 32];
                s += xv.x * wv.x + xv.y * wv.y + xv.z * wv.z + xv.w * wv.w;
            }
            s += __shfl_down_sync(0xffffffffu, s, 16);
            s += __shfl_down_sync(0xffffffffu, s, 8);
            s += __shfl_down_sync(0xffffffffu, s, 4);
            s += __shfl_down_sync(0xffffffffu, s, 2);
            s += __shfl_down_sync(0xffffffffu, s, 1);
            if (lane == 0) {
                sl[tok][ch * 2 + e] = s;
                if (outLogits) outLogits[(size_t)(t0 + tok) * NE + ch * 2 + e] = s;
            }
        }
        __syncthreads();
    }

    if (tid < GTOK) {
        int t = t0 + tid;
        float ssc[NE], ssrt[NE];
        #pragma unroll
        for (int i = 0; i < NE; i++) {
            float v = sl[tid][i];
            float sc = 1.f / (1.f + expf(-v));
            ssc[i] = sc;
            ssrt[i] = sc + EB[i];
        }
        float gs[4];
        #pragma unroll
        for (int g = 0; g < 4; g++) {
            float m1 = -1e30f, m2 = -1e30f;
            #pragma unroll
            for (int j = 0; j < 8; j++) {
                float v = ssrt[g * 8 + j];
                if (v > m1) { m2 = m1; m1 = v; }
                else if (v > m2) { m2 = v; }
            }
            gs[g] = m1 + m2;
        }
        int g1 = 0;
        for (int g = 1; g < 4; g++) if (gs[g] > gs[g1]) g1 = g;
        int g2 = -1;
        for (int g = 0; g < 4; g++) {
            if (g == g1) continue;
            if (g2 < 0 || gs[g] > gs[g2]) g2 = g;
        }
        bool used[NE];
        #pragma unroll
        for (int i = 0; i < NE; i++) used[i] = false;
        int idx[TK]; float wts[TK]; float sum = 0.f;
        #pragma unroll
        for (int k = 0; k < TK; k++) {
            int best = -1; float bv = -1e30f;
            for (int i = 0; i < NE; i++) {
                int grp = i >> 3;
                if (grp != g1 && grp != g2) continue;
                if (used[i]) continue;
                if (ssrt[i] > bv) { bv = ssrt[i]; best = i; }
            }
            used[best] = true;
            idx[k] = best;
            wts[k] = ssc[best];
            sum += wts[k];
        }
        float inv = RSCALE / (sum + 1e-20f);
        #pragma unroll
        for (int k = 0; k < TK; k++) {
            g_topk[t * TK + k] = idx[k];
            g_tw[t * TK + k]   = wts[k] * inv;
            if (outTopkF) outTopkF[t * TK + k] = (float)idx[k];
            atomicAdd(&g_counts[idx[k]], 1);
        }
    }
}

// warp-parallel exclusive scan of 128-padded counts
__global__ void scan_kernel() {
    int lane = threadIdx.x;
    int c = (lane < NE) ? ((g_counts[lane] + 127) & ~127) : 0;
    int s = c;
    #pragma unroll
    for (int d = 1; d < 32; d <<= 1) {
        int n = __shfl_up_sync(0xffffffffu, s, d);
        if (lane >= d) s += n;
    }
    if (lane < NE) g_offsets[lane + 1] = s;
    if (lane == 0) g_offsets[0] = 0;
}

__global__ void scatter_kernel(int N) {
    int s = blockIdx.x * 256 + threadIdx.x;
    if (s >= N) return;
    int e = g_topk[s];
    int p = g_offsets[e] + atomicAdd(&g_cursor[e], 1);
    g_rowmap[p] = s;
}

// ---------------- gather shared X: f32 -> tiled swizzled fp16 ---------------
__global__ void __launch_bounds__(256)
gather_sx(const float* __restrict__ X)
{
    int kc = blockIdx.x;
    int gt = blockIdx.y;
    int tid = threadIdx.x;
    __half* dh = g_sxh + ((size_t)gt * KC_GU + kc) * TILE_E;

    for (int i = tid; i < 128 * 16; i += 256) {
        int r = i >> 4, q = (i & 15) * 4;
        float4 v = *(const float4*)(X + (size_t)(gt * 128 + r) * H + kc * 64 + q);
        uint32_t h0 = packh(__float2half_rn(v.x), __float2half_rn(v.y));
        uint32_t h1 = packh(__float2half_rn(v.z), __float2half_rn(v.w));
        uint32_t b = swz((uint32_t)(r * 128 + q * 2));
        *(uint2*)((char*)dh + b) = make_uint2(h0, h1);
    }
}

// ---------------- gather routed X from fp16 tiles (pure swizzled row copy) --
__global__ void __launch_bounds__(256)
gather_rx()
{
    int kc = blockIdx.x;
    int gt = blockIdx.y;
    __shared__ int stok[128];
    if (gt * 128 >= g_offsets[NE]) return;

    int tid = threadIdx.x;
    if (tid < 128) stok[tid] = g_rowmap[gt * 128 + tid] >> 2;
    __syncthreads();

    char* dh = (char*)(g_xsh + ((size_t)gt * KC_GU + kc) * TILE_E);

    for (int i = tid; i < 128 * 8; i += 256) {
        int r = i >> 3, q16 = (i & 7) * 16;
        int t = stok[r];
        const char* sh = (const char*)(g_sxh + ((size_t)(t >> 7) * KC_GU + kc) * TILE_E);
        uint4 v = *(const uint4*)(sh + swz((uint32_t)((t & 127) * 128 + q16)));
        *(uint4*)(dh + swz((uint32_t)(r * 128 + q16))) = v;
    }
}

// ---------------- weight prep (single merged launch) ------------------------
__device__ __forceinline__ void prep_core(const float* src, int N, __half* dst)
{
    __shared__ float sT[128][65];
    int tid = threadIdx.x;
    for (int i = tid; i < 64 * 32; i += 256) {
        int k = i >> 5, nf = (i & 31) * 4;
        float4 v = *(const float4*)(src + (size_t)k * N + nf);
        sT[nf + 0][k] = v.x; sT[nf + 1][k] = v.y;
        sT[nf + 2][k] = v.z; sT[nf + 3][k] = v.w;
    }
    __syncthreads();
    for (int i = tid; i < 128 * 16; i += 256) {
        int n = i >> 4, k4 = (i & 15) * 4;
        uint32_t a = packh(__float2half_rn(sT[n][k4]),     __float2half_rn(sT[n][k4 + 1]));
        uint32_t b = packh(__float2half_rn(sT[n][k4 + 2]), __float2half_rn(sT[n][k4 + 3]));
        uint32_t off = swz((uint32_t)(n * 128 + k4 * 2));
        *(uint2*)((char*)dst + off) = make_uint2(a, b);
    }
}

#define NGU_BLK ((2*NE+2)*TN_GU*KC_GU)   // 4224
#define NDN_BLK ((NE+1)*TN_DN*KC_DN)     // 2112

__global__ void __launch_bounds__(256)
prep_all(const float* __restrict__ wg, const float* __restrict__ wu,
         const float* __restrict__ wsg, const float* __restrict__ wsu,
         const float* __restrict__ wd, const float* __restrict__ wsd)
{
    int bid = blockIdx.x;
    if (bid < NGU_BLK) {
        int z = bid / (TN_GU * KC_GU);
        int rem = bid % (TN_GU * KC_GU);
        int nt = rem / KC_GU, kc = rem % KC_GU;
        const float* W; __half* base; int e;
        if (z < NE)          { W = wg;  base = g_pwg; e = z; }
        else if (z < 2 * NE) { W = wu;  base = g_pwu; e = z - NE; }
        else if (z == 2*NE)  { W = wsg; base = g_psg; e = 0; }
        else                 { W = wsu; base = g_psu; e = 0; }
        const float* src = W + ((size_t)e * H + (size_t)kc * 64) * ID + (size_t)nt * 128;
        __half* dst = base + ((size_t)(e * TN_GU + nt) * KC_GU + kc) * TILE_E;
        prep_core(src, ID, dst);
    } else {
        int b2 = bid - NGU_BLK;
        int z = b2 / (TN_DN * KC_DN);
        int rem = b2 % (TN_DN * KC_DN);
        int nt = rem / KC_DN, kc = rem % KC_DN;
        const float* W; __half* base; int e;
        if (z < NE) { W = wd;  base = g_pwd; e = z; }
        else        { W = wsd; base = g_psd; e = 0; }
        const float* src = W + ((size_t)e * ID + (size_t)kc * 64) * H + (size_t)nt * 128;
        __half* dst = base + ((size_t)(e * TN_DN + nt) * KC_DN + kc) * TILE_E;
        prep_core(src, H, dst);
    }
}

// ---------------- fused gate+up GEMM (pure fp16, bulk pipeline) -------------
// z = 0..NE; z==NE is the shared expert. Epilogue: smem staging + bulk store.
__global__ void __launch_bounds__(512)
mma_gateup(int T)
{
    extern __shared__ char sm[];
    __shared__ __align__(8) unsigned long long s_bar[2 * NST_GU];

    int e = blockIdx.z;
    bool sh = (e == NE);
    int r0, cnt;
    if (sh) { r0 = 0; cnt = T; }
    else { r0 = g_offsets[e]; cnt = g_counts[e]; }
    int mbase = blockIdx.y * 128;
    if (mbase >= cnt) return;
    int nb = blockIdx.x;
    int gt = (r0 + mbase) >> 7;

    const __half* Ah = sh ? g_sxh : g_xsh;
    const __half* Bg = (sh ? g_psg : g_pwg)
        + (size_t)(sh ? 0 : e) * TN_GU * KC_GU * TILE_E + (size_t)nb * KC_GU * TILE_E;
    const __half* Bu = (sh ? g_psu : g_pwu)
        + (size_t)(sh ? 0 : e) * TN_GU * KC_GU * TILE_E + (size_t)nb * KC_GU * TILE_E;

    int tid = threadIdx.x;
    int wid = tid >> 5, lane = tid & 31;
    int warpM = wid & 3, warpN = wid >> 2;
    uint32_t smbase = smem_u32(sm);
    uint32_t barb = smem_u32(&s_bar[0]);
    auto fullb  = [&](int s) { return barb + s * 8; };
    auto emptyb = [&](int s) { return barb + (NST_GU + s) * 8; };

    if (tid == 0)
        for (int s = 0; s < NST_GU; s++) { mbar_init(fullb(s), 1); mbar_init(emptyb(s), 16); }
    __syncthreads();

    auto issue = [&](int j) {
        int s = j % NST_GU;
        uint32_t st = smbase + s * STAGE_GU;
        mbar_expect(fullb(s), STAGE_GU);
        TMA_BULK(st,         (const char*)(Ah + ((size_t)gt * KC_GU + j) * TILE_E), TILE_B, fullb(s));
        TMA_BULK(st + 16384, (const char*)(Bg + (size_t)j * TILE_E), TILE_B, fullb(s));
        TMA_BULK(st + 32768, (const char*)(Bu + (size_t)j * TILE_E), TILE_B, fullb(s));
    };

    const int nc = KC_GU;
    if (tid == 0)
        for (int j = 0; j < NST_GU - 1; j++) issue(j);

    float accG[2][4][4], accU[2][4][4];
    #pragma unroll
    for (int a = 0; a < 2; a++)
        #pragma unroll
        for (int b = 0; b < 4; b++)
            #pragma unroll
            for (int cc = 0; cc < 4; cc++) { accG[a][b][cc] = 0.f; accU[a][b][cc] = 0.f; }

    int arow = (lane & 7) + ((lane >> 3) & 1) * 8;
    int aselB = (lane >> 4) * 16;
    int brow = (lane & 7) + (lane >> 4) * 8;
    int bselB = ((lane >> 3) & 1) * 16;

    for (int c = 0; c < nc; c++) {
        int s = c % NST_GU;
        if (tid == 0) {
            int j = c + NST_GU - 1;
            if (j < nc) {
                if (j >= NST_GU) mbar_wait(emptyb(j % NST_GU), (j / NST_GU - 1) & 1);
                issue(j);
            }
        }
        mbar_wait(fullb(s), (c / NST_GU) & 1);

        uint32_t base = smbase + s * STAGE_GU;
        #pragma unroll
        for (int k16 = 0; k16 < 4; k16++) {
            uint32_t a[2][4], b[4][2];
            #pragma unroll
            for (int mi = 0; mi < 2; mi++) {
                uint32_t off = (uint32_t)((warpM * 32 + mi * 16 + arow) * 128 + k16 * 32 + aselB);
                LDMX4(a[mi][0], a[mi][1], a[mi][2], a[mi][3], base + swz(off));
            }
            // --- G ---
            #pragma unroll
            for (int gi = 0; gi < 2; gi++) {
                uint32_t off = (uint32_t)((warpN * 32 + gi * 16 + brow) * 128 + k16 * 32 + bselB);
                uint32_t x0, x1, x2, x3;
                LDMX4(x0, x1, x2, x3, base + 16384 + swz(off));
                b[gi*2][0]=x0; b[gi*2][1]=x1; b[gi*2+1][0]=x2; b[gi*2+1][1]=x3;
            }
            #pragma unroll
            for (int mi = 0; mi < 2; mi++)
                #pragma unroll
                for (int ni = 0; ni < 4; ni++)
                    MMAH(accG[mi][ni], a[mi], b[ni][0], b[ni][1]);
            // --- U ---
            #pragma unroll
            for (int gi = 0; gi < 2; gi++) {
                uint32_t off = (uint32_t)((warpN * 32 + gi * 16 + brow) * 128 + k16 * 32 + bselB);
                uint32_t x0, x1, x2, x3;
                LDMX4(x0, x1, x2, x3, base + 32768 + swz(off));
                b[gi*2][0]=x0; b[gi*2][1]=x1; b[gi*2+1][0]=x2; b[gi*2+1][1]=x3;
            }
            #pragma unroll
            for (int mi = 0; mi < 2; mi++)
                #pragma unroll
                for (int ni = 0; ni < 4; ni++)
                    MMAH(accU[mi][ni], a[mi], b[ni][0], b[ni][1]);
        }
        __syncwarp();
        if (lane == 0) mbar_arrive(emptyb(s));
    }

    // epilogue: stage act = silu(G)*U tile in smem, then 2 bulk stores
    __syncthreads();
    int g = lane >> 2, tg = lane & 3;
    #pragma unroll
    for (int mi = 0; mi < 2; mi++) {
        #pragma unroll
        for (int ni = 0; ni < 4; ni++) {
            int cl = warpN * 32 + ni * 8 + tg * 2;
            int which = cl >> 6, cc = cl & 63;
            #pragma unroll
            for (int half8 = 0; half8 < 2; half8++) {
                int rl = warpM * 32 + mi * 16 + g + half8 * 8;
                float a0 = silu_fast(accG[mi][ni][half8*2])   * accU[mi][ni][half8*2];
                float a1 = silu_fast(accG[mi][ni][half8*2+1]) * accU[mi][ni][half8*2+1];
                uint32_t hv = packh(__float2half_rn(a0), __float2half_rn(a1));
                *(uint32_t*)(sm + which * 16384 + swz((uint32_t)(rl * 128 + cc * 2))) = hv;
            }
        }
    }
    __syncthreads();
    if (tid == 0) {
        asm volatile("fence.proxy.async.shared::cta;" ::: "memory");
        __half* Dh = sh ? g_sacth : g_acth;
        const char* d0 = (const char*)(Dh + ((size_t)gt * KC_DN + 2 * nb) * TILE_E);
        const char* d1 = (const char*)(Dh + ((size_t)gt * KC_DN + 2 * nb + 1) * TILE_E);
        asm volatile("cp.async.bulk.global.shared::cta.bulk_group [%0], [%1], %2;"
                     :: "l"(d0), "r"(smbase), "r"(16384) : "memory");
        asm volatile("cp.async.bulk.global.shared::cta.bulk_group [%0], [%1], %2;"
                     :: "l"(d1), "r"(smbase + 16384), "r"(16384) : "memory");
        asm volatile("cp.async.bulk.commit_group;");
        asm volatile("cp.async.bulk.wait_group 0;" ::: "memory");
    }
}

// ---------------- down GEMM (pure fp16) with fused weighted combine ---------
// z = 0..NE (z==NE shared, weight 1); all epilogues atomicAdd into zeroed y
__global__ void __launch_bounds__(512)
mma_down(float* __restrict__ Y, int T)
{
    extern __shared__ char sm[];
    __shared__ __align__(8) unsigned long long s_bar[2 * NST_DN];
    __shared__ int   s_tok[128];
    __shared__ float s_w[128];

    int e = blockIdx.z;
    bool sh = (e == NE);
    int r0, cnt;
    if (sh) { r0 = 0; cnt = T; }
    else { r0 = g_offsets[e]; cnt = g_counts[e]; }
    int mbase = blockIdx.y * 128;
    if (mbase >= cnt) return;
    int nb = blockIdx.x;
    int gt = (r0 + mbase) >> 7;

    const __half* Ahp = sh ? g_sacth : g_acth;
    const __half* Bd = (sh ? g_psd : g_pwd)
        + (size_t)(sh ? 0 : e) * TN_DN * KC_DN * TILE_E + (size_t)nb * KC_DN * TILE_E;

    int tid = threadIdx.x;
    int wid = tid >> 5, lane = tid & 31;
    int warpM = wid & 3, warpN = wid >> 2;
    uint32_t smbase = smem_u32(sm);
    uint32_t barb = smem_u32(&s_bar[0]);
    auto fullb  = [&](int s) { return barb + s * 8; };
    auto emptyb = [&](int s) { return barb + (NST_DN + s) * 8; };

    if (tid == 0)
        for (int s = 0; s < NST_DN; s++) { mbar_init(fullb(s), 1); mbar_init(emptyb(s), 16); }
    if (tid < 128) {
        int rr = mbase + tid;
        if (sh) { s_tok[tid] = rr; s_w[tid] = 1.f; }
        else {
            int slot = (rr < cnt) ? g_rowmap[r0 + rr] : 0;
            s_tok[tid] = slot >> 2;
            s_w[tid] = g_tw[slot];
        }
    }
    __syncthreads();

    auto issue = [&](int j) {
        int s = j % NST_DN;
        uint32_t st = smbase + s * STAGE_DN;
        mbar_expect(fullb(s), STAGE_DN);
        TMA_BULK(st,         (const char*)(Ahp + ((size_t)gt * KC_DN + j) * TILE_E), TILE_B, fullb(s));
        TMA_BULK(st + 16384, (const char*)(Bd + (size_t)j * TILE_E), TILE_B, fullb(s));
    };

    const int nc = KC_DN;
    if (tid == 0)
        for (int j = 0; j < NST_DN - 1 && j < nc; j++) issue(j);

    float acc[2][4][4];
    #pragma unroll
    for (int a = 0; a < 2; a++)
        #pragma unroll
        for (int b = 0; b < 4; b++)
            #pragma unroll
            for (int cc = 0; cc < 4; cc++) acc[a][b][cc] = 0.f;

    int arow = (lane & 7) + ((lane >> 3) & 1) * 8;
    int aselB = (lane >> 4) * 16;
    int brow = (lane & 7) + (lane >> 4) * 8;
    int bselB = ((lane >> 3) & 1) * 16;

    for (int c = 0; c < nc; c++) {
        int s = c % NST_DN;
        if (tid == 0) {
            int j = c + NST_DN - 1;
            if (j < nc) {
                if (j >= NST_DN) mbar_wait(emptyb(j % NST_DN), (j / NST_DN - 1) & 1);
                issue(j);
            }
        }
        mbar_wait(fullb(s), (c / NST_DN) & 1);

        uint32_t base = smbase + s * STAGE_DN;
        #pragma unroll
        for (int k16 = 0; k16 < 4; k16++) {
            uint32_t a[2][4], b[4][2];
            #pragma unroll
            for (int mi = 0; mi < 2; mi++) {
                uint32_t off = (uint32_t)((warpM * 32 + mi * 16 + arow) * 128 + k16 * 32 + aselB);
                LDMX4(a[mi][0], a[mi][1], a[mi][2], a[mi][3], base + swz(off));
            }
            #pragma unroll
            for (int gi = 0; gi < 2; gi++) {
                uint32_t off = (uint32_t)((warpN * 32 + gi * 16 + brow) * 128 + k16 * 32 + bselB);
                uint32_t x0, x1, x2, x3;
                LDMX4(x0, x1, x2, x3, base + 16384 + swz(off));
                b[gi*2][0]=x0; b[gi*2][1]=x1; b[gi*2+1][0]=x2; b[gi*2+1][1]=x3;
            }
            #pragma unroll
            for (int mi = 0; mi < 2; mi++)
                #pragma unroll
                for (int ni = 0; ni < 4; ni++)
                    MMAH(acc[mi][ni], a[mi], b[ni][0], b[ni][1]);
        }
        __syncwarp();
        if (lane == 0) mbar_arrive(emptyb(s));
    }

    int g = lane >> 2, tg = lane & 3;
    #pragma unroll
    for (int mi = 0; mi < 2; mi++) {
        #pragma unroll
        for (int half8 = 0; half8 < 2; half8++) {
            int rl = warpM * 32 + mi * 16 + g + half8 * 8;
            if (mbase + rl >= cnt) continue;
            int tok = s_tok[rl];
            float w = s_w[rl];
            float* dst = Y + (size_t)tok * H + nb * 128 + warpN * 32;
            #pragma unroll
            for (int ni = 0; ni < 4; ni++) {
                int col = ni * 8 + tg * 2;
                atomicAdd(dst + col,     acc[mi][ni][half8*2]     * w);
                atomicAdd(dst + col + 1, acc[mi][ni][half8*2 + 1] * w);
            }
        }
    }
}

__global__ void fill_zero(float* p, long long n) {
    long long i = (long long)blockIdx.x * 256 + threadIdx.x;
    if (i < n) p[i] = 0.f;
}

// ---------------- launch -----------------------------------------------------
extern "C" void kernel_launch(void* const* d_in, const int* in_sizes, int n_in,
                              void* d_out, int out_size)
{
    const float* x   = (const float*)d_in[0];
    const float* gw  = (const float*)d_in[1];
    const float* eb  = (const float*)d_in[2];
    const float* wg  = (const float*)d_in[3];
    const float* wu  = (const float*)d_in[4];
    const float* wd  = (const float*)d_in[5];
    const float* wsg = (const float*)d_in[6];
    const float* wsu = (const float*)d_in[7];
    const float* wsd = (const float*)d_in[8];
    float* out = (float*)d_out;

    int T = in_sizes[0] / H;
    int N = T * TK;
    int MT = (T + 127) / 128;

    long long oL = (long long)T * H;
    long long oK = oL + (long long)T * NE;
    long long oEnd = oK + (long long)T * TK;

    float* outLogits = ((long long)out_size >= oK)   ? (out + oL) : nullptr;
    float* outTopkF  = ((long long)out_size >= oEnd) ? (out + oK) : nullptr;
    long long written = ((long long)out_size >= oEnd) ? oEnd
                       : ((long long)out_size >= oK) ? oK
                       : oL;

    cudaFuncSetAttribute(mma_gateup, cudaFuncAttributeMaxDynamicSharedMemorySize, SMEM_GU);
    cudaFuncSetAttribute(mma_down,   cudaFuncAttributeMaxDynamicSharedMemorySize, SMEM_DN);

    long long n4 = oL / 4;
    zero_init<<<(unsigned)((n4 + 255) / 256), 256>>>(out, n4);
    gather_sx<<<dim3(KC_GU, NT_SH), 256>>>(x);
    prep_all<<<NGU_BLK + NDN_BLK, 256>>>(wg, wu, wsg, wsu, wd, wsd);
    gate_kernel<<<T / GTOK, 256>>>(x, gw, eb, outLogits, outTopkF);   // profiled slot
    scan_kernel<<<1, 32>>>();
    scatter_kernel<<<(N + 255) / 256, 256>>>(N);
    gather_rx<<<dim3(KC_GU, NT_X), 256>>>();

    // merged GEMMs (shared expert = z==NE) for full-wave packing
    mma_gateup<<<dim3(TN_GU, MT, NE + 1), 512, SMEM_GU>>>(T);
    mma_down  <<<dim3(TN_DN, MT, NE + 1), 512, SMEM_DN>>>(out, T);

    if ((long long)out_size > written) {
        long long rest = (long long)out_size - written;
        fill_zero<<<(unsigned)((rest + 255) / 256), 256>>>(out + written, rest);
    }
}

// round 15
// speedup vs baseline: 1.8884x; 1.0576x over previous
#include <cuda_runtime.h>
#include <cuda_fp16.h>
#include <math.h>
#include <stdint.h>

#define H   1024
#define ID  512
#define NE  32
#define TK  4
#define MAXT 4096
#define MAXN (MAXT*TK)
#define RSCALE 2.5f

#define TILE_E   8192          // elems per tile (128x64 A-major or 64x128 B-major)
#define TILE_B   16384         // bytes per tile
#define HT_B     8192          // bytes per B half-tile (64 rows x 128B)
#define NT_X     160           // row-tiles for padded sorted rows (20480/128)
#define NT_SH    32            // T/128
#define KC_GU    16            // H/64
#define KC_DN    8             // ID/64
#define TN_GU    4             // ID/128
#define TN_DN    8             // H/128

#define NST_GU   4
#define NST_DN   6
#define STAGE_GU 49152         // A, Bg, Bu
#define STAGE_DN 32768         // A, B
#define SMEM_GU  (NST_GU*STAGE_GU)   // 196608
#define SMEM_DN  (NST_DN*STAGE_DN)   // 196608

// ---------------- scratch (device globals; referenced ONLY in device code) --
__device__ float g_logits[(size_t)MAXT * NE];
__device__ float g_tw[MAXT * TK];
__device__ int   g_topk[MAXT * TK];
__device__ int   g_counts[NE];
__device__ int   g_offsets[NE + 1];
__device__ int   g_cursor[NE];
__device__ int   g_rowmap[NT_X * 128];

// tiled fp16 planes (A-side, row-major [m][k], SW128)
__device__ __align__(16) __half g_xsh[(size_t)NT_X * KC_GU * TILE_E];
__device__ __align__(16) __half g_sxh[(size_t)NT_SH * KC_GU * TILE_E];
__device__ __align__(16) __half g_acth[(size_t)NT_X * KC_DN * TILE_E];
__device__ __align__(16) __half g_sacth[(size_t)NT_SH * KC_DN * TILE_E];

// tiled weights [e][nt][kc][8192], B-major: [k 0..63][n 0..127] as 2 SW128 half-tiles
__device__ __align__(16) __half g_pwg[(size_t)NE * TN_GU * KC_GU * TILE_E];
__device__ __align__(16) __half g_pwu[(size_t)NE * TN_GU * KC_GU * TILE_E];
__device__ __align__(16) __half g_pwd[(size_t)NE * TN_DN * KC_DN * TILE_E];
__device__ __align__(16) __half g_psg[(size_t)TN_GU * KC_GU * TILE_E];
__device__ __align__(16) __half g_psu[(size_t)TN_GU * KC_GU * TILE_E];
__device__ __align__(16) __half g_psd[(size_t)TN_DN * KC_DN * TILE_E];

// ---------------- helpers ----------------------------------------------
__device__ __forceinline__ uint32_t smem_u32(const void* p) {
    return (uint32_t)__cvta_generic_to_shared(p);
}
__device__ __forceinline__ uint32_t swz(uint32_t b) { return b ^ ((b >> 3) & 0x70); }
__device__ __forceinline__ uint32_t packh(__half a, __half b) {
    return (uint32_t)(*(uint16_t*)&a) | ((uint32_t)(*(uint16_t*)&b) << 16);
}
__device__ __forceinline__ float silu_fast(float g) { return g / (1.f + __expf(-g)); }

__device__ __forceinline__ void mbar_init(uint32_t a, uint32_t cnt) {
    asm volatile("mbarrier.init.shared.b64 [%0], %1;" :: "r"(a), "r"(cnt) : "memory");
}
__device__ __forceinline__ void mbar_arrive(uint32_t a) {
    asm volatile("mbarrier.arrive.shared.b64 _, [%0];" :: "r"(a) : "memory");
}
__device__ __forceinline__ void mbar_expect(uint32_t a, uint32_t bytes) {
    asm volatile("mbarrier.arrive.expect_tx.shared.b64 _, [%0], %1;"
                 :: "r"(a), "r"(bytes) : "memory");
}
__device__ __forceinline__ void mbar_wait(uint32_t a, uint32_t ph) {
    asm volatile(
        "{\n\t.reg .pred P;\n\t"
        "W_%=:\n\t"
        "mbarrier.try_wait.parity.acquire.cta.shared::cta.b64 P, [%0], %1, 0x989680;\n\t"
        "@P bra D_%=;\n\t"
        "bra W_%=;\n\t"
        "D_%=:\n\t}"
        :: "r"(a), "r"(ph) : "memory");
}
#define TMA_BULK(dst, src, bytes, mbar) \
    asm volatile("cp.async.bulk.shared::cta.global.mbarrier::complete_tx::bytes " \
                 "[%0], [%1], %2, [%3];" \
                 :: "r"(dst), "l"(src), "r"(bytes), "r"(mbar) : "memory")

#define LDMX4(r0_,r1_,r2_,r3_,addr) \
    asm volatile("ldmatrix.sync.aligned.m8n8.x4.shared.b16 {%0,%1,%2,%3}, [%4];" \
        : "=r"(r0_), "=r"(r1_), "=r"(r2_), "=r"(r3_) : "r"(addr))

#define LDMX4T(r0_,r1_,r2_,r3_,addr) \
    asm volatile("ldmatrix.sync.aligned.m8n8.x4.trans.shared.b16 {%0,%1,%2,%3}, [%4];" \
        : "=r"(r0_), "=r"(r1_), "=r"(r2_), "=r"(r3_) : "r"(addr))

#define MMAH(c_, a_, b0_, b1_) \
    asm volatile("mma.sync.aligned.m16n8k16.row.col.f32.f16.f16.f32 " \
        "{%0,%1,%2,%3}, {%4,%5,%6,%7}, {%8,%9}, {%0,%1,%2,%3};" \
        : "+f"((c_)[0]), "+f"((c_)[1]), "+f"((c_)[2]), "+f"((c_)[3]) \
        : "r"((a_)[0]), "r"((a_)[1]), "r"((a_)[2]), "r"((a_)[3]), \
          "r"(b0_), "r"(b1_))

// ---------------- zero y + init counters -----------------------------------
__global__ void zero_init(float* __restrict__ y, long long n4) {
    long long i = (long long)blockIdx.x * 256 + threadIdx.x;
    if (i < n4) ((float4*)y)[i] = make_float4(0.f, 0.f, 0.f, 0.f);
    if (i < NE) { g_counts[i] = 0; g_cursor[i] = 0; }
    if (i < NT_X * 128) g_rowmap[i] = 0;
}

// ---------------- gate GEMV: warp per token, x in registers -----------------
__global__ void __launch_bounds__(1024)
gate_kernel(const float* __restrict__ X, const float* __restrict__ GW,
            float* outLogits)
{
    int warp = threadIdx.x >> 5, lane = threadIdx.x & 31;
    int t = blockIdx.x * 32 + warp;
    const float4* xp = (const float4*)(X + (size_t)t * H);
    float4 xv[8];
    #pragma unroll
    for (int j = 0; j < 8; j++) xv[j] = xp[j * 32 + lane];

    for (int e = 0; e < NE; e++) {
        const float4* wp = (const float4*)(GW + (size_t)e * H);
        float s = 0.f;
        #pragma unroll
        for (int j = 0; j < 8; j++) {
            float4 wv = wp[j * 32 + lane];
            s += xv[j].x * wv.x + xv[j].y * wv.y + xv[j].z * wv.z + xv[j].w * wv.w;
        }
        s += __shfl_down_sync(0xffffffffu, s, 16);
        s += __shfl_down_sync(0xffffffffu, s, 8);
        s += __shfl_down_sync(0xffffffffu, s, 4);
        s += __shfl_down_sync(0xffffffffu, s, 2);
        s += __shfl_down_sync(0xffffffffu, s, 1);
        if (lane == 0) {
            g_logits[(size_t)t * NE + e] = s;
            if (outLogits) outLogits[(size_t)t * NE + e] = s;
        }
    }
}

// ---------------- top-k routing (thread per token) ---------------------------
__global__ void __launch_bounds__(256)
topk_kernel(const float* __restrict__ EB, float* outTopkF, int T)
{
    int t = blockIdx.x * 256 + threadIdx.x;
    if (t >= T) return;
    float ssc[NE], ssrt[NE];
    #pragma unroll
    for (int i = 0; i < NE; i++) {
        float v = g_logits[(size_t)t * NE + i];
        float sc = 1.f / (1.f + expf(-v));
        ssc[i] = sc;
        ssrt[i] = sc + EB[i];
    }
    float gs[4];
    #pragma unroll
    for (int g = 0; g < 4; g++) {
        float m1 = -1e30f, m2 = -1e30f;
        #pragma unroll
        for (int j = 0; j < 8; j++) {
            float v = ssrt[g * 8 + j];
            if (v > m1) { m2 = m1; m1 = v; }
            else if (v > m2) { m2 = v; }
        }
        gs[g] = m1 + m2;
    }
    int g1 = 0;
    for (int g = 1; g < 4; g++) if (gs[g] > gs[g1]) g1 = g;
    int g2 = -1;
    for (int g = 0; g < 4; g++) {
        if (g == g1) continue;
        if (g2 < 0 || gs[g] > gs[g2]) g2 = g;
    }
    bool used[NE];
    #pragma unroll
    for (int i = 0; i < NE; i++) used[i] = false;
    int idx[TK]; float wts[TK]; float sum = 0.f;
    #pragma unroll
    for (int k = 0; k < TK; k++) {
        int best = -1; float bv = -1e30f;
        for (int i = 0; i < NE; i++) {
            int grp = i >> 3;
            if (grp != g1 && grp != g2) continue;
            if (used[i]) continue;
            if (ssrt[i] > bv) { bv = ssrt[i]; best = i; }
        }
        used[best] = true;
        idx[k] = best;
        wts[k] = ssc[best];
        sum += wts[k];
    }
    float inv = RSCALE / (sum + 1e-20f);
    #pragma unroll
    for (int k = 0; k < TK; k++) {
        g_topk[t * TK + k] = idx[k];
        g_tw[t * TK + k]   = wts[k] * inv;
        if (outTopkF) outTopkF[t * TK + k] = (float)idx[k];
        atomicAdd(&g_counts[idx[k]], 1);
    }
}

// warp-parallel exclusive scan of 128-padded counts
__global__ void scan_kernel() {
    int lane = threadIdx.x;
    int c = (lane < NE) ? ((g_counts[lane] + 127) & ~127) : 0;
    int s = c;
    #pragma unroll
    for (int d = 1; d < 32; d <<= 1) {
        int n = __shfl_up_sync(0xffffffffu, s, d);
        if (lane >= d) s += n;
    }
    if (lane < NE) g_offsets[lane + 1] = s;
    if (lane == 0) g_offsets[0] = 0;
}

__global__ void scatter_kernel(int N) {
    int s = blockIdx.x * 256 + threadIdx.x;
    if (s >= N) return;
    int e = g_topk[s];
    int p = g_offsets[e] + atomicAdd(&g_cursor[e], 1);
    g_rowmap[p] = s;
}

// ---------------- gather shared X: f32 -> tiled swizzled fp16 (A-major) -----
__global__ void __launch_bounds__(256)
gather_sx(const float* __restrict__ X)
{
    int kc = blockIdx.x;
    int gt = blockIdx.y;
    int tid = threadIdx.x;
    __half* dh = g_sxh + ((size_t)gt * KC_GU + kc) * TILE_E;

    for (int i = tid; i < 128 * 16; i += 256) {
        int r = i >> 4, q = (i & 15) * 4;
        float4 v = *(const float4*)(X + (size_t)(gt * 128 + r) * H + kc * 64 + q);
        uint32_t h0 = packh(__float2half_rn(v.x), __float2half_rn(v.y));
        uint32_t h1 = packh(__float2half_rn(v.z), __float2half_rn(v.w));
        uint32_t b = swz((uint32_t)(r * 128 + q * 2));
        *(uint2*)((char*)dh + b) = make_uint2(h0, h1);
    }
}

// ---------------- gather routed X from fp16 tiles (pure swizzled row copy) --
__global__ void __launch_bounds__(256)
gather_rx()
{
    int kc = blockIdx.x;
    int gt = blockIdx.y;
    __shared__ int stok[128];
    if (gt * 128 >= g_offsets[NE]) return;

    int tid = threadIdx.x;
    if (tid < 128) stok[tid] = g_rowmap[gt * 128 + tid] >> 2;
    __syncthreads();

    char* dh = (char*)(g_xsh + ((size_t)gt * KC_GU + kc) * TILE_E);

    for (int i = tid; i < 128 * 8; i += 256) {
        int r = i >> 3, q16 = (i & 7) * 16;
        int t = stok[r];
        const char* sh = (const char*)(g_sxh + ((size_t)(t >> 7) * KC_GU + kc) * TILE_E);
        uint4 v = *(const uint4*)(sh + swz((uint32_t)((t & 127) * 128 + q16)));
        *(uint4*)(dh + swz((uint32_t)(r * 128 + q16))) = v;
    }
}

// ---------------- weight prep: pure streaming convert (B-major tiles) -------
// tile = 64 k-rows x 128 n-cols, stored as 2 half-tiles of 8192B (n<64, n>=64),
// each half: SW128 rows of 128B (64 n fp16 per k-row)
__device__ __forceinline__ void prep_core(const float* src, int N, __half* dst)
{
    int tid = threadIdx.x;
    #pragma unroll
    for (int i = tid; i < 2048; i += 256) {
        int k = i >> 5, n4 = (i & 31) * 4;
        float4 v = *(const float4*)(src + (size_t)k * N + n4);
        uint32_t h0 = packh(__float2half_rn(v.x), __float2half_rn(v.y));
        uint32_t h1 = packh(__float2half_rn(v.z), __float2half_rn(v.w));
        uint32_t off = (uint32_t)((n4 >> 6) * HT_B)
                     + swz((uint32_t)(k * 128 + (n4 & 63) * 2));
        *(uint2*)((char*)dst + off) = make_uint2(h0, h1);
    }
}

#define NGU_BLK ((2*NE+2)*TN_GU*KC_GU)   // 4224
#define NDN_BLK ((NE+1)*TN_DN*KC_DN)     // 2112

__global__ void __launch_bounds__(256)
prep_all(const float* __restrict__ wg, const float* __restrict__ wu,
         const float* __restrict__ wsg, const float* __restrict__ wsu,
         const float* __restrict__ wd, const float* __restrict__ wsd)
{
    int bid = blockIdx.x;
    if (bid < NGU_BLK) {
        int z = bid / (TN_GU * KC_GU);
        int rem = bid % (TN_GU * KC_GU);
        int nt = rem / KC_GU, kc = rem % KC_GU;
        const float* W; __half* base; int e;
        if (z < NE)          { W = wg;  base = g_pwg; e = z; }
        else if (z < 2 * NE) { W = wu;  base = g_pwu; e = z - NE; }
        else if (z == 2*NE)  { W = wsg; base = g_psg; e = 0; }
        else                 { W = wsu; base = g_psu; e = 0; }
        const float* src = W + ((size_t)e * H + (size_t)kc * 64) * ID + (size_t)nt * 128;
        __half* dst = base + ((size_t)(e * TN_GU + nt) * KC_GU + kc) * TILE_E;
        prep_core(src, ID, dst);
    } else {
        int b2 = bid - NGU_BLK;
        int z = b2 / (TN_DN * KC_DN);
        int rem = b2 % (TN_DN * KC_DN);
        int nt = rem / KC_DN, kc = rem % KC_DN;
        const float* W; __half* base; int e;
        if (z < NE) { W = wd;  base = g_pwd; e = z; }
        else        { W = wsd; base = g_psd; e = 0; }
        const float* src = W + ((size_t)e * ID + (size_t)kc * 64) * H + (size_t)nt * 128;
        __half* dst = base + ((size_t)(e * TN_DN + nt) * KC_DN + kc) * TILE_E;
        prep_core(src, H, dst);
    }
}

// ---------------- fused gate+up GEMM (pure fp16, bulk pipeline, trans-B) ----
__global__ void __launch_bounds__(512)
mma_gateup(int T)
{
    extern __shared__ char sm[];
    __shared__ __align__(8) unsigned long long s_bar[2 * NST_GU];

    int e = blockIdx.z;
    bool sh = (e == NE);
    int r0, cnt;
    if (sh) { r0 = 0; cnt = T; }
    else { r0 = g_offsets[e]; cnt = g_counts[e]; }
    int mbase = blockIdx.y * 128;
    if (mbase >= cnt) return;
    int nb = blockIdx.x;
    int gt = (r0 + mbase) >> 7;

    const __half* Ah = sh ? g_sxh : g_xsh;
    const __half* Bg = (sh ? g_psg : g_pwg)
        + (size_t)(sh ? 0 : e) * TN_GU * KC_GU * TILE_E + (size_t)nb * KC_GU * TILE_E;
    const __half* Bu = (sh ? g_psu : g_pwu)
        + (size_t)(sh ? 0 : e) * TN_GU * KC_GU * TILE_E + (size_t)nb * KC_GU * TILE_E;

    int tid = threadIdx.x;
    int wid = tid >> 5, lane = tid & 31;
    int warpM = wid & 3, warpN = wid >> 2;
    uint32_t smbase = smem_u32(sm);
    uint32_t barb = smem_u32(&s_bar[0]);
    auto fullb  = [&](int s) { return barb + s * 8; };
    auto emptyb = [&](int s) { return barb + (NST_GU + s) * 8; };

    if (tid == 0)
        for (int s = 0; s < NST_GU; s++) { mbar_init(fullb(s), 1); mbar_init(emptyb(s), 16); }
    __syncthreads();

    auto issue = [&](int j) {
        int s = j % NST_GU;
        uint32_t st = smbase + s * STAGE_GU;
        mbar_expect(fullb(s), STAGE_GU);
        TMA_BULK(st,         (const char*)(Ah + ((size_t)gt * KC_GU + j) * TILE_E), TILE_B, fullb(s));
        TMA_BULK(st + 16384, (const char*)(Bg + (size_t)j * TILE_E), TILE_B, fullb(s));
        TMA_BULK(st + 32768, (const char*)(Bu + (size_t)j * TILE_E), TILE_B, fullb(s));
    };

    const int nc = KC_GU;
    if (tid == 0)
        for (int j = 0; j < NST_GU - 1; j++) issue(j);

    float accG[2][4][4], accU[2][4][4];
    #pragma unroll
    for (int a = 0; a < 2; a++)
        #pragma unroll
        for (int b = 0; b < 4; b++)
            #pragma unroll
            for (int cc = 0; cc < 4; cc++) { accG[a][b][cc] = 0.f; accU[a][b][cc] = 0.f; }

    int arow = (lane & 7) + ((lane >> 3) & 1) * 8;
    int aselB = (lane >> 4) * 16;
    int bkrow = (lane & 7) + ((lane >> 3) & 1) * 8;   // k row within 16
    int bn8   = (lane >> 4) * 8;                      // n sub-group

    for (int c = 0; c < nc; c++) {
        int s = c % NST_GU;
        if (tid == 0) {
            int j = c + NST_GU - 1;
            if (j < nc) {
                if (j >= NST_GU) mbar_wait(emptyb(j % NST_GU), (j / NST_GU - 1) & 1);
                issue(j);
            }
        }
        mbar_wait(fullb(s), (c / NST_GU) & 1);

        uint32_t base = smbase + s * STAGE_GU;
        #pragma unroll
        for (int k16 = 0; k16 < 4; k16++) {
            uint32_t a[2][4], b[4][2];
            #pragma unroll
            for (int mi = 0; mi < 2; mi++) {
                uint32_t off = (uint32_t)((warpM * 32 + mi * 16 + arow) * 128 + k16 * 32 + aselB);
                LDMX4(a[mi][0], a[mi][1], a[mi][2], a[mi][3], base + swz(off));
            }
            // --- G (trans-B: rows = k, cols = n) ---
            #pragma unroll
            for (int gi = 0; gi < 2; gi++) {
                int n = warpN * 32 + gi * 16 + bn8;
                uint32_t off = (uint32_t)((n >> 6) * HT_B)
                             + swz((uint32_t)((k16 * 16 + bkrow) * 128 + (n & 63) * 2));
                uint32_t x0, x1, x2, x3;
                LDMX4T(x0, x1, x2, x3, base + 16384 + off);
                b[gi*2][0]=x0; b[gi*2][1]=x1; b[gi*2+1][0]=x2; b[gi*2+1][1]=x3;
            }
            #pragma unroll
            for (int mi = 0; mi < 2; mi++)
                #pragma unroll
                for (int ni = 0; ni < 4; ni++)
                    MMAH(accG[mi][ni], a[mi], b[ni][0], b[ni][1]);
            // --- U ---
            #pragma unroll
            for (int gi = 0; gi < 2; gi++) {
                int n = warpN * 32 + gi * 16 + bn8;
                uint32_t off = (uint32_t)((n >> 6) * HT_B)
                             + swz((uint32_t)((k16 * 16 + bkrow) * 128 + (n & 63) * 2));
                uint32_t x0, x1, x2, x3;
                LDMX4T(x0, x1, x2, x3, base + 32768 + off);
                b[gi*2][0]=x0; b[gi*2][1]=x1; b[gi*2+1][0]=x2; b[gi*2+1][1]=x3;
            }
            #pragma unroll
            for (int mi = 0; mi < 2; mi++)
                #pragma unroll
                for (int ni = 0; ni < 4; ni++)
                    MMAH(accU[mi][ni], a[mi], b[ni][0], b[ni][1]);
        }
        __syncwarp();
        if (lane == 0) mbar_arrive(emptyb(s));
    }

    // epilogue: stage act = silu(G)*U tile in smem, then 2 bulk stores
    __syncthreads();
    int g = lane >> 2, tg = lane & 3;
    #pragma unroll
    for (int mi = 0; mi < 2; mi++) {
        #pragma unroll
        for (int ni = 0; ni < 4; ni++) {
            int cl = warpN * 32 + ni * 8 + tg * 2;
            int which = cl >> 6, cc = cl & 63;
            #pragma unroll
            for (int half8 = 0; half8 < 2; half8++) {
                int rl = warpM * 32 + mi * 16 + g + half8 * 8;
                float a0 = silu_fast(accG[mi][ni][half8*2])   * accU[mi][ni][half8*2];
                float a1 = silu_fast(accG[mi][ni][half8*2+1]) * accU[mi][ni][half8*2+1];
                uint32_t hv = packh(__float2half_rn(a0), __float2half_rn(a1));
                *(uint32_t*)(sm + which * 16384 + swz((uint32_t)(rl * 128 + cc * 2))) = hv;
            }
        }
    }
    __syncthreads();
    if (tid == 0) {
        asm volatile("fence.proxy.async.shared::cta;" ::: "memory");
        __half* Dh = sh ? g_sacth : g_acth;
        const char* d0 = (const char*)(Dh + ((size_t)gt * KC_DN + 2 * nb) * TILE_E);
        const char* d1 = (const char*)(Dh + ((size_t)gt * KC_DN + 2 * nb + 1) * TILE_E);
        asm volatile("cp.async.bulk.global.shared::cta.bulk_group [%0], [%1], %2;"
                     :: "l"(d0), "r"(smbase), "r"(16384) : "memory");
        asm volatile("cp.async.bulk.global.shared::cta.bulk_group [%0], [%1], %2;"
                     :: "l"(d1), "r"(smbase + 16384), "r"(16384) : "memory");
        asm volatile("cp.async.bulk.commit_group;");
        asm volatile("cp.async.bulk.wait_group 0;" ::: "memory");
    }
}

// ---------------- down GEMM (pure fp16, trans-B) + fused weighted combine ---
__global__ void __launch_bounds__(512)
mma_down(float* __restrict__ Y, int T)
{
    extern __shared__ char sm[];
    __shared__ __align__(8) unsigned long long s_bar[2 * NST_DN];
    __shared__ int   s_tok[128];
    __shared__ float s_w[128];

    int e = blockIdx.z;
    bool sh = (e == NE);
    int r0, cnt;
    if (sh) { r0 = 0; cnt = T; }
    else { r0 = g_offsets[e]; cnt = g_counts[e]; }
    int mbase = blockIdx.y * 128;
    if (mbase >= cnt) return;
    int nb = blockIdx.x;
    int gt = (r0 + mbase) >> 7;

    const __half* Ahp = sh ? g_sacth : g_acth;
    const __half* Bd = (sh ? g_psd : g_pwd)
        + (size_t)(sh ? 0 : e) * TN_DN * KC_DN * TILE_E + (size_t)nb * KC_DN * TILE_E;

    int tid = threadIdx.x;
    int wid = tid >> 5, lane = tid & 31;
    int warpM = wid & 3, warpN = wid >> 2;
    uint32_t smbase = smem_u32(sm);
    uint32_t barb = smem_u32(&s_bar[0]);
    auto fullb  = [&](int s) { return barb + s * 8; };
    auto emptyb = [&](int s) { return barb + (NST_DN + s) * 8; };

    if (tid == 0)
        for (int s = 0; s < NST_DN; s++) { mbar_init(fullb(s), 1); mbar_init(emptyb(s), 16); }
    if (tid < 128) {
        int rr = mbase + tid;
        if (sh) { s_tok[tid] = rr; s_w[tid] = 1.f; }
        else {
            int slot = (rr < cnt) ? g_rowmap[r0 + rr] : 0;
            s_tok[tid] = slot >> 2;
            s_w[tid] = g_tw[slot];
        }
    }
    __syncthreads();

    auto issue = [&](int j) {
        int s = j % NST_DN;
        uint32_t st = smbase + s * STAGE_DN;
        mbar_expect(fullb(s), STAGE_DN);
        TMA_BULK(st,         (const char*)(Ahp + ((size_t)gt * KC_DN + j) * TILE_E), TILE_B, fullb(s));
        TMA_BULK(st + 16384, (const char*)(Bd + (size_t)j * TILE_E), TILE_B, fullb(s));
    };

    const int nc = KC_DN;
    if (tid == 0)
        for (int j = 0; j < NST_DN - 1 && j < nc; j++) issue(j);

    float acc[2][4][4];
    #pragma unroll
    for (int a = 0; a < 2; a++)
        #pragma unroll
        for (int b = 0; b < 4; b++)
            #pragma unroll
            for (int cc = 0; cc < 4; cc++) acc[a][b][cc] = 0.f;

    int arow = (lane & 7) + ((lane >> 3) & 1) * 8;
    int aselB = (lane >> 4) * 16;
    int bkrow = (lane & 7) + ((lane >> 3) & 1) * 8;
    int bn8   = (lane >> 4) * 8;

    for (int c = 0; c < nc; c++) {
        int s = c % NST_DN;
        if (tid == 0) {
            int j = c + NST_DN - 1;
            if (j < nc) {
                if (j >= NST_DN) mbar_wait(emptyb(j % NST_DN), (j / NST_DN - 1) & 1);
                issue(j);
            }
        }
        mbar_wait(fullb(s), (c / NST_DN) & 1);

        uint32_t base = smbase + s * STAGE_DN;
        #pragma unroll
        for (int k16 = 0; k16 < 4; k16++) {
            uint32_t a[2][4], b[4][2];
            #pragma unroll
            for (int mi = 0; mi < 2; mi++) {
                uint32_t off = (uint32_t)((warpM * 32 + mi * 16 + arow) * 128 + k16 * 32 + aselB);
                LDMX4(a[mi][0], a[mi][1], a[mi][2], a[mi][3], base + swz(off));
            }
            #pragma unroll
            for (int gi = 0; gi < 2; gi++) {
                int n = warpN * 32 + gi * 16 + bn8;
                uint32_t off = (uint32_t)((n >> 6) * HT_B)
                             + swz((uint32_t)((k16 * 16 + bkrow) * 128 + (n & 63) * 2));
                uint32_t x0, x1, x2, x3;
                LDMX4T(x0, x1, x2, x3, base + 16384 + off);
                b[gi*2][0]=x0; b[gi*2][1]=x1; b[gi*2+1][0]=x2; b[gi*2+1][1]=x3;
            }
            #pragma unroll
            for (int mi = 0; mi < 2; mi++)
                #pragma unroll
                for (int ni = 0; ni < 4; ni++)
                    MMAH(acc[mi][ni], a[mi], b[ni][0], b[ni][1]);
        }
        __syncwarp();
        if (lane == 0) mbar_arrive(emptyb(s));
    }

    int g = lane >> 2, tg = lane & 3;
    #pragma unroll
    for (int mi = 0; mi < 2; mi++) {
        #pragma unroll
        for (int half8 = 0; half8 < 2; half8++) {
            int rl = warpM * 32 + mi * 16 + g + half8 * 8;
            if (mbase + rl >= cnt) continue;
            int tok = s_tok[rl];
            float w = s_w[rl];
            float* dst = Y + (size_t)tok * H + nb * 128 + warpN * 32;
            #pragma unroll
            for (int ni = 0; ni < 4; ni++) {
                int col = ni * 8 + tg * 2;
                atomicAdd(dst + col,     acc[mi][ni][half8*2]     * w);
                atomicAdd(dst + col + 1, acc[mi][ni][half8*2 + 1] * w);
            }
        }
    }
}

__global__ void fill_zero(float* p, long long n) {
    long long i = (long long)blockIdx.x * 256 + threadIdx.x;
    if (i < n) p[i] = 0.f;
}

// ---------------- launch -----------------------------------------------------
extern "C" void kernel_launch(void* const* d_in, const int* in_sizes, int n_in,
                              void* d_out, int out_size)
{
    const float* x   = (const float*)d_in[0];
    const float* gw  = (const float*)d_in[1];
    const float* eb  = (const float*)d_in[2];
    const float* wg  = (const float*)d_in[3];
    const float* wu  = (const float*)d_in[4];
    const float* wd  = (const float*)d_in[5];
    const float* wsg = (const float*)d_in[6];
    const float* wsu = (const float*)d_in[7];
    const float* wsd = (const float*)d_in[8];
    float* out = (float*)d_out;

    int T = in_sizes[0] / H;
    int N = T * TK;
    int MT = (T + 127) / 128;

    long long oL = (long long)T * H;
    long long oK = oL + (long long)T * NE;
    long long oEnd = oK + (long long)T * TK;

    float* outLogits = ((long long)out_size >= oK)   ? (out + oL) : nullptr;
    float* outTopkF  = ((long long)out_size >= oEnd) ? (out + oK) : nullptr;
    long long written = ((long long)out_size >= oEnd) ? oEnd
                       : ((long long)out_size >= oK) ? oK
                       : oL;

    cudaFuncSetAttribute(mma_gateup, cudaFuncAttributeMaxDynamicSharedMemorySize, SMEM_GU);
    cudaFuncSetAttribute(mma_down,   cudaFuncAttributeMaxDynamicSharedMemorySize, SMEM_DN);

    long long n4 = oL / 4;
    zero_init<<<(unsigned)((n4 + 255) / 256), 256>>>(out, n4);
    gather_sx<<<dim3(KC_GU, NT_SH), 256>>>(x);
    prep_all<<<NGU_BLK + NDN_BLK, 256>>>(wg, wu, wsg, wsu, wd, wsd);
    gate_kernel<<<T / 32, 1024>>>(x, gw, outLogits);        // profiled slot
    topk_kernel<<<(T + 255) / 256, 256>>>(eb, outTopkF, T);
    scan_kernel<<<1, 32>>>();
    scatter_kernel<<<(N + 255) / 256, 256>>>(N);
    gather_rx<<<dim3(KC_GU, NT_X), 256>>>();

    mma_gateup<<<dim3(TN_GU, MT, NE + 1), 512, SMEM_GU>>>(T);
    mma_down  <<<dim3(TN_DN, MT, NE + 1), 512, SMEM_DN>>>(out, T);

    if ((long long)out_size > written) {
        long long rest = (long long)out_size - written;
        fill_zero<<<(unsigned)((rest + 255) / 256), 256>>>(out + written, rest);
    }
}

// round 16
// speedup vs baseline: 1.8977x; 1.0049x over previous
#include <cuda_runtime.h>
#include <cuda_fp16.h>
#include <math.h>
#include <stdint.h>

#define H   1024
#define ID  512
#define NE  32
#define TK  4
#define MAXT 4096
#define MAXN (MAXT*TK)
#define RSCALE 2.5f

#define TILE_E   8192          // elems per tile (128x64 A-major or 64x128 B-major)
#define TILE_B   16384         // bytes per tile
#define HT_B     8192          // bytes per B half-tile (64 rows x 128B)
#define NT_X     160           // row-tiles for padded sorted rows (20480/128)
#define NT_SH    32            // T/128
#define KC_GU    16            // H/64
#define KC_DN    8             // ID/64
#define TN_GU    4             // ID/128
#define TN_DN    8             // H/128

#define NST_GU   4
#define NST_DN   6
#define STAGE_GU 49152         // A, Bg, Bu
#define STAGE_DN 32768         // A, B
#define SMEM_GU  (NST_GU*STAGE_GU)   // 196608
#define SMEM_DN  (NST_DN*STAGE_DN)   // 196608

// ---------------- scratch (device globals; referenced ONLY in device code) --
__device__ float g_logits[(size_t)MAXT * NE];
__device__ float g_tw[MAXT * TK];
__device__ int   g_topk[MAXT * TK];
__device__ int   g_counts[NE];
__device__ int   g_offsets[NE + 1];
__device__ int   g_cursor[NE];
__device__ int   g_rowmap[NT_X * 128];

// tiled fp16 planes (A-side, row-major [m][k], SW128)
__device__ __align__(16) __half g_xsh[(size_t)NT_X * KC_GU * TILE_E];
__device__ __align__(16) __half g_sxh[(size_t)NT_SH * KC_GU * TILE_E];
__device__ __align__(16) __half g_acth[(size_t)NT_X * KC_DN * TILE_E];
__device__ __align__(16) __half g_sacth[(size_t)NT_SH * KC_DN * TILE_E];

// tiled weights [e][nt][kc][8192], B-major: [k 0..63][n 0..127] as 2 SW128 half-tiles
__device__ __align__(16) __half g_pwg[(size_t)NE * TN_GU * KC_GU * TILE_E];
__device__ __align__(16) __half g_pwu[(size_t)NE * TN_GU * KC_GU * TILE_E];
__device__ __align__(16) __half g_pwd[(size_t)NE * TN_DN * KC_DN * TILE_E];
__device__ __align__(16) __half g_psg[(size_t)TN_GU * KC_GU * TILE_E];
__device__ __align__(16) __half g_psu[(size_t)TN_GU * KC_GU * TILE_E];
__device__ __align__(16) __half g_psd[(size_t)TN_DN * KC_DN * TILE_E];

// ---------------- helpers ----------------------------------------------
__device__ __forceinline__ uint32_t smem_u32(const void* p) {
    return (uint32_t)__cvta_generic_to_shared(p);
}
__device__ __forceinline__ uint32_t swz(uint32_t b) { return b ^ ((b >> 3) & 0x70); }
__device__ __forceinline__ uint32_t packh(__half a, __half b) {
    return (uint32_t)(*(uint16_t*)&a) | ((uint32_t)(*(uint16_t*)&b) << 16);
}
__device__ __forceinline__ float silu_fast(float g) { return g / (1.f + __expf(-g)); }

__device__ __forceinline__ void mbar_init(uint32_t a, uint32_t cnt) {
    asm volatile("mbarrier.init.shared.b64 [%0], %1;" :: "r"(a), "r"(cnt) : "memory");
}
__device__ __forceinline__ void mbar_arrive(uint32_t a) {
    asm volatile("mbarrier.arrive.shared.b64 _, [%0];" :: "r"(a) : "memory");
}
__device__ __forceinline__ void mbar_expect(uint32_t a, uint32_t bytes) {
    asm volatile("mbarrier.arrive.expect_tx.shared.b64 _, [%0], %1;"
                 :: "r"(a), "r"(bytes) : "memory");
}
__device__ __forceinline__ void mbar_wait(uint32_t a, uint32_t ph) {
    asm volatile(
        "{\n\t.reg .pred P;\n\t"
        "W_%=:\n\t"
        "mbarrier.try_wait.parity.acquire.cta.shared::cta.b64 P, [%0], %1, 0x989680;\n\t"
        "@P bra D_%=;\n\t"
        "bra W_%=;\n\t"
        "D_%=:\n\t}"
        :: "r"(a), "r"(ph) : "memory");
}
#define TMA_BULK(dst, src, bytes, mbar) \
    asm volatile("cp.async.bulk.shared::cta.global.mbarrier::complete_tx::bytes " \
                 "[%0], [%1], %2, [%3];" \
                 :: "r"(dst), "l"(src), "r"(bytes), "r"(mbar) : "memory")

#define LDMX4(r0_,r1_,r2_,r3_,addr) \
    asm volatile("ldmatrix.sync.aligned.m8n8.x4.shared.b16 {%0,%1,%2,%3}, [%4];" \
        : "=r"(r0_), "=r"(r1_), "=r"(r2_), "=r"(r3_) : "r"(addr))

#define LDMX4T(r0_,r1_,r2_,r3_,addr) \
    asm volatile("ldmatrix.sync.aligned.m8n8.x4.trans.shared.b16 {%0,%1,%2,%3}, [%4];" \
        : "=r"(r0_), "=r"(r1_), "=r"(r2_), "=r"(r3_) : "r"(addr))

#define MMAH(c_, a_, b0_, b1_) \
    asm volatile("mma.sync.aligned.m16n8k16.row.col.f32.f16.f16.f32 " \
        "{%0,%1,%2,%3}, {%4,%5,%6,%7}, {%8,%9}, {%0,%1,%2,%3};" \
        : "+f"((c_)[0]), "+f"((c_)[1]), "+f"((c_)[2]), "+f"((c_)[3]) \
        : "r"((a_)[0]), "r"((a_)[1]), "r"((a_)[2]), "r"((a_)[3]), \
          "r"(b0_), "r"(b1_))

// ---------------- zero y + init counters -----------------------------------
__global__ void zero_init(float* __restrict__ y, long long n4) {
    long long i = (long long)blockIdx.x * 256 + threadIdx.x;
    if (i < n4) ((float4*)y)[i] = make_float4(0.f, 0.f, 0.f, 0.f);
    if (i < NE) { g_counts[i] = 0; g_cursor[i] = 0; }
    if (i < NT_X * 128) g_rowmap[i] = 0;
}

// ---------------- gate GEMV (2 tokens/warp) + fused X->fp16 tile gather -----
__global__ void __launch_bounds__(512)
gate_kernel(const float* __restrict__ X, const float* __restrict__ GW,
            float* outLogits)
{
    int warp = threadIdx.x >> 5, lane = threadIdx.x & 31;
    int t0 = blockIdx.x * 32 + warp * 2;

    float4 xv[2][8];
    #pragma unroll
    for (int u = 0; u < 2; u++) {
        const float4* xp = (const float4*)(X + (size_t)(t0 + u) * H);
        #pragma unroll
        for (int j = 0; j < 8; j++) xv[u][j] = xp[j * 32 + lane];
    }

    // fused gather: write swizzled fp16 tiles of X (shared-expert A source)
    #pragma unroll
    for (int u = 0; u < 2; u++) {
        int t = t0 + u;
        int gt = t >> 7, row = t & 127;
        #pragma unroll
        for (int j = 0; j < 8; j++) {
            int p = j * 128 + lane * 4;
            int kc = p >> 6, q = p & 63;
            __half* dh = g_sxh + ((size_t)gt * KC_GU + kc) * TILE_E;
            uint32_t h0 = packh(__float2half_rn(xv[u][j].x), __float2half_rn(xv[u][j].y));
            uint32_t h1 = packh(__float2half_rn(xv[u][j].z), __float2half_rn(xv[u][j].w));
            *(uint2*)((char*)dh + swz((uint32_t)(row * 128 + q * 2))) = make_uint2(h0, h1);
        }
    }

    #pragma unroll 1
    for (int e = 0; e < NE; e++) {
        const float4* wp = (const float4*)(GW + (size_t)e * H);
        float s0 = 0.f, s1 = 0.f;
        #pragma unroll
        for (int j = 0; j < 8; j++) {
            float4 wv = wp[j * 32 + lane];
            s0 += xv[0][j].x * wv.x + xv[0][j].y * wv.y + xv[0][j].z * wv.z + xv[0][j].w * wv.w;
            s1 += xv[1][j].x * wv.x + xv[1][j].y * wv.y + xv[1][j].z * wv.z + xv[1][j].w * wv.w;
        }
        #pragma unroll
        for (int d = 16; d > 0; d >>= 1) {
            s0 += __shfl_down_sync(0xffffffffu, s0, d);
            s1 += __shfl_down_sync(0xffffffffu, s1, d);
        }
        if (lane == 0) {
            g_logits[(size_t)t0 * NE + e] = s0;
            g_logits[(size_t)(t0 + 1) * NE + e] = s1;
            if (outLogits) {
                outLogits[(size_t)t0 * NE + e] = s0;
                outLogits[(size_t)(t0 + 1) * NE + e] = s1;
            }
        }
    }
}

// ---------------- top-k routing (thread per token) ---------------------------
__global__ void __launch_bounds__(256)
topk_kernel(const float* __restrict__ EB, float* outTopkF, int T)
{
    int t = blockIdx.x * 256 + threadIdx.x;
    if (t >= T) return;
    float ssc[NE], ssrt[NE];
    #pragma unroll
    for (int i = 0; i < NE; i++) {
        float v = g_logits[(size_t)t * NE + i];
        float sc = 1.f / (1.f + expf(-v));
        ssc[i] = sc;
        ssrt[i] = sc + EB[i];
    }
    float gs[4];
    #pragma unroll
    for (int g = 0; g < 4; g++) {
        float m1 = -1e30f, m2 = -1e30f;
        #pragma unroll
        for (int j = 0; j < 8; j++) {
            float v = ssrt[g * 8 + j];
            if (v > m1) { m2 = m1; m1 = v; }
            else if (v > m2) { m2 = v; }
        }
        gs[g] = m1 + m2;
    }
    int g1 = 0;
    for (int g = 1; g < 4; g++) if (gs[g] > gs[g1]) g1 = g;
    int g2 = -1;
    for (int g = 0; g < 4; g++) {
        if (g == g1) continue;
        if (g2 < 0 || gs[g] > gs[g2]) g2 = g;
    }
    bool used[NE];
    #pragma unroll
    for (int i = 0; i < NE; i++) used[i] = false;
    int idx[TK]; float wts[TK]; float sum = 0.f;
    #pragma unroll
    for (int k = 0; k < TK; k++) {
        int best = -1; float bv = -1e30f;
        for (int i = 0; i < NE; i++) {
            int grp = i >> 3;
            if (grp != g1 && grp != g2) continue;
            if (used[i]) continue;
            if (ssrt[i] > bv) { bv = ssrt[i]; best = i; }
        }
        used[best] = true;
        idx[k] = best;
        wts[k] = ssc[best];
        sum += wts[k];
    }
    float inv = RSCALE / (sum + 1e-20f);
    #pragma unroll
    for (int k = 0; k < TK; k++) {
        g_topk[t * TK + k] = idx[k];
        g_tw[t * TK + k]   = wts[k] * inv;
        if (outTopkF) outTopkF[t * TK + k] = (float)idx[k];
        atomicAdd(&g_counts[idx[k]], 1);
    }
}

// warp-parallel exclusive scan of 128-padded counts
__global__ void scan_kernel() {
    int lane = threadIdx.x;
    int c = (lane < NE) ? ((g_counts[lane] + 127) & ~127) : 0;
    int s = c;
    #pragma unroll
    for (int d = 1; d < 32; d <<= 1) {
        int n = __shfl_up_sync(0xffffffffu, s, d);
        if (lane >= d) s += n;
    }
    if (lane < NE) g_offsets[lane + 1] = s;
    if (lane == 0) g_offsets[0] = 0;
}

__global__ void scatter_kernel(int N) {
    int s = blockIdx.x * 256 + threadIdx.x;
    if (s >= N) return;
    int e = g_topk[s];
    int p = g_offsets[e] + atomicAdd(&g_cursor[e], 1);
    g_rowmap[p] = s;
}

// ---------------- gather routed X from fp16 tiles (pure swizzled row copy) --
__global__ void __launch_bounds__(256)
gather_rx()
{
    int kc = blockIdx.x;
    int gt = blockIdx.y;
    __shared__ int stok[128];
    if (gt * 128 >= g_offsets[NE]) return;

    int tid = threadIdx.x;
    if (tid < 128) stok[tid] = g_rowmap[gt * 128 + tid] >> 2;
    __syncthreads();

    char* dh = (char*)(g_xsh + ((size_t)gt * KC_GU + kc) * TILE_E);

    for (int i = tid; i < 128 * 8; i += 256) {
        int r = i >> 3, q16 = (i & 7) * 16;
        int t = stok[r];
        const char* sh = (const char*)(g_sxh + ((size_t)(t >> 7) * KC_GU + kc) * TILE_E);
        uint4 v = *(const uint4*)(sh + swz((uint32_t)((t & 127) * 128 + q16)));
        *(uint4*)(dh + swz((uint32_t)(r * 128 + q16))) = v;
    }
}

// ---------------- weight prep: pure streaming convert (B-major tiles) -------
__device__ __forceinline__ void prep_core(const float* src, int N, __half* dst)
{
    int tid = threadIdx.x;
    #pragma unroll
    for (int i = tid; i < 2048; i += 256) {
        int k = i >> 5, n4 = (i & 31) * 4;
        float4 v = *(const float4*)(src + (size_t)k * N + n4);
        uint32_t h0 = packh(__float2half_rn(v.x), __float2half_rn(v.y));
        uint32_t h1 = packh(__float2half_rn(v.z), __float2half_rn(v.w));
        uint32_t off = (uint32_t)((n4 >> 6) * HT_B)
                     + swz((uint32_t)(k * 128 + (n4 & 63) * 2));
        *(uint2*)((char*)dst + off) = make_uint2(h0, h1);
    }
}

#define NGU_BLK ((2*NE+2)*TN_GU*KC_GU)   // 4224
#define NDN_BLK ((NE+1)*TN_DN*KC_DN)     // 2112

__global__ void __launch_bounds__(256)
prep_all(const float* __restrict__ wg, const float* __restrict__ wu,
         const float* __restrict__ wsg, const float* __restrict__ wsu,
         const float* __restrict__ wd, const float* __restrict__ wsd)
{
    int bid = blockIdx.x;
    if (bid < NGU_BLK) {
        int z = bid / (TN_GU * KC_GU);
        int rem = bid % (TN_GU * KC_GU);
        int nt = rem / KC_GU, kc = rem % KC_GU;
        const float* W; __half* base; int e;
        if (z < NE)          { W = wg;  base = g_pwg; e = z; }
        else if (z < 2 * NE) { W = wu;  base = g_pwu; e = z - NE; }
        else if (z == 2*NE)  { W = wsg; base = g_psg; e = 0; }
        else                 { W = wsu; base = g_psu; e = 0; }
        const float* src = W + ((size_t)e * H + (size_t)kc * 64) * ID + (size_t)nt * 128;
        __half* dst = base + ((size_t)(e * TN_GU + nt) * KC_GU + kc) * TILE_E;
        prep_core(src, ID, dst);
    } else {
        int b2 = bid - NGU_BLK;
        int z = b2 / (TN_DN * KC_DN);
        int rem = b2 % (TN_DN * KC_DN);
        int nt = rem / KC_DN, kc = rem % KC_DN;
        const float* W; __half* base; int e;
        if (z < NE) { W = wd;  base = g_pwd; e = z; }
        else        { W = wsd; base = g_psd; e = 0; }
        const float* src = W + ((size_t)e * ID + (size_t)kc * 64) * H + (size_t)nt * 128;
        __half* dst = base + ((size_t)(e * TN_DN + nt) * KC_DN + kc) * TILE_E;
        prep_core(src, H, dst);
    }
}

// ---------------- fused gate+up GEMM (pure fp16, bulk pipeline, trans-B) ----
__global__ void __launch_bounds__(512)
mma_gateup(int T)
{
    extern __shared__ char sm[];
    __shared__ __align__(8) unsigned long long s_bar[2 * NST_GU];

    int e = blockIdx.z;
    bool sh = (e == NE);
    int r0, cnt;
    if (sh) { r0 = 0; cnt = T; }
    else { r0 = g_offsets[e]; cnt = g_counts[e]; }
    int mbase = blockIdx.y * 128;
    if (mbase >= cnt) return;
    int nb = blockIdx.x;
    int gt = (r0 + mbase) >> 7;

    const __half* Ah = sh ? g_sxh : g_xsh;
    const __half* Bg = (sh ? g_psg : g_pwg)
        + (size_t)(sh ? 0 : e) * TN_GU * KC_GU * TILE_E + (size_t)nb * KC_GU * TILE_E;
    const __half* Bu = (sh ? g_psu : g_pwu)
        + (size_t)(sh ? 0 : e) * TN_GU * KC_GU * TILE_E + (size_t)nb * KC_GU * TILE_E;

    int tid = threadIdx.x;
    int wid = tid >> 5, lane = tid & 31;
    int warpM = wid & 3, warpN = wid >> 2;
    uint32_t smbase = smem_u32(sm);
    uint32_t barb = smem_u32(&s_bar[0]);
    auto fullb  = [&](int s) { return barb + s * 8; };
    auto emptyb = [&](int s) { return barb + (NST_GU + s) * 8; };

    if (tid == 0)
        for (int s = 0; s < NST_GU; s++) { mbar_init(fullb(s), 1); mbar_init(emptyb(s), 16); }
    __syncthreads();

    auto issue = [&](int j) {
        int s = j % NST_GU;
        uint32_t st = smbase + s * STAGE_GU;
        mbar_expect(fullb(s), STAGE_GU);
        TMA_BULK(st,         (const char*)(Ah + ((size_t)gt * KC_GU + j) * TILE_E), TILE_B, fullb(s));
        TMA_BULK(st + 16384, (const char*)(Bg + (size_t)j * TILE_E), TILE_B, fullb(s));
        TMA_BULK(st + 32768, (const char*)(Bu + (size_t)j * TILE_E), TILE_B, fullb(s));
    };

    const int nc = KC_GU;
    if (tid == 0)
        for (int j = 0; j < NST_GU - 1; j++) issue(j);

    float accG[2][4][4], accU[2][4][4];
    #pragma unroll
    for (int a = 0; a < 2; a++)
        #pragma unroll
        for (int b = 0; b < 4; b++)
            #pragma unroll
            for (int cc = 0; cc < 4; cc++) { accG[a][b][cc] = 0.f; accU[a][b][cc] = 0.f; }

    int arow = (lane & 7) + ((lane >> 3) & 1) * 8;
    int aselB = (lane >> 4) * 16;
    int bkrow = (lane & 7) + ((lane >> 3) & 1) * 8;
    int bn8   = (lane >> 4) * 8;

    for (int c = 0; c < nc; c++) {
        int s = c % NST_GU;
        if (tid == 0) {
            int j = c + NST_GU - 1;
            if (j < nc) {
                if (j >= NST_GU) mbar_wait(emptyb(j % NST_GU), (j / NST_GU - 1) & 1);
                issue(j);
            }
        }
        mbar_wait(fullb(s), (c / NST_GU) & 1);

        uint32_t base = smbase + s * STAGE_GU;
        #pragma unroll
        for (int k16 = 0; k16 < 4; k16++) {
            uint32_t a[2][4], b[4][2];
            #pragma unroll
            for (int mi = 0; mi < 2; mi++) {
                uint32_t off = (uint32_t)((warpM * 32 + mi * 16 + arow) * 128 + k16 * 32 + aselB);
                LDMX4(a[mi][0], a[mi][1], a[mi][2], a[mi][3], base + swz(off));
            }
            // --- G ---
            #pragma unroll
            for (int gi = 0; gi < 2; gi++) {
                int n = warpN * 32 + gi * 16 + bn8;
                uint32_t off = (uint32_t)((n >> 6) * HT_B)
                             + swz((uint32_t)((k16 * 16 + bkrow) * 128 + (n & 63) * 2));
                uint32_t x0, x1, x2, x3;
                LDMX4T(x0, x1, x2, x3, base + 16384 + off);
                b[gi*2][0]=x0; b[gi*2][1]=x1; b[gi*2+1][0]=x2; b[gi*2+1][1]=x3;
            }
            #pragma unroll
            for (int mi = 0; mi < 2; mi++)
                #pragma unroll
                for (int ni = 0; ni < 4; ni++)
                    MMAH(accG[mi][ni], a[mi], b[ni][0], b[ni][1]);
            // --- U ---
            #pragma unroll
            for (int gi = 0; gi < 2; gi++) {
                int n = warpN * 32 + gi * 16 + bn8;
                uint32_t off = (uint32_t)((n >> 6) * HT_B)
                             + swz((uint32_t)((k16 * 16 + bkrow) * 128 + (n & 63) * 2));
                uint32_t x0, x1, x2, x3;
                LDMX4T(x0, x1, x2, x3, base + 32768 + off);
                b[gi*2][0]=x0; b[gi*2][1]=x1; b[gi*2+1][0]=x2; b[gi*2+1][1]=x3;
            }
            #pragma unroll
            for (int mi = 0; mi < 2; mi++)
                #pragma unroll
                for (int ni = 0; ni < 4; ni++)
                    MMAH(accU[mi][ni], a[mi], b[ni][0], b[ni][1]);
        }
        __syncwarp();
        if (lane == 0) mbar_arrive(emptyb(s));
    }

    // epilogue: stage act = silu(G)*U tile in smem, then 2 bulk stores
    __syncthreads();
    int g = lane >> 2, tg = lane & 3;
    #pragma unroll
    for (int mi = 0; mi < 2; mi++) {
        #pragma unroll
        for (int ni = 0; ni < 4; ni++) {
            int cl = warpN * 32 + ni * 8 + tg * 2;
            int which = cl >> 6, cc = cl & 63;
            #pragma unroll
            for (int half8 = 0; half8 < 2; half8++) {
                int rl = warpM * 32 + mi * 16 + g + half8 * 8;
                float a0 = silu_fast(accG[mi][ni][half8*2])   * accU[mi][ni][half8*2];
                float a1 = silu_fast(accG[mi][ni][half8*2+1]) * accU[mi][ni][half8*2+1];
                uint32_t hv = packh(__float2half_rn(a0), __float2half_rn(a1));
                *(uint32_t*)(sm + which * 16384 + swz((uint32_t)(rl * 128 + cc * 2))) = hv;
            }
        }
    }
    __syncthreads();
    if (tid == 0) {
        asm volatile("fence.proxy.async.shared::cta;" ::: "memory");
        __half* Dh = sh ? g_sacth : g_acth;
        const char* d0 = (const char*)(Dh + ((size_t)gt * KC_DN + 2 * nb) * TILE_E);
        const char* d1 = (const char*)(Dh + ((size_t)gt * KC_DN + 2 * nb + 1) * TILE_E);
        asm volatile("cp.async.bulk.global.shared::cta.bulk_group [%0], [%1], %2;"
                     :: "l"(d0), "r"(smbase), "r"(16384) : "memory");
        asm volatile("cp.async.bulk.global.shared::cta.bulk_group [%0], [%1], %2;"
                     :: "l"(d1), "r"(smbase + 16384), "r"(16384) : "memory");
        asm volatile("cp.async.bulk.commit_group;");
        asm volatile("cp.async.bulk.wait_group 0;" ::: "memory");
    }
}

// ---------------- down GEMM (pure fp16, trans-B) + fused weighted combine ---
__global__ void __launch_bounds__(512)
mma_down(float* __restrict__ Y, int T)
{
    extern __shared__ char sm[];
    __shared__ __align__(8) unsigned long long s_bar[2 * NST_DN];
    __shared__ int   s_tok[128];
    __shared__ float s_w[128];

    int e = blockIdx.z;
    bool sh = (e == NE);
    int r0, cnt;
    if (sh) { r0 = 0; cnt = T; }
    else { r0 = g_offsets[e]; cnt = g_counts[e]; }
    int mbase = blockIdx.y * 128;
    if (mbase >= cnt) return;
    int nb = blockIdx.x;
    int gt = (r0 + mbase) >> 7;

    const __half* Ahp = sh ? g_sacth : g_acth;
    const __half* Bd = (sh ? g_psd : g_pwd)
        + (size_t)(sh ? 0 : e) * TN_DN * KC_DN * TILE_E + (size_t)nb * KC_DN * TILE_E;

    int tid = threadIdx.x;
    int wid = tid >> 5, lane = tid & 31;
    int warpM = wid & 3, warpN = wid >> 2;
    uint32_t smbase = smem_u32(sm);
    uint32_t barb = smem_u32(&s_bar[0]);
    auto fullb  = [&](int s) { return barb + s * 8; };
    auto emptyb = [&](int s) { return barb + (NST_DN + s) * 8; };

    if (tid == 0)
        for (int s = 0; s < NST_DN; s++) { mbar_init(fullb(s), 1); mbar_init(emptyb(s), 16); }
    if (tid < 128) {
        int rr = mbase + tid;
        if (sh) { s_tok[tid] = rr; s_w[tid] = 1.f; }
        else {
            int slot = (rr < cnt) ? g_rowmap[r0 + rr] : 0;
            s_tok[tid] = slot >> 2;
            s_w[tid] = g_tw[slot];
        }
    }
    __syncthreads();

    auto issue = [&](int j) {
        int s = j % NST_DN;
        uint32_t st = smbase + s * STAGE_DN;
        mbar_expect(fullb(s), STAGE_DN);
        TMA_BULK(st,         (const char*)(Ahp + ((size_t)gt * KC_DN + j) * TILE_E), TILE_B, fullb(s));
        TMA_BULK(st + 16384, (const char*)(Bd + (size_t)j * TILE_E), TILE_B, fullb(s));
    };

    const int nc = KC_DN;
    if (tid == 0)
        for (int j = 0; j < NST_DN - 1 && j < nc; j++) issue(j);

    float acc[2][4][4];
    #pragma unroll
    for (int a = 0; a < 2; a++)
        #pragma unroll
        for (int b = 0; b < 4; b++)
            #pragma unroll
            for (int cc = 0; cc < 4; cc++) acc[a][b][cc] = 0.f;

    int arow = (lane & 7) + ((lane >> 3) & 1) * 8;
    int aselB = (lane >> 4) * 16;
    int bkrow = (lane & 7) + ((lane >> 3) & 1) * 8;
    int bn8   = (lane >> 4) * 8;

    for (int c = 0; c < nc; c++) {
        int s = c % NST_DN;
        if (tid == 0) {
            int j = c + NST_DN - 1;
            if (j < nc) {
                if (j >= NST_DN) mbar_wait(emptyb(j % NST_DN), (j / NST_DN - 1) & 1);
                issue(j);
            }
        }
        mbar_wait(fullb(s), (c / NST_DN) & 1);

        uint32_t base = smbase + s * STAGE_DN;
        #pragma unroll
        for (int k16 = 0; k16 < 4; k16++) {
            uint32_t a[2][4], b[4][2];
            #pragma unroll
            for (int mi = 0; mi < 2; mi++) {
                uint32_t off = (uint32_t)((warpM * 32 + mi * 16 + arow) * 128 + k16 * 32 + aselB);
                LDMX4(a[mi][0], a[mi][1], a[mi][2], a[mi][3], base + swz(off));
            }
            #pragma unroll
            for (int gi = 0; gi < 2; gi++) {
                int n = warpN * 32 + gi * 16 + bn8;
                uint32_t off = (uint32_t)((n >> 6) * HT_B)
                             + swz((uint32_t)((k16 * 16 + bkrow) * 128 + (n & 63) * 2));
                uint32_t x0, x1, x2, x3;
                LDMX4T(x0, x1, x2, x3, base + 16384 + off);
                b[gi*2][0]=x0; b[gi*2][1]=x1; b[gi*2+1][0]=x2; b[gi*2+1][1]=x3;
            }
            #pragma unroll
            for (int mi = 0; mi < 2; mi++)
                #pragma unroll
                for (int ni = 0; ni < 4; ni++)
                    MMAH(acc[mi][ni], a[mi], b[ni][0], b[ni][1]);
        }
        __syncwarp();
        if (lane == 0) mbar_arrive(emptyb(s));
    }

    int g = lane >> 2, tg = lane & 3;
    #pragma unroll
    for (int mi = 0; mi < 2; mi++) {
        #pragma unroll
        for (int half8 = 0; half8 < 2; half8++) {
            int rl = warpM * 32 + mi * 16 + g + half8 * 8;
            if (mbase + rl >= cnt) continue;
            int tok = s_tok[rl];
            float w = s_w[rl];
            float* dst = Y + (size_t)tok * H + nb * 128 + warpN * 32;
            #pragma unroll
            for (int ni = 0; ni < 4; ni++) {
                int col = ni * 8 + tg * 2;
                atomicAdd(dst + col,     acc[mi][ni][half8*2]     * w);
                atomicAdd(dst + col + 1, acc[mi][ni][half8*2 + 1] * w);
            }
        }
    }
}

__global__ void fill_zero(float* p, long long n) {
    long long i = (long long)blockIdx.x * 256 + threadIdx.x;
    if (i < n) p[i] = 0.f;
}

// ---------------- launch -----------------------------------------------------
extern "C" void kernel_launch(void* const* d_in, const int* in_sizes, int n_in,
                              void* d_out, int out_size)
{
    const float* x   = (const float*)d_in[0];
    const float* gw  = (const float*)d_in[1];
    const float* eb  = (const float*)d_in[2];
    const float* wg  = (const float*)d_in[3];
    const float* wu  = (const float*)d_in[4];
    const float* wd  = (const float*)d_in[5];
    const float* wsg = (const float*)d_in[6];
    const float* wsu = (const float*)d_in[7];
    const float* wsd = (const float*)d_in[8];
    float* out = (float*)d_out;

    int T = in_sizes[0] / H;
    int N = T * TK;
    int MT = (T + 127) / 128;

    long long oL = (long long)T * H;
    long long oK = oL + (long long)T * NE;
    long long oEnd = oK + (long long)T * TK;

    float* outLogits = ((long long)out_size >= oK)   ? (out + oL) : nullptr;
    float* outTopkF  = ((long long)out_size >= oEnd) ? (out + oK) : nullptr;
    long long written = ((long long)out_size >= oEnd) ? oEnd
                       : ((long long)out_size >= oK) ? oK
                       : oL;

    cudaFuncSetAttribute(mma_gateup, cudaFuncAttributeMaxDynamicSharedMemorySize, SMEM_GU);
    cudaFuncSetAttribute(mma_down,   cudaFuncAttributeMaxDynamicSharedMemorySize, SMEM_DN);

    long long n4 = oL / 4;
    zero_init<<<(unsigned)((n4 + 255) / 256), 256>>>(out, n4);
    prep_all<<<NGU_BLK + NDN_BLK, 256>>>(wg, wu, wsg, wsu, wd, wsd);
    gate_kernel<<<T / 32, 512>>>(x, gw, outLogits);          // also writes g_sxh tiles
    topk_kernel<<<(T + 255) / 256, 256>>>(eb, outTopkF, T);  // profiled slot
    scan_kernel<<<1, 32>>>();
    scatter_kernel<<<(N + 255) / 256, 256>>>(N);
    gather_rx<<<dim3(KC_GU, NT_X), 256>>>();

    mma_gateup<<<dim3(TN_GU, MT, NE + 1), 512, SMEM_GU>>>(T);
    mma_down  <<<dim3(TN_DN, MT, NE + 1), 512, SMEM_DN>>>(out, T);

    if ((long long)out_size > written) {
        long long rest = (long long)out_size - written;
        fill_zero<<<(unsigned)((rest + 255) / 256), 256>>>(out + written, rest);
    }
}

// round 17
// speedup vs baseline: 1.9089x; 1.0059x over previous
#include <cuda_runtime.h>
#include <cuda_fp16.h>
#include <math.h>
#include <stdint.h>

#define H   1024
#define ID  512
#define NE  32
#define TK  4
#define MAXT 4096
#define MAXN (MAXT*TK)
#define RSCALE 2.5f

#define TILE_E   8192          // elems per tile (128x64 A-major or 64x128 B-major)
#define TILE_B   16384         // bytes per tile
#define HT_B     8192          // bytes per B half-tile (64 rows x 128B)
#define NT_X     160           // row-tiles for padded sorted rows (20480/128)
#define NT_SH    32            // T/128
#define KC_GU    16            // H/64
#define KC_DN    8             // ID/64
#define TN_GU    4             // ID/128
#define TN_DN    8             // H/128

#define NST_GU   4
#define NST_DN   6
#define STAGE_GU 49152         // A, Bg, Bu
#define STAGE_DN 32768         // A, B
#define SMEM_GU  (NST_GU*STAGE_GU)   // 196608
#define SMEM_DN  (NST_DN*STAGE_DN)   // 196608

// ---------------- scratch (device globals; referenced ONLY in device code) --
__device__ float g_logits[(size_t)MAXT * NE];
__device__ float g_tw[MAXT * TK];
__device__ int   g_topk[MAXT * TK];
__device__ int   g_counts[NE];
__device__ int   g_offsets[NE + 1];
__device__ int   g_cursor[NE];
__device__ int   g_rowmap[NT_X * 128];

// tiled fp16 planes (A-side, row-major [m][k], SW128)
__device__ __align__(16) __half g_xsh[(size_t)NT_X * KC_GU * TILE_E];
__device__ __align__(16) __half g_sxh[(size_t)NT_SH * KC_GU * TILE_E];
__device__ __align__(16) __half g_acth[(size_t)NT_X * KC_DN * TILE_E];
__device__ __align__(16) __half g_sacth[(size_t)NT_SH * KC_DN * TILE_E];

// tiled weights [e][nt][kc][8192], B-major: [k 0..63][n 0..127] as 2 SW128 half-tiles
__device__ __align__(16) __half g_pwg[(size_t)NE * TN_GU * KC_GU * TILE_E];
__device__ __align__(16) __half g_pwu[(size_t)NE * TN_GU * KC_GU * TILE_E];
__device__ __align__(16) __half g_pwd[(size_t)NE * TN_DN * KC_DN * TILE_E];
__device__ __align__(16) __half g_psg[(size_t)TN_GU * KC_GU * TILE_E];
__device__ __align__(16) __half g_psu[(size_t)TN_GU * KC_GU * TILE_E];
__device__ __align__(16) __half g_psd[(size_t)TN_DN * KC_DN * TILE_E];

// ---------------- helpers ----------------------------------------------
__device__ __forceinline__ uint32_t smem_u32(const void* p) {
    return (uint32_t)__cvta_generic_to_shared(p);
}
__device__ __forceinline__ uint32_t swz(uint32_t b) { return b ^ ((b >> 3) & 0x70); }
__device__ __forceinline__ uint32_t packh(__half a, __half b) {
    return (uint32_t)(*(uint16_t*)&a) | ((uint32_t)(*(uint16_t*)&b) << 16);
}
__device__ __forceinline__ float silu_fast(float g) { return g / (1.f + __expf(-g)); }

__device__ __forceinline__ void mbar_init(uint32_t a, uint32_t cnt) {
    asm volatile("mbarrier.init.shared.b64 [%0], %1;" :: "r"(a), "r"(cnt) : "memory");
}
__device__ __forceinline__ void mbar_arrive(uint32_t a) {
    asm volatile("mbarrier.arrive.shared.b64 _, [%0];" :: "r"(a) : "memory");
}
__device__ __forceinline__ void mbar_expect(uint32_t a, uint32_t bytes) {
    asm volatile("mbarrier.arrive.expect_tx.shared.b64 _, [%0], %1;"
                 :: "r"(a), "r"(bytes) : "memory");
}
__device__ __forceinline__ void mbar_wait(uint32_t a, uint32_t ph) {
    asm volatile(
        "{\n\t.reg .pred P;\n\t"
        "W_%=:\n\t"
        "mbarrier.try_wait.parity.acquire.cta.shared::cta.b64 P, [%0], %1, 0x989680;\n\t"
        "@P bra D_%=;\n\t"
        "bra W_%=;\n\t"
        "D_%=:\n\t}"
        :: "r"(a), "r"(ph) : "memory");
}
#define TMA_BULK(dst, src, bytes, mbar) \
    asm volatile("cp.async.bulk.shared::cta.global.mbarrier::complete_tx::bytes " \
                 "[%0], [%1], %2, [%3];" \
                 :: "r"(dst), "l"(src), "r"(bytes), "r"(mbar) : "memory")

#define LDMX4(r0_,r1_,r2_,r3_,addr) \
    asm volatile("ldmatrix.sync.aligned.m8n8.x4.shared.b16 {%0,%1,%2,%3}, [%4];" \
        : "=r"(r0_), "=r"(r1_), "=r"(r2_), "=r"(r3_) : "r"(addr))

#define LDMX4T(r0_,r1_,r2_,r3_,addr) \
    asm volatile("ldmatrix.sync.aligned.m8n8.x4.trans.shared.b16 {%0,%1,%2,%3}, [%4];" \
        : "=r"(r0_), "=r"(r1_), "=r"(r2_), "=r"(r3_) : "r"(addr))

#define MMAH(c_, a_, b0_, b1_) \
    asm volatile("mma.sync.aligned.m16n8k16.row.col.f32.f16.f16.f32 " \
        "{%0,%1,%2,%3}, {%4,%5,%6,%7}, {%8,%9}, {%0,%1,%2,%3};" \
        : "+f"((c_)[0]), "+f"((c_)[1]), "+f"((c_)[2]), "+f"((c_)[3]) \
        : "r"((a_)[0]), "r"((a_)[1]), "r"((a_)[2]), "r"((a_)[3]), \
          "r"(b0_), "r"(b1_))

// ---------------- zero y + init counters -----------------------------------
__global__ void zero_init(float* __restrict__ y, long long n4) {
    long long i = (long long)blockIdx.x * 256 + threadIdx.x;
    if (i < n4) ((float4*)y)[i] = make_float4(0.f, 0.f, 0.f, 0.f);
    if (i < NE) { g_counts[i] = 0; g_cursor[i] = 0; }
    if (i < NT_X * 128) g_rowmap[i] = 0;
}

// ---------------- gate GEMV (2 tokens/warp) + fused X->fp16 tile gather -----
__global__ void __launch_bounds__(512)
gate_kernel(const float* __restrict__ X, const float* __restrict__ GW,
            float* outLogits)
{
    int warp = threadIdx.x >> 5, lane = threadIdx.x & 31;
    int t0 = blockIdx.x * 32 + warp * 2;

    float4 xv[2][8];
    #pragma unroll
    for (int u = 0; u < 2; u++) {
        const float4* xp = (const float4*)(X + (size_t)(t0 + u) * H);
        #pragma unroll
        for (int j = 0; j < 8; j++) xv[u][j] = xp[j * 32 + lane];
    }

    // fused gather: write swizzled fp16 tiles of X (shared-expert A source)
    #pragma unroll
    for (int u = 0; u < 2; u++) {
        int t = t0 + u;
        int gt = t >> 7, row = t & 127;
        #pragma unroll
        for (int j = 0; j < 8; j++) {
            int p = j * 128 + lane * 4;
            int kc = p >> 6, q = p & 63;
            __half* dh = g_sxh + ((size_t)gt * KC_GU + kc) * TILE_E;
            uint32_t h0 = packh(__float2half_rn(xv[u][j].x), __float2half_rn(xv[u][j].y));
            uint32_t h1 = packh(__float2half_rn(xv[u][j].z), __float2half_rn(xv[u][j].w));
            *(uint2*)((char*)dh + swz((uint32_t)(row * 128 + q * 2))) = make_uint2(h0, h1);
        }
    }

    #pragma unroll 1
    for (int e = 0; e < NE; e++) {
        const float4* wp = (const float4*)(GW + (size_t)e * H);
        float s0 = 0.f, s1 = 0.f;
        #pragma unroll
        for (int j = 0; j < 8; j++) {
            float4 wv = wp[j * 32 + lane];
            s0 += xv[0][j].x * wv.x + xv[0][j].y * wv.y + xv[0][j].z * wv.z + xv[0][j].w * wv.w;
            s1 += xv[1][j].x * wv.x + xv[1][j].y * wv.y + xv[1][j].z * wv.z + xv[1][j].w * wv.w;
        }
        #pragma unroll
        for (int d = 16; d > 0; d >>= 1) {
            s0 += __shfl_down_sync(0xffffffffu, s0, d);
            s1 += __shfl_down_sync(0xffffffffu, s1, d);
        }
        if (lane == 0) {
            g_logits[(size_t)t0 * NE + e] = s0;
            g_logits[(size_t)(t0 + 1) * NE + e] = s1;
            if (outLogits) {
                outLogits[(size_t)t0 * NE + e] = s0;
                outLogits[(size_t)(t0 + 1) * NE + e] = s1;
            }
        }
    }
}

// ---------------- top-k routing: warp per token, lane per expert -------------
__global__ void __launch_bounds__(256)
topk_kernel(const float* __restrict__ EB, float* outTopkF, int T)
{
    int gwarp = (blockIdx.x * 256 + threadIdx.x) >> 5;
    int lane = threadIdx.x & 31;
    if (gwarp >= T) return;
    int t = gwarp;

    float v = g_logits[(size_t)t * NE + lane];
    float sc = 1.f / (1.f + expf(-v));
    float srt = sc + EB[lane];

    // group score = sum of top-2 within this lane's group of 8 (same order as ref)
    int gbase = lane & 24;
    float m1 = -1e30f, m2 = -1e30f;
    #pragma unroll
    for (int j = 0; j < 8; j++) {
        float u = __shfl_sync(0xffffffffu, srt, gbase + j);
        if (u > m1) { m2 = m1; m1 = u; }
        else if (u > m2) { m2 = u; }
    }
    float gsv = m1 + m2;

    // top-2 groups (serial over 4, exact ref semantics: strict >, first wins)
    float q0 = __shfl_sync(0xffffffffu, gsv, 0);
    float q1 = __shfl_sync(0xffffffffu, gsv, 8);
    float q2 = __shfl_sync(0xffffffffu, gsv, 16);
    float q3 = __shfl_sync(0xffffffffu, gsv, 24);
    int b1 = 0; float bv = q0;
    if (q1 > bv) { bv = q1; b1 = 1; }
    if (q2 > bv) { bv = q2; b1 = 2; }
    if (q3 > bv) { bv = q3; b1 = 3; }
    int b2 = -1; float bv2 = -1e30f;
    if (b1 != 0) { b2 = 0; bv2 = q0; }
    if (b1 != 1 && q1 > bv2) { b2 = 1; bv2 = q1; }
    if (b1 != 2 && q2 > bv2) { b2 = 2; bv2 = q2; }
    if (b1 != 3 && q3 > bv2) { b2 = 3; bv2 = q3; }

    int mygrp = lane >> 3;
    float cand = (mygrp == b1 || mygrp == b2) ? srt : -1e30f;

    // 4 rounds of warp argmax (ties -> lower lane index, matching serial >)
    int idx[TK]; float wts[TK]; float sum = 0.f;
    #pragma unroll
    for (int k = 0; k < TK; k++) {
        float mv = cand; int mi = lane;
        #pragma unroll
        for (int d = 16; d > 0; d >>= 1) {
            float ov = __shfl_down_sync(0xffffffffu, mv, d);
            int   oi = __shfl_down_sync(0xffffffffu, mi, d);
            if (ov > mv || (ov == mv && oi < mi)) { mv = ov; mi = oi; }
        }
        mi = __shfl_sync(0xffffffffu, mi, 0);
        float w = __shfl_sync(0xffffffffu, sc, mi);
        idx[k] = mi; wts[k] = w; sum += w;
        if (lane == mi) cand = -1e30f;
    }

    if (lane < TK) {
        float inv = RSCALE / (sum + 1e-20f);
        g_topk[t * TK + lane] = idx[lane];
        g_tw[t * TK + lane]   = wts[lane] * inv;
        if (outTopkF) outTopkF[t * TK + lane] = (float)idx[lane];
        atomicAdd(&g_counts[idx[lane]], 1);
    }
}

// warp-parallel exclusive scan of 128-padded counts
__global__ void scan_kernel() {
    int lane = threadIdx.x;
    int c = (lane < NE) ? ((g_counts[lane] + 127) & ~127) : 0;
    int s = c;
    #pragma unroll
    for (int d = 1; d < 32; d <<= 1) {
        int n = __shfl_up_sync(0xffffffffu, s, d);
        if (lane >= d) s += n;
    }
    if (lane < NE) g_offsets[lane + 1] = s;
    if (lane == 0) g_offsets[0] = 0;
}

__global__ void scatter_kernel(int N) {
    int s = blockIdx.x * 256 + threadIdx.x;
    if (s >= N) return;
    int e = g_topk[s];
    int p = g_offsets[e] + atomicAdd(&g_cursor[e], 1);
    g_rowmap[p] = s;
}

// ---------------- gather routed X from fp16 tiles (pure swizzled row copy) --
__global__ void __launch_bounds__(256)
gather_rx()
{
    int kc = blockIdx.x;
    int gt = blockIdx.y;
    __shared__ int stok[128];
    if (gt * 128 >= g_offsets[NE]) return;

    int tid = threadIdx.x;
    if (tid < 128) stok[tid] = g_rowmap[gt * 128 + tid] >> 2;
    __syncthreads();

    char* dh = (char*)(g_xsh + ((size_t)gt * KC_GU + kc) * TILE_E);

    for (int i = tid; i < 128 * 8; i += 256) {
        int r = i >> 3, q16 = (i & 7) * 16;
        int t = stok[r];
        const char* sh = (const char*)(g_sxh + ((size_t)(t >> 7) * KC_GU + kc) * TILE_E);
        uint4 v = *(const uint4*)(sh + swz((uint32_t)((t & 127) * 128 + q16)));
        *(uint4*)(dh + swz((uint32_t)(r * 128 + q16))) = v;
    }
}

// ---------------- weight prep: pure streaming convert (B-major tiles) -------
__device__ __forceinline__ void prep_core(const float* src, int N, __half* dst)
{
    int tid = threadIdx.x;
    #pragma unroll
    for (int i = tid; i < 2048; i += 256) {
        int k = i >> 5, n4 = (i & 31) * 4;
        float4 v = *(const float4*)(src + (size_t)k * N + n4);
        uint32_t h0 = packh(__float2half_rn(v.x), __float2half_rn(v.y));
        uint32_t h1 = packh(__float2half_rn(v.z), __float2half_rn(v.w));
        uint32_t off = (uint32_t)((n4 >> 6) * HT_B)
                     + swz((uint32_t)(k * 128 + (n4 & 63) * 2));
        *(uint2*)((char*)dst + off) = make_uint2(h0, h1);
    }
}

#define NGU_BLK ((2*NE+2)*TN_GU*KC_GU)   // 4224
#define NDN_BLK ((NE+1)*TN_DN*KC_DN)     // 2112

__global__ void __launch_bounds__(256)
prep_all(const float* __restrict__ wg, const float* __restrict__ wu,
         const float* __restrict__ wsg, const float* __restrict__ wsu,
         const float* __restrict__ wd, const float* __restrict__ wsd)
{
    int bid = blockIdx.x;
    if (bid < NGU_BLK) {
        int z = bid / (TN_GU * KC_GU);
        int rem = bid % (TN_GU * KC_GU);
        int nt = rem / KC_GU, kc = rem % KC_GU;
        const float* W; __half* base; int e;
        if (z < NE)          { W = wg;  base = g_pwg; e = z; }
        else if (z < 2 * NE) { W = wu;  base = g_pwu; e = z - NE; }
        else if (z == 2*NE)  { W = wsg; base = g_psg; e = 0; }
        else                 { W = wsu; base = g_psu; e = 0; }
        const float* src = W + ((size_t)e * H + (size_t)kc * 64) * ID + (size_t)nt * 128;
        __half* dst = base + ((size_t)(e * TN_GU + nt) * KC_GU + kc) * TILE_E;
        prep_core(src, ID, dst);
    } else {
        int b2 = bid - NGU_BLK;
        int z = b2 / (TN_DN * KC_DN);
        int rem = b2 % (TN_DN * KC_DN);
        int nt = rem / KC_DN, kc = rem % KC_DN;
        const float* W; __half* base; int e;
        if (z < NE) { W = wd;  base = g_pwd; e = z; }
        else        { W = wsd; base = g_psd; e = 0; }
        const float* src = W + ((size_t)e * ID + (size_t)kc * 64) * H + (size_t)nt * 128;
        __half* dst = base + ((size_t)(e * TN_DN + nt) * KC_DN + kc) * TILE_E;
        prep_core(src, H, dst);
    }
}

// ---------------- fused gate+up GEMM (pure fp16, bulk pipeline, trans-B) ----
__global__ void __launch_bounds__(512)
mma_gateup(int T)
{
    extern __shared__ char sm[];
    __shared__ __align__(8) unsigned long long s_bar[2 * NST_GU];

    int e = blockIdx.z;
    bool sh = (e == NE);
    int r0, cnt;
    if (sh) { r0 = 0; cnt = T; }
    else { r0 = g_offsets[e]; cnt = g_counts[e]; }
    int mbase = blockIdx.y * 128;
    if (mbase >= cnt) return;
    int nb = blockIdx.x;
    int gt = (r0 + mbase) >> 7;

    const __half* Ah = sh ? g_sxh : g_xsh;
    const __half* Bg = (sh ? g_psg : g_pwg)
        + (size_t)(sh ? 0 : e) * TN_GU * KC_GU * TILE_E + (size_t)nb * KC_GU * TILE_E;
    const __half* Bu = (sh ? g_psu : g_pwu)
        + (size_t)(sh ? 0 : e) * TN_GU * KC_GU * TILE_E + (size_t)nb * KC_GU * TILE_E;

    int tid = threadIdx.x;
    int wid = tid >> 5, lane = tid & 31;
    int warpM = wid & 3, warpN = wid >> 2;
    uint32_t smbase = smem_u32(sm);
    uint32_t barb = smem_u32(&s_bar[0]);
    auto fullb  = [&](int s) { return barb + s * 8; };
    auto emptyb = [&](int s) { return barb + (NST_GU + s) * 8; };

    if (tid == 0)
        for (int s = 0; s < NST_GU; s++) { mbar_init(fullb(s), 1); mbar_init(emptyb(s), 16); }
    __syncthreads();

    auto issue = [&](int j) {
        int s = j % NST_GU;
        uint32_t st = smbase + s * STAGE_GU;
        mbar_expect(fullb(s), STAGE_GU);
        TMA_BULK(st,         (const char*)(Ah + ((size_t)gt * KC_GU + j) * TILE_E), TILE_B, fullb(s));
        TMA_BULK(st + 16384, (const char*)(Bg + (size_t)j * TILE_E), TILE_B, fullb(s));
        TMA_BULK(st + 32768, (const char*)(Bu + (size_t)j * TILE_E), TILE_B, fullb(s));
    };

    const int nc = KC_GU;
    if (tid == 0)
        for (int j = 0; j < NST_GU - 1; j++) issue(j);

    float accG[2][4][4], accU[2][4][4];
    #pragma unroll
    for (int a = 0; a < 2; a++)
        #pragma unroll
        for (int b = 0; b < 4; b++)
            #pragma unroll
            for (int cc = 0; cc < 4; cc++) { accG[a][b][cc] = 0.f; accU[a][b][cc] = 0.f; }

    int arow = (lane & 7) + ((lane >> 3) & 1) * 8;
    int aselB = (lane >> 4) * 16;
    int bkrow = (lane & 7) + ((lane >> 3) & 1) * 8;
    int bn8   = (lane >> 4) * 8;

    for (int c = 0; c < nc; c++) {
        int s = c % NST_GU;
        if (tid == 0) {
            int j = c + NST_GU - 1;
            if (j < nc) {
                if (j >= NST_GU) mbar_wait(emptyb(j % NST_GU), (j / NST_GU - 1) & 1);
                issue(j);
            }
        }
        mbar_wait(fullb(s), (c / NST_GU) & 1);

        uint32_t base = smbase + s * STAGE_GU;
        #pragma unroll
        for (int k16 = 0; k16 < 4; k16++) {
            uint32_t a[2][4], b[4][2];
            #pragma unroll
            for (int mi = 0; mi < 2; mi++) {
                uint32_t off = (uint32_t)((warpM * 32 + mi * 16 + arow) * 128 + k16 * 32 + aselB);
                LDMX4(a[mi][0], a[mi][1], a[mi][2], a[mi][3], base + swz(off));
            }
            // --- G ---
            #pragma unroll
            for (int gi = 0; gi < 2; gi++) {
                int n = warpN * 32 + gi * 16 + bn8;
                uint32_t off = (uint32_t)((n >> 6) * HT_B)
                             + swz((uint32_t)((k16 * 16 + bkrow) * 128 + (n & 63) * 2));
                uint32_t x0, x1, x2, x3;
                LDMX4T(x0, x1, x2, x3, base + 16384 + off);
                b[gi*2][0]=x0; b[gi*2][1]=x1; b[gi*2+1][0]=x2; b[gi*2+1][1]=x3;
            }
            #pragma unroll
            for (int mi = 0; mi < 2; mi++)
                #pragma unroll
                for (int ni = 0; ni < 4; ni++)
                    MMAH(accG[mi][ni], a[mi], b[ni][0], b[ni][1]);
            // --- U ---
            #pragma unroll
            for (int gi = 0; gi < 2; gi++) {
                int n = warpN * 32 + gi * 16 + bn8;
                uint32_t off = (uint32_t)((n >> 6) * HT_B)
                             + swz((uint32_t)((k16 * 16 + bkrow) * 128 + (n & 63) * 2));
                uint32_t x0, x1, x2, x3;
                LDMX4T(x0, x1, x2, x3, base + 32768 + off);
                b[gi*2][0]=x0; b[gi*2][1]=x1; b[gi*2+1][0]=x2; b[gi*2+1][1]=x3;
            }
            #pragma unroll
            for (int mi = 0; mi < 2; mi++)
                #pragma unroll
                for (int ni = 0; ni < 4; ni++)
                    MMAH(accU[mi][ni], a[mi], b[ni][0], b[ni][1]);
        }
        __syncwarp();
        if (lane == 0) mbar_arrive(emptyb(s));
    }

    // epilogue: stage act = silu(G)*U tile in smem, then 2 bulk stores
    __syncthreads();
    int g = lane >> 2, tg = lane & 3;
    #pragma unroll
    for (int mi = 0; mi < 2; mi++) {
        #pragma unroll
        for (int ni = 0; ni < 4; ni++) {
            int cl = warpN * 32 + ni * 8 + tg * 2;
            int which = cl >> 6, cc = cl & 63;
            #pragma unroll
            for (int half8 = 0; half8 < 2; half8++) {
                int rl = warpM * 32 + mi * 16 + g + half8 * 8;
                float a0 = silu_fast(accG[mi][ni][half8*2])   * accU[mi][ni][half8*2];
                float a1 = silu_fast(accG[mi][ni][half8*2+1]) * accU[mi][ni][half8*2+1];
                uint32_t hv = packh(__float2half_rn(a0), __float2half_rn(a1));
                *(uint32_t*)(sm + which * 16384 + swz((uint32_t)(rl * 128 + cc * 2))) = hv;
            }
        }
    }
    __syncthreads();
    if (tid == 0) {
        asm volatile("fence.proxy.async.shared::cta;" ::: "memory");
        __half* Dh = sh ? g_sacth : g_acth;
        const char* d0 = (const char*)(Dh + ((size_t)gt * KC_DN + 2 * nb) * TILE_E);
        const char* d1 = (const char*)(Dh + ((size_t)gt * KC_DN + 2 * nb + 1) * TILE_E);
        asm volatile("cp.async.bulk.global.shared::cta.bulk_group [%0], [%1], %2;"
                     :: "l"(d0), "r"(smbase), "r"(16384) : "memory");
        asm volatile("cp.async.bulk.global.shared::cta.bulk_group [%0], [%1], %2;"
                     :: "l"(d1), "r"(smbase + 16384), "r"(16384) : "memory");
        asm volatile("cp.async.bulk.commit_group;");
        asm volatile("cp.async.bulk.wait_group 0;" ::: "memory");
    }
}

// ---------------- down GEMM (pure fp16, trans-B) + fused weighted combine ---
__global__ void __launch_bounds__(512)
mma_down(float* __restrict__ Y, int T)
{
    extern __shared__ char sm[];
    __shared__ __align__(8) unsigned long long s_bar[2 * NST_DN];
    __shared__ int   s_tok[128];
    __shared__ float s_w[128];

    int e = blockIdx.z;
    bool sh = (e == NE);
    int r0, cnt;
    if (sh) { r0 = 0; cnt = T; }
    else { r0 = g_offsets[e]; cnt = g_counts[e]; }
    int mbase = blockIdx.y * 128;
    if (mbase >= cnt) return;
    int nb = blockIdx.x;
    int gt = (r0 + mbase) >> 7;

    const __half* Ahp = sh ? g_sacth : g_acth;
    const __half* Bd = (sh ? g_psd : g_pwd)
        + (size_t)(sh ? 0 : e) * TN_DN * KC_DN * TILE_E + (size_t)nb * KC_DN * TILE_E;

    int tid = threadIdx.x;
    int wid = tid >> 5, lane = tid & 31;
    int warpM = wid & 3, warpN = wid >> 2;
    uint32_t smbase = smem_u32(sm);
    uint32_t barb = smem_u32(&s_bar[0]);
    auto fullb  = [&](int s) { return barb + s * 8; };
    auto emptyb = [&](int s) { return barb + (NST_DN + s) * 8; };

    if (tid == 0)
        for (int s = 0; s < NST_DN; s++) { mbar_init(fullb(s), 1); mbar_init(emptyb(s), 16); }
    if (tid < 128) {
        int rr = mbase + tid;
        if (sh) { s_tok[tid] = rr; s_w[tid] = 1.f; }
        else {
            int slot = (rr < cnt) ? g_rowmap[r0 + rr] : 0;
            s_tok[tid] = slot >> 2;
            s_w[tid] = g_tw[slot];
        }
    }
    __syncthreads();

    auto issue = [&](int j) {
        int s = j % NST_DN;
        uint32_t st = smbase + s * STAGE_DN;
        mbar_expect(fullb(s), STAGE_DN);
        TMA_BULK(st,         (const char*)(Ahp + ((size_t)gt * KC_DN + j) * TILE_E), TILE_B, fullb(s));
        TMA_BULK(st + 16384, (const char*)(Bd + (size_t)j * TILE_E), TILE_B, fullb(s));
    };

    const int nc = KC_DN;
    if (tid == 0)
        for (int j = 0; j < NST_DN - 1 && j < nc; j++) issue(j);

    float acc[2][4][4];
    #pragma unroll
    for (int a = 0; a < 2; a++)
        #pragma unroll
        for (int b = 0; b < 4; b++)
            #pragma unroll
            for (int cc = 0; cc < 4; cc++) acc[a][b][cc] = 0.f;

    int arow = (lane & 7) + ((lane >> 3) & 1) * 8;
    int aselB = (lane >> 4) * 16;
    int bkrow = (lane & 7) + ((lane >> 3) & 1) * 8;
    int bn8   = (lane >> 4) * 8;

    for (int c = 0; c < nc; c++) {
        int s = c % NST_DN;
        if (tid == 0) {
            int j = c + NST_DN - 1;
            if (j < nc) {
                if (j >= NST_DN) mbar_wait(emptyb(j % NST_DN), (j / NST_DN - 1) & 1);
                issue(j);
            }
        }
        mbar_wait(fullb(s), (c / NST_DN) & 1);

        uint32_t base = smbase + s * STAGE_DN;
        #pragma unroll
        for (int k16 = 0; k16 < 4; k16++) {
            uint32_t a[2][4], b[4][2];
            #pragma unroll
            for (int mi = 0; mi < 2; mi++) {
                uint32_t off = (uint32_t)((warpM * 32 + mi * 16 + arow) * 128 + k16 * 32 + aselB);
                LDMX4(a[mi][0], a[mi][1], a[mi][2], a[mi][3], base + swz(off));
            }
            #pragma unroll
            for (int gi = 0; gi < 2; gi++) {
                int n = warpN * 32 + gi * 16 + bn8;
                uint32_t off = (uint32_t)((n >> 6) * HT_B)
                             + swz((uint32_t)((k16 * 16 + bkrow) * 128 + (n & 63) * 2));
                uint32_t x0, x1, x2, x3;
                LDMX4T(x0, x1, x2, x3, base + 16384 + off);
                b[gi*2][0]=x0; b[gi*2][1]=x1; b[gi*2+1][0]=x2; b[gi*2+1][1]=x3;
            }
            #pragma unroll
            for (int mi = 0; mi < 2; mi++)
                #pragma unroll
                for (int ni = 0; ni < 4; ni++)
                    MMAH(acc[mi][ni], a[mi], b[ni][0], b[ni][1]);
        }
        __syncwarp();
        if (lane == 0) mbar_arrive(emptyb(s));
    }

    int g = lane >> 2, tg = lane & 3;
    #pragma unroll
    for (int mi = 0; mi < 2; mi++) {
        #pragma unroll
        for (int half8 = 0; half8 < 2; half8++) {
            int rl = warpM * 32 + mi * 16 + g + half8 * 8;
            if (mbase + rl >= cnt) continue;
            int tok = s_tok[rl];
            float w = s_w[rl];
            float* dst = Y + (size_t)tok * H + nb * 128 + warpN * 32;
            #pragma unroll
            for (int ni = 0; ni < 4; ni++) {
                int col = ni * 8 + tg * 2;
                atomicAdd(dst + col,     acc[mi][ni][half8*2]     * w);
                atomicAdd(dst + col + 1, acc[mi][ni][half8*2 + 1] * w);
            }
        }
    }
}

__global__ void fill_zero(float* p, long long n) {
    long long i = (long long)blockIdx.x * 256 + threadIdx.x;
    if (i < n) p[i] = 0.f;
}

// ---------------- launch -----------------------------------------------------
extern "C" void kernel_launch(void* const* d_in, const int* in_sizes, int n_in,
                              void* d_out, int out_size)
{
    const float* x   = (const float*)d_in[0];
    const float* gw  = (const float*)d_in[1];
    const float* eb  = (const float*)d_in[2];
    const float* wg  = (const float*)d_in[3];
    const float* wu  = (const float*)d_in[4];
    const float* wd  = (const float*)d_in[5];
    const float* wsg = (const float*)d_in[6];
    const float* wsu = (const float*)d_in[7];
    const float* wsd = (const float*)d_in[8];
    float* out = (float*)d_out;

    int T = in_sizes[0] / H;
    int N = T * TK;
    int MT = (T + 127) / 128;

    long long oL = (long long)T * H;
    long long oK = oL + (long long)T * NE;
    long long oEnd = oK + (long long)T * TK;

    float* outLogits = ((long long)out_size >= oK)   ? (out + oL) : nullptr;
    float* outTopkF  = ((long long)out_size >= oEnd) ? (out + oK) : nullptr;
    long long written = ((long long)out_size >= oEnd) ? oEnd
                       : ((long long)out_size >= oK) ? oK
                       : oL;

    cudaFuncSetAttribute(mma_gateup, cudaFuncAttributeMaxDynamicSharedMemorySize, SMEM_GU);
    cudaFuncSetAttribute(mma_down,   cudaFuncAttributeMaxDynamicSharedMemorySize, SMEM_DN);

    long long n4 = oL / 4;
    zero_init<<<(unsigned)((n4 + 255) / 256), 256>>>(out, n4);
    prep_all<<<NGU_BLK + NDN_BLK, 256>>>(wg, wu, wsg, wsu, wd, wsd);
    gate_kernel<<<T / 32, 512>>>(x, gw, outLogits);          // also writes g_sxh tiles
    topk_kernel<<<(T * 32 + 255) / 256, 256>>>(eb, outTopkF, T);  // profiled slot
    scan_kernel<<<1, 32>>>();
    scatter_kernel<<<(N + 255) / 256, 256>>>(N);
    gather_rx<<<dim3(KC_GU, NT_X), 256>>>();

    mma_gateup<<<dim3(TN_GU, MT, NE + 1), 512, SMEM_GU>>>(T);
    mma_down  <<<dim3(TN_DN, MT, NE + 1), 512, SMEM_DN>>>(out, T);

    if ((long long)out_size > written) {
        long long rest = (long long)out_size - written;
        fill_zero<<<(unsigned)((rest + 255) / 256), 256>>>(out + written, rest);
    }
}